// round 1
// baseline (speedup 1.0000x reference)
#include <cuda_runtime.h>
#include <math.h>

#define BATCH    2
#define SEQ      2048
#define HIDDEN   1024
#define HEADS    16
#define HEAD_DIM 64
#define MTOT     (BATCH*SEQ)      // 4096
#define BHN      (BATCH*HEADS)    // 32

// scratch (allocation-free rule: __device__ globals)
static __device__ float g_q [BHN*SEQ*HEAD_DIM];   // [B,H,S,D] 16MB
static __device__ float g_k [BHN*SEQ*HEAD_DIM];
static __device__ float g_v [BHN*SEQ*HEAD_DIM];
static __device__ float g_ao[MTOT*HIDDEN];        // attention out, [B*S, HIDDEN]

// ---------------------------------------------------------------------------
// GEMM mainloop: C(128x128) += A(MxK) * W(NxK)^T  tile at (blockIdx.y, blockIdx.x)
// 256 threads, BK=8, 8x8 micro-tile.
// ---------------------------------------------------------------------------
__device__ __forceinline__ void gemm_mainloop(const float* __restrict__ A,
                                              const float* __restrict__ W,
                                              float acc[8][8])
{
    __shared__ float As[8][132];   // k-major, padded (132%4==0 for float4)
    __shared__ float Bs[8][132];

    const int tid = threadIdx.x;
    const int ty  = tid >> 4;      // 0..15  -> rows ty*8..+8
    const int tx  = tid & 15;      // 0..15  -> cols tx*8..+8
    const int m0  = blockIdx.y * 128;
    const int n0  = blockIdx.x * 128;

    const int lr = tid >> 1;           // 0..127
    const int lc = (tid & 1) * 4;      // 0 or 4
    const float* Aptr = A + (size_t)(m0 + lr) * HIDDEN + lc;
    const float* Wptr = W + (size_t)(n0 + lr) * HIDDEN + lc;

    for (int k0 = 0; k0 < HIDDEN; k0 += 8) {
        float4 av = *(const float4*)(Aptr + k0);
        float4 wv = *(const float4*)(Wptr + k0);
        As[lc+0][lr] = av.x; As[lc+1][lr] = av.y;
        As[lc+2][lr] = av.z; As[lc+3][lr] = av.w;
        Bs[lc+0][lr] = wv.x; Bs[lc+1][lr] = wv.y;
        Bs[lc+2][lr] = wv.z; Bs[lc+3][lr] = wv.w;
        __syncthreads();
#pragma unroll
        for (int k = 0; k < 8; k++) {
            float4 a0 = *(const float4*)&As[k][ty*8];
            float4 a1 = *(const float4*)&As[k][ty*8+4];
            float4 b0 = *(const float4*)&Bs[k][tx*8];
            float4 b1 = *(const float4*)&Bs[k][tx*8+4];
            float a[8] = {a0.x,a0.y,a0.z,a0.w,a1.x,a1.y,a1.z,a1.w};
            float b[8] = {b0.x,b0.y,b0.z,b0.w,b1.x,b1.y,b1.z,b1.w};
#pragma unroll
            for (int i = 0; i < 8; i++)
#pragma unroll
                for (int j = 0; j < 8; j++)
                    acc[i][j] = fmaf(a[i], b[j], acc[i][j]);
        }
        __syncthreads();
    }
}

// ---------------------------------------------------------------------------
// QKV projection: grid (8, 32, 3); z selects Q/K/V. Writes [B,H,S,D] + bias.
// ---------------------------------------------------------------------------
__global__ void __launch_bounds__(256)
qkv_kernel(const float* __restrict__ X,
           const float* __restrict__ Wq, const float* __restrict__ bq,
           const float* __restrict__ Wk, const float* __restrict__ bk,
           const float* __restrict__ Wv, const float* __restrict__ bv)
{
    const float* W; const float* bias; float* dst;
    if      (blockIdx.z == 0) { W = Wq; bias = bq; dst = g_q; }
    else if (blockIdx.z == 1) { W = Wk; bias = bk; dst = g_k; }
    else                      { W = Wv; bias = bv; dst = g_v; }

    float acc[8][8];
#pragma unroll
    for (int i = 0; i < 8; i++)
#pragma unroll
        for (int j = 0; j < 8; j++) acc[i][j] = 0.f;

    gemm_mainloop(X, W, acc);

    const int ty = threadIdx.x >> 4, tx = threadIdx.x & 15;
    const int m0 = blockIdx.y * 128, n0 = blockIdx.x * 128;
#pragma unroll
    for (int i = 0; i < 8; i++) {
        int m = m0 + ty*8 + i;
        int b = m >> 11, s = m & (SEQ-1);
#pragma unroll
        for (int j = 0; j < 8; j++) {
            int n = n0 + tx*8 + j;
            int h = n >> 6, d = n & 63;
            dst[(((size_t)(b*HEADS + h))*SEQ + s)*HEAD_DIM + d] = acc[i][j] + bias[n];
        }
    }
}

// ---------------------------------------------------------------------------
// Output projection: reads g_ao, plain row-major output + bias.
// ---------------------------------------------------------------------------
__global__ void __launch_bounds__(256)
out_kernel(const float* __restrict__ Wo, const float* __restrict__ bo,
           float* __restrict__ out)
{
    float acc[8][8];
#pragma unroll
    for (int i = 0; i < 8; i++)
#pragma unroll
        for (int j = 0; j < 8; j++) acc[i][j] = 0.f;

    gemm_mainloop(g_ao, Wo, acc);

    const int ty = threadIdx.x >> 4, tx = threadIdx.x & 15;
    const int m0 = blockIdx.y * 128, n0 = blockIdx.x * 128;
#pragma unroll
    for (int i = 0; i < 8; i++) {
        int m = m0 + ty*8 + i;
#pragma unroll
        for (int j = 0; j < 8; j++) {
            int n = n0 + tx*8 + j;
            out[(size_t)m*HIDDEN + n] = acc[i][j] + bo[n];
        }
    }
}

// ---------------------------------------------------------------------------
// RoPE in-place on g_q, g_k. One thread per (bh, s, pair i<32).
// ---------------------------------------------------------------------------
__global__ void rope_kernel()
{
    int t = blockIdx.x * blockDim.x + threadIdx.x;   // < BHN*SEQ*32
    int i  = t & 31;
    int s  = (t >> 5) & (SEQ-1);
    int bh = t >> 16;                                 // SEQ*32 = 65536

    float inv = powf(10000.0f, -(float)i * (1.0f/32.0f));
    float ang = (float)s * inv;
    float c, sn;
    sincosf(ang, &sn, &c);

    size_t base = ((size_t)bh*SEQ + s)*HEAD_DIM + i;
    float q1 = g_q[base], q2 = g_q[base+32];
    g_q[base]    = q1*c - q2*sn;
    g_q[base+32] = q2*c + q1*sn;
    float k1 = g_k[base], k2 = g_k[base+32];
    g_k[base]    = k1*c - k2*sn;
    g_k[base+32] = k2*c + k1*sn;
}

// ---------------------------------------------------------------------------
// Flash attention: grid (SEQ/64, BHN), 256 threads, 64x64 tiles.
// smem: Qt,Kt d-major [64][68]; Vs j-major [64][68]; Ps i-major [64][68].
// ---------------------------------------------------------------------------
#define FP 68           // row pitch (floats): 68%4==0 keeps float4 alignment
__global__ void __launch_bounds__(256)
flash_kernel()
{
    extern __shared__ float sm[];
    float* Qt = sm;                 // Qt[d*FP + i]
    float* Kt = Qt + 64*FP;         // Kt[d*FP + j]
    float* Vs = Kt + 64*FP;         // Vs[j*FP + d]
    float* Ps = Vs + 64*FP;         // Ps[i*FP + j]

    const int tid = threadIdx.x;
    const int ty  = tid >> 4;       // rows ty*4..+4
    const int tx  = tid & 15;       // cols tx*4..+4
    const int bh  = blockIdx.y;
    const int q0  = blockIdx.x * 64;

    // load Q (scaled by 1/sqrt(64)), transposed to d-major
    const float* qbase = g_q + ((size_t)bh*SEQ + q0)*HEAD_DIM;
    for (int e = tid; e < 64*64; e += 256) {
        int r = e >> 6, d = e & 63;
        Qt[d*FP + r] = qbase[e] * 0.125f;
    }

    float mrow[4], lrow[4], o[4][4];
#pragma unroll
    for (int i = 0; i < 4; i++) {
        mrow[i] = -1e30f; lrow[i] = 0.f;
#pragma unroll
        for (int j = 0; j < 4; j++) o[i][j] = 0.f;
    }

    for (int kt = 0; kt < SEQ/64; kt++) {
        const float* kbase = g_k + ((size_t)bh*SEQ + kt*64)*HEAD_DIM;
        const float* vbase = g_v + ((size_t)bh*SEQ + kt*64)*HEAD_DIM;
        for (int e = tid; e < 64*64; e += 256) {
            int r = e >> 6, d = e & 63;
            Kt[d*FP + r] = kbase[e];
            Vs[r*FP + d] = vbase[e];
        }
        __syncthreads();

        // scores S = (Q*scale) K^T   (4x4 per thread)
        float s4[4][4];
#pragma unroll
        for (int i = 0; i < 4; i++)
#pragma unroll
            for (int j = 0; j < 4; j++) s4[i][j] = 0.f;

#pragma unroll 8
        for (int d = 0; d < 64; d++) {
            float4 a = *(const float4*)&Qt[d*FP + ty*4];
            float4 b = *(const float4*)&Kt[d*FP + tx*4];
            float av[4] = {a.x, a.y, a.z, a.w};
            float bv[4] = {b.x, b.y, b.z, b.w};
#pragma unroll
            for (int i = 0; i < 4; i++)
#pragma unroll
                for (int j = 0; j < 4; j++)
                    s4[i][j] = fmaf(av[i], bv[j], s4[i][j]);
        }

        // online softmax per row; 16 tx-threads share a row (shfl width 16)
#pragma unroll
        for (int i = 0; i < 4; i++) {
            float rm = fmaxf(fmaxf(s4[i][0], s4[i][1]), fmaxf(s4[i][2], s4[i][3]));
#pragma unroll
            for (int off = 8; off; off >>= 1)
                rm = fmaxf(rm, __shfl_xor_sync(0xffffffffu, rm, off));
            float mnew  = fmaxf(mrow[i], rm);
            float alpha = __expf(mrow[i] - mnew);
            float rs = 0.f;
#pragma unroll
            for (int j = 0; j < 4; j++) {
                float p = __expf(s4[i][j] - mnew);
                s4[i][j] = p;
                rs += p;
            }
#pragma unroll
            for (int off = 8; off; off >>= 1)
                rs += __shfl_xor_sync(0xffffffffu, rs, off);
            lrow[i] = lrow[i]*alpha + rs;
            mrow[i] = mnew;
#pragma unroll
            for (int j = 0; j < 4; j++) o[i][j] *= alpha;
            *(float4*)&Ps[(ty*4 + i)*FP + tx*4] =
                make_float4(s4[i][0], s4[i][1], s4[i][2], s4[i][3]);
        }
        __syncthreads();

        // O += P @ V
#pragma unroll 8
        for (int j = 0; j < 64; j++) {
            float4 v = *(const float4*)&Vs[j*FP + tx*4];
#pragma unroll
            for (int i = 0; i < 4; i++) {
                float p = Ps[(ty*4 + i)*FP + j];
                o[i][0] = fmaf(p, v.x, o[i][0]);
                o[i][1] = fmaf(p, v.y, o[i][1]);
                o[i][2] = fmaf(p, v.z, o[i][2]);
                o[i][3] = fmaf(p, v.w, o[i][3]);
            }
        }
        __syncthreads();
    }

    // epilogue: normalize + transpose back into [B*S, HIDDEN]
    const int b = bh >> 4, h = bh & 15;
#pragma unroll
    for (int i = 0; i < 4; i++) {
        float inv = 1.0f / lrow[i];
        int srow = q0 + ty*4 + i;
#pragma unroll
        for (int j = 0; j < 4; j++)
            g_ao[((size_t)(b*SEQ + srow))*HIDDEN + h*HEAD_DIM + tx*4 + j] = o[i][j]*inv;
    }
}

// ---------------------------------------------------------------------------
extern "C" void kernel_launch(void* const* d_in, const int* in_sizes, int n_in,
                              void* d_out, int out_size)
{
    const float* X  = (const float*)d_in[0];
    const float* Wq = (const float*)d_in[1];
    const float* bq = (const float*)d_in[2];
    const float* Wk = (const float*)d_in[3];
    const float* bk = (const float*)d_in[4];
    const float* Wv = (const float*)d_in[5];
    const float* bv = (const float*)d_in[6];
    const float* Wo = (const float*)d_in[7];
    const float* bo = (const float*)d_in[8];
    float* out = (float*)d_out;

    // QKV projections (+bias) into [B,H,S,D] scratch
    dim3 gq(HIDDEN/128, MTOT/128, 3);
    qkv_kernel<<<gq, 256>>>(X, Wq, bq, Wk, bk, Wv, bv);

    // RoPE in place on q,k
    rope_kernel<<<(BHN*SEQ*32)/256, 256>>>();

    // flash attention
    static const int FLASH_SMEM = 4*64*FP*4;   // 69632 B
    cudaFuncSetAttribute(flash_kernel,
                         cudaFuncAttributeMaxDynamicSharedMemorySize, FLASH_SMEM);
    dim3 gf(SEQ/64, BHN);
    flash_kernel<<<gf, 256, FLASH_SMEM>>>();

    // output projection
    dim3 go(HIDDEN/128, MTOT/128, 1);
    out_kernel<<<go, 256>>>(Wo, bo, out);
}

// round 4
// speedup vs baseline: 1.2335x; 1.2335x over previous
#include <cuda_runtime.h>
#include <mma.h>
#include <math.h>
#include <cstdint>

using namespace nvcuda;

#define BATCH    2
#define SEQ      2048
#define HIDDEN   1024
#define HEADS    16
#define HEAD_DIM 64
#define MTOT     (BATCH*SEQ)      // 4096
#define BHN      (BATCH*HEADS)    // 32

// scratch (allocation-free rule: __device__ globals)
static __device__ float g_q [BHN*SEQ*HEAD_DIM];   // [B,H,S,D]
static __device__ float g_k [BHN*SEQ*HEAD_DIM];
static __device__ float g_v [BHN*SEQ*HEAD_DIM];
static __device__ float g_ao[MTOT*HIDDEN];        // attention out, [B*S, HIDDEN]

// ---------------------------------------------------------------------------
// wmma tf32 GEMM: C(128x128) = A(128xK) * W(128xK)^T, K=1024, BK=32.
// 8 warps: warp_m = wid&3 (32 rows), warp_n = wid>>2 (64 cols).
// Each warp: 2x4 fragments of 16x16.
// ---------------------------------------------------------------------------
#define BK  32
#define LDA 36   // padded smem leading dim (multiple of 4)

using FragA = wmma::fragment<wmma::matrix_a, 16, 16, 8, wmma::precision::tf32, wmma::row_major>;
using FragB = wmma::fragment<wmma::matrix_b, 16, 16, 8, wmma::precision::tf32, wmma::col_major>;
using FragC = wmma::fragment<wmma::accumulator, 16, 16, 8, float>;

__device__ __forceinline__ void mma_mainloop(const float* __restrict__ A,
                                             const float* __restrict__ W,
                                             float (*As)[LDA], float (*Ws)[LDA],
                                             FragC acc[2][4],
                                             int warp_m, int warp_n)
{
    const int tid = threadIdx.x;
#pragma unroll
    for (int mi = 0; mi < 2; mi++)
#pragma unroll
        for (int ni = 0; ni < 4; ni++)
            wmma::fill_fragment(acc[mi][ni], 0.0f);

    for (int kb = 0; kb < HIDDEN / BK; kb++) {
#pragma unroll
        for (int i = 0; i < 4; i++) {
            int idx = tid + i * 256;        // 0..1023
            int r = idx >> 3;               // 0..127
            int c = (idx & 7) * 4;          // 0..28
            float4 av = *(const float4*)(A + (size_t)r * HIDDEN + kb * BK + c);
            float4 wv = *(const float4*)(W + (size_t)r * HIDDEN + kb * BK + c);
            As[r][c + 0] = wmma::__float_to_tf32(av.x);
            As[r][c + 1] = wmma::__float_to_tf32(av.y);
            As[r][c + 2] = wmma::__float_to_tf32(av.z);
            As[r][c + 3] = wmma::__float_to_tf32(av.w);
            Ws[r][c + 0] = wmma::__float_to_tf32(wv.x);
            Ws[r][c + 1] = wmma::__float_to_tf32(wv.y);
            Ws[r][c + 2] = wmma::__float_to_tf32(wv.z);
            Ws[r][c + 3] = wmma::__float_to_tf32(wv.w);
        }
        __syncthreads();

#pragma unroll
        for (int kk = 0; kk < BK; kk += 8) {
            FragA af[2];
            FragB bf[4];
#pragma unroll
            for (int mi = 0; mi < 2; mi++)
                wmma::load_matrix_sync(af[mi], &As[warp_m * 32 + mi * 16][kk], LDA);
#pragma unroll
            for (int ni = 0; ni < 4; ni++)
                wmma::load_matrix_sync(bf[ni], &Ws[warp_n * 64 + ni * 16][kk], LDA);
#pragma unroll
            for (int mi = 0; mi < 2; mi++)
#pragma unroll
                for (int ni = 0; ni < 4; ni++)
                    wmma::mma_sync(acc[mi][ni], af[mi], bf[ni], acc[mi][ni]);
        }
        __syncthreads();
    }
}

// ---------------------------------------------------------------------------
// QKV projection: grid (8, 32, 3); z selects Q/K/V. Scatter into [B,H,S,D].
// Bias is added later in rope_bias_kernel.
// ---------------------------------------------------------------------------
__global__ void __launch_bounds__(256)
qkv_mma(const float* __restrict__ X,
        const float* __restrict__ Wq,
        const float* __restrict__ Wk,
        const float* __restrict__ Wv)
{
    __shared__ float As[128][LDA];
    __shared__ float Ws[128][LDA];

    const int tid = threadIdx.x, wid = tid >> 5;
    const int warp_m = wid & 3, warp_n = wid >> 2;
    const int m0 = blockIdx.y * 128, n0 = blockIdx.x * 128;

    const float* W; float* dst;
    if      (blockIdx.z == 0) { W = Wq; dst = g_q; }
    else if (blockIdx.z == 1) { W = Wk; dst = g_k; }
    else                      { W = Wv; dst = g_v; }

    FragC acc[2][4];
    mma_mainloop(X + (size_t)m0 * HIDDEN, W + (size_t)n0 * HIDDEN,
                 As, Ws, acc, warp_m, warp_n);

#pragma unroll
    for (int mi = 0; mi < 2; mi++) {
#pragma unroll
        for (int ni = 0; ni < 4; ni++) {
            int m = m0 + warp_m * 32 + mi * 16;
            int n = n0 + warp_n * 64 + ni * 16;
            int b = m >> 11, s = m & (SEQ - 1);
            int h = n >> 6,  d = n & 63;
            float* p = dst + (((size_t)(b * HEADS + h)) * SEQ + s) * HEAD_DIM + d;
            wmma::store_matrix_sync(p, acc[mi][ni], HEAD_DIM, wmma::mem_row_major);
        }
    }
}

// ---------------------------------------------------------------------------
// Output projection: grid (8, 32). Bias added by out_bias_kernel.
// ---------------------------------------------------------------------------
__global__ void __launch_bounds__(256)
out_mma(const float* __restrict__ Wo, float* __restrict__ out)
{
    __shared__ float As[128][LDA];
    __shared__ float Ws[128][LDA];

    const int tid = threadIdx.x, wid = tid >> 5;
    const int warp_m = wid & 3, warp_n = wid >> 2;
    const int m0 = blockIdx.y * 128, n0 = blockIdx.x * 128;

    FragC acc[2][4];
    mma_mainloop(g_ao + (size_t)m0 * HIDDEN, Wo + (size_t)n0 * HIDDEN,
                 As, Ws, acc, warp_m, warp_n);

#pragma unroll
    for (int mi = 0; mi < 2; mi++) {
#pragma unroll
        for (int ni = 0; ni < 4; ni++) {
            int m = m0 + warp_m * 32 + mi * 16;
            int n = n0 + warp_n * 64 + ni * 16;
            wmma::store_matrix_sync(out + (size_t)m * HIDDEN + n,
                                    acc[mi][ni], HIDDEN, wmma::mem_row_major);
        }
    }
}

__global__ void out_bias_kernel(const float* __restrict__ bo, float* __restrict__ out)
{
    int idx = blockIdx.x * blockDim.x + threadIdx.x;   // < MTOT*HIDDEN
    out[idx] += bo[idx & (HIDDEN - 1)];
}

// ---------------------------------------------------------------------------
// Bias + RoPE in-place on g_q, g_k (bias also for g_v).
// One thread per (bh, s, pair i<32).
// ---------------------------------------------------------------------------
__global__ void rope_bias_kernel(const float* __restrict__ bq,
                                 const float* __restrict__ bk,
                                 const float* __restrict__ bv)
{
    int t = blockIdx.x * blockDim.x + threadIdx.x;
    int i  = t & 31;
    int s  = (t >> 5) & (SEQ - 1);
    int bh = t >> 16;                    // SEQ*32 = 65536
    int h  = bh & (HEADS - 1);

    float inv = powf(10000.0f, -(float)i * (1.0f / 32.0f));
    float ang = (float)s * inv;
    float c, sn;
    sincosf(ang, &sn, &c);

    size_t base = ((size_t)bh * SEQ + s) * HEAD_DIM + i;
    int nb = h * HEAD_DIM + i;

    float q1 = g_q[base] + bq[nb], q2 = g_q[base + 32] + bq[nb + 32];
    g_q[base]      = q1 * c - q2 * sn;
    g_q[base + 32] = q2 * c + q1 * sn;

    float k1 = g_k[base] + bk[nb], k2 = g_k[base + 32] + bk[nb + 32];
    g_k[base]      = k1 * c - k2 * sn;
    g_k[base + 32] = k2 * c + k1 * sn;

    g_v[base]      += bv[nb];
    g_v[base + 32] += bv[nb + 32];
}

// ---------------------------------------------------------------------------
// Flash attention (fp32 SIMT): grid (SEQ/64, BHN), 256 threads, 64x64 tiles.
// ---------------------------------------------------------------------------
#define FP 68
__global__ void __launch_bounds__(256)
flash_kernel()
{
    extern __shared__ float sm[];
    float* Qt = sm;
    float* Kt = Qt + 64 * FP;
    float* Vs = Kt + 64 * FP;
    float* Ps = Vs + 64 * FP;

    const int tid = threadIdx.x;
    const int ty  = tid >> 4;
    const int tx  = tid & 15;
    const int bh  = blockIdx.y;
    const int q0  = blockIdx.x * 64;

    const float* qbase = g_q + ((size_t)bh * SEQ + q0) * HEAD_DIM;
    for (int e = tid; e < 64 * 64; e += 256) {
        int r = e >> 6, d = e & 63;
        Qt[d * FP + r] = qbase[e] * 0.125f;
    }

    float mrow[4], lrow[4], o[4][4];
#pragma unroll
    for (int i = 0; i < 4; i++) {
        mrow[i] = -1e30f; lrow[i] = 0.f;
#pragma unroll
        for (int j = 0; j < 4; j++) o[i][j] = 0.f;
    }

    for (int kt = 0; kt < SEQ / 64; kt++) {
        const float* kbase = g_k + ((size_t)bh * SEQ + kt * 64) * HEAD_DIM;
        const float* vbase = g_v + ((size_t)bh * SEQ + kt * 64) * HEAD_DIM;
        for (int e = tid; e < 64 * 64; e += 256) {
            int r = e >> 6, d = e & 63;
            Kt[d * FP + r] = kbase[e];
            Vs[r * FP + d] = vbase[e];
        }
        __syncthreads();

        float s4[4][4];
#pragma unroll
        for (int i = 0; i < 4; i++)
#pragma unroll
            for (int j = 0; j < 4; j++) s4[i][j] = 0.f;

#pragma unroll 8
        for (int d = 0; d < 64; d++) {
            float4 a = *(const float4*)&Qt[d * FP + ty * 4];
            float4 b = *(const float4*)&Kt[d * FP + tx * 4];
            float av[4] = {a.x, a.y, a.z, a.w};
            float bv4[4] = {b.x, b.y, b.z, b.w};
#pragma unroll
            for (int i = 0; i < 4; i++)
#pragma unroll
                for (int j = 0; j < 4; j++)
                    s4[i][j] = fmaf(av[i], bv4[j], s4[i][j]);
        }

#pragma unroll
        for (int i = 0; i < 4; i++) {
            float rm = fmaxf(fmaxf(s4[i][0], s4[i][1]), fmaxf(s4[i][2], s4[i][3]));
#pragma unroll
            for (int off = 8; off; off >>= 1)
                rm = fmaxf(rm, __shfl_xor_sync(0xffffffffu, rm, off));
            float mnew  = fmaxf(mrow[i], rm);
            float alpha = __expf(mrow[i] - mnew);
            float rs = 0.f;
#pragma unroll
            for (int j = 0; j < 4; j++) {
                float p = __expf(s4[i][j] - mnew);
                s4[i][j] = p;
                rs += p;
            }
#pragma unroll
            for (int off = 8; off; off >>= 1)
                rs += __shfl_xor_sync(0xffffffffu, rs, off);
            lrow[i] = lrow[i] * alpha + rs;
            mrow[i] = mnew;
#pragma unroll
            for (int j = 0; j < 4; j++) o[i][j] *= alpha;
            *(float4*)&Ps[(ty * 4 + i) * FP + tx * 4] =
                make_float4(s4[i][0], s4[i][1], s4[i][2], s4[i][3]);
        }
        __syncthreads();

#pragma unroll 8
        for (int j = 0; j < 64; j++) {
            float4 v = *(const float4*)&Vs[j * FP + tx * 4];
#pragma unroll
            for (int i = 0; i < 4; i++) {
                float p = Ps[(ty * 4 + i) * FP + j];
                o[i][0] = fmaf(p, v.x, o[i][0]);
                o[i][1] = fmaf(p, v.y, o[i][1]);
                o[i][2] = fmaf(p, v.z, o[i][2]);
                o[i][3] = fmaf(p, v.w, o[i][3]);
            }
        }
        __syncthreads();
    }

    const int b = bh >> 4, h = bh & 15;
#pragma unroll
    for (int i = 0; i < 4; i++) {
        float inv = 1.0f / lrow[i];
        int srow = q0 + ty * 4 + i;
#pragma unroll
        for (int j = 0; j < 4; j++)
            g_ao[((size_t)(b * SEQ + srow)) * HIDDEN + h * HEAD_DIM + tx * 4 + j] = o[i][j] * inv;
    }
}

// ---------------------------------------------------------------------------
extern "C" void kernel_launch(void* const* d_in, const int* in_sizes, int n_in,
                              void* d_out, int out_size)
{
    const float* X  = (const float*)d_in[0];
    const float* Wq = (const float*)d_in[1];
    const float* bq = (const float*)d_in[2];
    const float* Wk = (const float*)d_in[3];
    const float* bk = (const float*)d_in[4];
    const float* Wv = (const float*)d_in[5];
    const float* bv = (const float*)d_in[6];
    const float* Wo = (const float*)d_in[7];
    const float* bo = (const float*)d_in[8];
    float* out = (float*)d_out;

    // QKV projections (no bias) into [B,H,S,D] scratch
    dim3 gq(HIDDEN / 128, MTOT / 128, 3);
    qkv_mma<<<gq, 256>>>(X, Wq, Wk, Wv);

    // bias + RoPE
    rope_bias_kernel<<<(BHN * SEQ * 32) / 256, 256>>>(bq, bk, bv);

    // flash attention
    static const int FLASH_SMEM = 4 * 64 * FP * 4;   // 69632 B
    cudaFuncSetAttribute(flash_kernel,
                         cudaFuncAttributeMaxDynamicSharedMemorySize, FLASH_SMEM);
    dim3 gf(SEQ / 64, BHN);
    flash_kernel<<<gf, 256, FLASH_SMEM>>>();

    // output projection + bias
    dim3 go(HIDDEN / 128, MTOT / 128, 1);
    out_mma<<<go, 256>>>(Wo, out);
    out_bias_kernel<<<(MTOT * HIDDEN) / 256, 256>>>(bo, out);
}

// round 5
// speedup vs baseline: 1.4021x; 1.1367x over previous
#include <cuda_runtime.h>
#include <mma.h>
#include <math.h>
#include <cstdint>

using namespace nvcuda;

#define BATCH    2
#define SEQ      2048
#define HIDDEN   1024
#define HEADS    16
#define HEAD_DIM 64
#define MTOT     (BATCH*SEQ)      // 4096
#define BHN      (BATCH*HEADS)    // 32

// scratch (allocation-free rule: __device__ globals)
static __device__ float g_q [BHN*SEQ*HEAD_DIM];   // [B,H,S,D]
static __device__ float g_k [BHN*SEQ*HEAD_DIM];
static __device__ float g_v [BHN*SEQ*HEAD_DIM];
static __device__ float g_ao[MTOT*HIDDEN];        // attention out, [B*S, HIDDEN]

// ---------------------------------------------------------------------------
// wmma tf32 GEMM: C(128x128) = A(128xK) * W(128xK)^T, K=1024, BK=32.
// ---------------------------------------------------------------------------
#define BK  32
#define LDA 36

using FragA = wmma::fragment<wmma::matrix_a, 16, 16, 8, wmma::precision::tf32, wmma::row_major>;
using FragB = wmma::fragment<wmma::matrix_b, 16, 16, 8, wmma::precision::tf32, wmma::col_major>;
using FragBR = wmma::fragment<wmma::matrix_b, 16, 16, 8, wmma::precision::tf32, wmma::row_major>;
using FragC = wmma::fragment<wmma::accumulator, 16, 16, 8, float>;

__device__ __forceinline__ void mma_mainloop(const float* __restrict__ A,
                                             const float* __restrict__ W,
                                             float (*As)[LDA], float (*Ws)[LDA],
                                             FragC acc[2][4],
                                             int warp_m, int warp_n)
{
    const int tid = threadIdx.x;
#pragma unroll
    for (int mi = 0; mi < 2; mi++)
#pragma unroll
        for (int ni = 0; ni < 4; ni++)
            wmma::fill_fragment(acc[mi][ni], 0.0f);

    for (int kb = 0; kb < HIDDEN / BK; kb++) {
#pragma unroll
        for (int i = 0; i < 4; i++) {
            int idx = tid + i * 256;
            int r = idx >> 3;
            int c = (idx & 7) * 4;
            float4 av = *(const float4*)(A + (size_t)r * HIDDEN + kb * BK + c);
            float4 wv = *(const float4*)(W + (size_t)r * HIDDEN + kb * BK + c);
            As[r][c + 0] = wmma::__float_to_tf32(av.x);
            As[r][c + 1] = wmma::__float_to_tf32(av.y);
            As[r][c + 2] = wmma::__float_to_tf32(av.z);
            As[r][c + 3] = wmma::__float_to_tf32(av.w);
            Ws[r][c + 0] = wmma::__float_to_tf32(wv.x);
            Ws[r][c + 1] = wmma::__float_to_tf32(wv.y);
            Ws[r][c + 2] = wmma::__float_to_tf32(wv.z);
            Ws[r][c + 3] = wmma::__float_to_tf32(wv.w);
        }
        __syncthreads();

#pragma unroll
        for (int kk = 0; kk < BK; kk += 8) {
            FragA af[2];
            FragB bf[4];
#pragma unroll
            for (int mi = 0; mi < 2; mi++)
                wmma::load_matrix_sync(af[mi], &As[warp_m * 32 + mi * 16][kk], LDA);
#pragma unroll
            for (int ni = 0; ni < 4; ni++)
                wmma::load_matrix_sync(bf[ni], &Ws[warp_n * 64 + ni * 16][kk], LDA);
#pragma unroll
            for (int mi = 0; mi < 2; mi++)
#pragma unroll
                for (int ni = 0; ni < 4; ni++)
                    wmma::mma_sync(acc[mi][ni], af[mi], bf[ni], acc[mi][ni]);
        }
        __syncthreads();
    }
}

// ---------------------------------------------------------------------------
__global__ void __launch_bounds__(256)
qkv_mma(const float* __restrict__ X,
        const float* __restrict__ Wq,
        const float* __restrict__ Wk,
        const float* __restrict__ Wv)
{
    __shared__ float As[128][LDA];
    __shared__ float Ws[128][LDA];

    const int tid = threadIdx.x, wid = tid >> 5;
    const int warp_m = wid & 3, warp_n = wid >> 2;
    const int m0 = blockIdx.y * 128, n0 = blockIdx.x * 128;

    const float* W; float* dst;
    if      (blockIdx.z == 0) { W = Wq; dst = g_q; }
    else if (blockIdx.z == 1) { W = Wk; dst = g_k; }
    else                      { W = Wv; dst = g_v; }

    FragC acc[2][4];
    mma_mainloop(X + (size_t)m0 * HIDDEN, W + (size_t)n0 * HIDDEN,
                 As, Ws, acc, warp_m, warp_n);

#pragma unroll
    for (int mi = 0; mi < 2; mi++) {
#pragma unroll
        for (int ni = 0; ni < 4; ni++) {
            int m = m0 + warp_m * 32 + mi * 16;
            int n = n0 + warp_n * 64 + ni * 16;
            int b = m >> 11, s = m & (SEQ - 1);
            int h = n >> 6,  d = n & 63;
            float* p = dst + (((size_t)(b * HEADS + h)) * SEQ + s) * HEAD_DIM + d;
            wmma::store_matrix_sync(p, acc[mi][ni], HEAD_DIM, wmma::mem_row_major);
        }
    }
}

// ---------------------------------------------------------------------------
__global__ void __launch_bounds__(256)
out_mma(const float* __restrict__ Wo, float* __restrict__ out)
{
    __shared__ float As[128][LDA];
    __shared__ float Ws[128][LDA];

    const int tid = threadIdx.x, wid = tid >> 5;
    const int warp_m = wid & 3, warp_n = wid >> 2;
    const int m0 = blockIdx.y * 128, n0 = blockIdx.x * 128;

    FragC acc[2][4];
    mma_mainloop(g_ao + (size_t)m0 * HIDDEN, Wo + (size_t)n0 * HIDDEN,
                 As, Ws, acc, warp_m, warp_n);

#pragma unroll
    for (int mi = 0; mi < 2; mi++) {
#pragma unroll
        for (int ni = 0; ni < 4; ni++) {
            int m = m0 + warp_m * 32 + mi * 16;
            int n = n0 + warp_n * 64 + ni * 16;
            wmma::store_matrix_sync(out + (size_t)m * HIDDEN + n,
                                    acc[mi][ni], HIDDEN, wmma::mem_row_major);
        }
    }
}

__global__ void out_bias_kernel(const float* __restrict__ bo, float* __restrict__ out)
{
    int idx = blockIdx.x * blockDim.x + threadIdx.x;
    out[idx] += bo[idx & (HIDDEN - 1)];
}

// ---------------------------------------------------------------------------
// Bias + RoPE in-place on g_q (pre-scaled by 1/8), g_k; bias for g_v.
// ---------------------------------------------------------------------------
__global__ void rope_bias_kernel(const float* __restrict__ bq,
                                 const float* __restrict__ bk,
                                 const float* __restrict__ bv)
{
    int t = blockIdx.x * blockDim.x + threadIdx.x;
    int i  = t & 31;
    int s  = (t >> 5) & (SEQ - 1);
    int bh = t >> 16;
    int h  = bh & (HEADS - 1);

    float inv = powf(10000.0f, -(float)i * (1.0f / 32.0f));
    float ang = (float)s * inv;
    float c, sn;
    sincosf(ang, &sn, &c);

    size_t base = ((size_t)bh * SEQ + s) * HEAD_DIM + i;
    int nb = h * HEAD_DIM + i;

    float q1 = g_q[base] + bq[nb], q2 = g_q[base + 32] + bq[nb + 32];
    g_q[base]      = (q1 * c - q2 * sn) * 0.125f;   // fold 1/sqrt(64)
    g_q[base + 32] = (q2 * c + q1 * sn) * 0.125f;

    float k1 = g_k[base] + bk[nb], k2 = g_k[base + 32] + bk[nb + 32];
    g_k[base]      = k1 * c - k2 * sn;
    g_k[base + 32] = k2 * c + k1 * sn;

    g_v[base]      += bv[nb];
    g_v[base + 32] += bv[nb + 32];
}

// ---------------------------------------------------------------------------
// Flash attention (wmma tf32): grid (SEQ/64, BHN), 256 threads / 8 warps.
// Warp (rb=wid&3, cb=wid>>2) owns S/O block [16 rows x 32 cols].
// ---------------------------------------------------------------------------
#define FPAD 72
__global__ void __launch_bounds__(256)
flash_wmma()
{
    extern __shared__ float sm[];
    float* Qs = sm;                  // [64][FPAD] row=q, col=d   (tf32)
    float* Ks = Qs + 64 * FPAD;      // [64][FPAD] row=key, col=d (tf32)
    float* Vs = Ks + 64 * FPAD;      // [64][FPAD] row=key, col=d (tf32)
    float* Ps = Vs + 64 * FPAD;      // [64][FPAD] scores/probs
    float* Os = Ps + 64 * FPAD;      // [64][FPAD] output accum (fp32)
    float* mS = Os + 64 * FPAD;      // [64]
    float* lS = mS + 64;             // [64]

    const int tid = threadIdx.x, wid = tid >> 5;
    const int rb = wid & 3, cb = wid >> 2;
    const int bh = blockIdx.y;
    const int q0 = blockIdx.x * 64;

    // load Q (already scaled), zero O, init m/l
    const float* qbase = g_q + ((size_t)bh * SEQ + q0) * HEAD_DIM;
#pragma unroll
    for (int i = 0; i < 4; i++) {
        int e = tid + i * 256;               // 0..1023
        int r = e >> 4, c = (e & 15) * 4;    // 64 rows x 64 cols
        float4 v = *(const float4*)(qbase + r * HEAD_DIM + c);
        float* qrow = Qs + r * FPAD + c;
        qrow[0] = wmma::__float_to_tf32(v.x);
        qrow[1] = wmma::__float_to_tf32(v.y);
        qrow[2] = wmma::__float_to_tf32(v.z);
        qrow[3] = wmma::__float_to_tf32(v.w);
        float* orow = Os + r * FPAD + c;
        orow[0] = 0.f; orow[1] = 0.f; orow[2] = 0.f; orow[3] = 0.f;
    }
    if (tid < 64) { mS[tid] = -1e30f; lS[tid] = 0.f; }
    __syncthreads();

    for (int kt = 0; kt < SEQ / 64; kt++) {
        const float* kbase = g_k + ((size_t)bh * SEQ + kt * 64) * HEAD_DIM;
        const float* vbase = g_v + ((size_t)bh * SEQ + kt * 64) * HEAD_DIM;
#pragma unroll
        for (int i = 0; i < 4; i++) {
            int e = tid + i * 256;
            int r = e >> 4, c = (e & 15) * 4;
            float4 kv = *(const float4*)(kbase + r * HEAD_DIM + c);
            float4 vv = *(const float4*)(vbase + r * HEAD_DIM + c);
            float* krow = Ks + r * FPAD + c;
            krow[0] = wmma::__float_to_tf32(kv.x);
            krow[1] = wmma::__float_to_tf32(kv.y);
            krow[2] = wmma::__float_to_tf32(kv.z);
            krow[3] = wmma::__float_to_tf32(kv.w);
            float* vrow = Vs + r * FPAD + c;
            vrow[0] = wmma::__float_to_tf32(vv.x);
            vrow[1] = wmma::__float_to_tf32(vv.y);
            vrow[2] = wmma::__float_to_tf32(vv.z);
            vrow[3] = wmma::__float_to_tf32(vv.w);
        }
        __syncthreads();

        // S[16x32] = Q[16x64] * K^T
        {
            FragC sacc[2];
            wmma::fill_fragment(sacc[0], 0.f);
            wmma::fill_fragment(sacc[1], 0.f);
#pragma unroll
            for (int kk = 0; kk < 64; kk += 8) {
                FragA af;
                wmma::load_matrix_sync(af, Qs + (rb * 16) * FPAD + kk, FPAD);
#pragma unroll
                for (int ni = 0; ni < 2; ni++) {
                    FragB bf;
                    wmma::load_matrix_sync(bf, Ks + (cb * 32 + ni * 16) * FPAD + kk, FPAD);
                    wmma::mma_sync(sacc[ni], af, bf, sacc[ni]);
                }
            }
#pragma unroll
            for (int ni = 0; ni < 2; ni++)
                wmma::store_matrix_sync(Ps + (rb * 16) * FPAD + cb * 32 + ni * 16,
                                        sacc[ni], FPAD, wmma::mem_row_major);
        }
        __syncthreads();

        // online softmax: 4 threads per row, 16 cols each
        {
            int row = tid >> 2, q = tid & 3;
            float* prow = Ps + row * FPAD + q * 16;
            float rm = -1e30f;
#pragma unroll
            for (int j = 0; j < 16; j++) rm = fmaxf(rm, prow[j]);
            rm = fmaxf(rm, __shfl_xor_sync(0xffffffffu, rm, 1));
            rm = fmaxf(rm, __shfl_xor_sync(0xffffffffu, rm, 2));
            float mold = mS[row];
            float mnew = fmaxf(mold, rm);
            float rs = 0.f;
#pragma unroll
            for (int j = 0; j < 16; j++) {
                float p = __expf(prow[j] - mnew);
                prow[j] = wmma::__float_to_tf32(p);
                rs += p;
            }
            rs += __shfl_xor_sync(0xffffffffu, rs, 1);
            rs += __shfl_xor_sync(0xffffffffu, rs, 2);
            float alpha = __expf(mold - mnew);
            if (q == 0) {
                mS[row] = mnew;
                lS[row] = lS[row] * alpha + rs;
            }
            // rescale O row
            float* orow = Os + row * FPAD + q * 16;
#pragma unroll
            for (int j = 0; j < 16; j += 4) {
                float4 o4 = *(float4*)(orow + j);
                o4.x *= alpha; o4.y *= alpha; o4.z *= alpha; o4.w *= alpha;
                *(float4*)(orow + j) = o4;
            }
        }
        __syncthreads();

        // O[16x32] += P[16x64] * V[64x32]
        {
            FragC oacc[2];
#pragma unroll
            for (int ni = 0; ni < 2; ni++)
                wmma::load_matrix_sync(oacc[ni],
                    Os + (rb * 16) * FPAD + cb * 32 + ni * 16, FPAD, wmma::mem_row_major);
#pragma unroll
            for (int kk = 0; kk < 64; kk += 8) {
                FragA af;
                wmma::load_matrix_sync(af, Ps + (rb * 16) * FPAD + kk, FPAD);
#pragma unroll
                for (int ni = 0; ni < 2; ni++) {
                    FragBR bf;
                    wmma::load_matrix_sync(bf, Vs + kk * FPAD + cb * 32 + ni * 16, FPAD);
                    wmma::mma_sync(oacc[ni], af, bf, oacc[ni]);
                }
            }
#pragma unroll
            for (int ni = 0; ni < 2; ni++)
                wmma::store_matrix_sync(Os + (rb * 16) * FPAD + cb * 32 + ni * 16,
                                        oacc[ni], FPAD, wmma::mem_row_major);
        }
        __syncthreads();
    }

    // epilogue: normalize + write to g_ao
    const int b = bh >> 4, h = bh & 15;
#pragma unroll
    for (int i = 0; i < 4; i++) {
        int e = tid + i * 256;
        int r = e >> 4, c = (e & 15) * 4;
        float inv = 1.0f / lS[r];
        float4 o4 = *(const float4*)(Os + r * FPAD + c);
        o4.x *= inv; o4.y *= inv; o4.z *= inv; o4.w *= inv;
        *(float4*)(g_ao + ((size_t)(b * SEQ + q0 + r)) * HIDDEN + h * HEAD_DIM + c) = o4;
    }
}

// ---------------------------------------------------------------------------
extern "C" void kernel_launch(void* const* d_in, const int* in_sizes, int n_in,
                              void* d_out, int out_size)
{
    const float* X  = (const float*)d_in[0];
    const float* Wq = (const float*)d_in[1];
    const float* bq = (const float*)d_in[2];
    const float* Wk = (const float*)d_in[3];
    const float* bk = (const float*)d_in[4];
    const float* Wv = (const float*)d_in[5];
    const float* bv = (const float*)d_in[6];
    const float* Wo = (const float*)d_in[7];
    const float* bo = (const float*)d_in[8];
    float* out = (float*)d_out;

    dim3 gq(HIDDEN / 128, MTOT / 128, 3);
    qkv_mma<<<gq, 256>>>(X, Wq, Wk, Wv);

    rope_bias_kernel<<<(BHN * SEQ * 32) / 256, 256>>>(bq, bk, bv);

    static const int FLASH_SMEM = (5 * 64 * FPAD + 128) * 4;   // 92672 B
    cudaFuncSetAttribute(flash_wmma,
                         cudaFuncAttributeMaxDynamicSharedMemorySize, FLASH_SMEM);
    dim3 gf(SEQ / 64, BHN);
    flash_wmma<<<gf, 256, FLASH_SMEM>>>();

    dim3 go(HIDDEN / 128, MTOT / 128, 1);
    out_mma<<<go, 256>>>(Wo, out);
    out_bias_kernel<<<(MTOT * HIDDEN) / 256, 256>>>(bo, out);
}

// round 6
// speedup vs baseline: 2.0108x; 1.4341x over previous
#include <cuda_runtime.h>
#include <mma.h>
#include <math.h>
#include <cstdint>

using namespace nvcuda;

#define BATCH    2
#define SEQ      2048
#define HIDDEN   1024
#define HEADS    16
#define HEAD_DIM 64
#define MTOT     (BATCH*SEQ)      // 4096
#define BHN      (BATCH*HEADS)    // 32

// scratch (allocation-free rule: __device__ globals)
static __device__ float g_q [BHN*SEQ*HEAD_DIM];   // [B,H,S,D]
static __device__ float g_k [BHN*SEQ*HEAD_DIM];
static __device__ float g_v [BHN*SEQ*HEAD_DIM];
static __device__ float g_ao[MTOT*HIDDEN];        // attention out, [B*S, HIDDEN]

// ---------------------------------------------------------------------------
// helpers
// ---------------------------------------------------------------------------
__device__ __forceinline__ void cp16(uint32_t dst, const void* src) {
    asm volatile("cp.async.cg.shared.global [%0], [%1], 16;" :: "r"(dst), "l"(src));
}
__device__ __forceinline__ void cp_commit() {
    asm volatile("cp.async.commit_group;" ::: "memory");
}
__device__ __forceinline__ void cp_wait0() {
    asm volatile("cp.async.wait_group 0;" ::: "memory");
}
// mma.sync m16n8k8 tf32: D += A*B, A row-major 16x8, B col-major 8x8
__device__ __forceinline__ void mma8(float d[4], const float a[4], float b0, float b1)
{
    asm volatile(
        "mma.sync.aligned.m16n8k8.row.col.f32.tf32.tf32.f32 "
        "{%0,%1,%2,%3}, {%4,%5,%6,%7}, {%8,%9}, {%0,%1,%2,%3};"
        : "+f"(d[0]), "+f"(d[1]), "+f"(d[2]), "+f"(d[3])
        : "r"(__float_as_uint(a[0])), "r"(__float_as_uint(a[1])),
          "r"(__float_as_uint(a[2])), "r"(__float_as_uint(a[3])),
          "r"(__float_as_uint(b0)),  "r"(__float_as_uint(b1)));
}

// ---------------------------------------------------------------------------
// wmma tf32 GEMM: C(128x128) = A(128xK) * W(128xK)^T, K=1024, BK=32.
// double-buffered smem + register prefetch. 8 warps, warp = (wm=wid&3, wn=wid>>2).
// ---------------------------------------------------------------------------
#define BK  32
#define LDA 36
#define GSTG (2*128*LDA)          // floats per stage (A+W)

using FragA = wmma::fragment<wmma::matrix_a, 16, 16, 8, wmma::precision::tf32, wmma::row_major>;
using FragB = wmma::fragment<wmma::matrix_b, 16, 16, 8, wmma::precision::tf32, wmma::col_major>;
using FragC = wmma::fragment<wmma::accumulator, 16, 16, 8, float>;

__device__ __forceinline__ void mma_mainloop(const float* __restrict__ A,
                                             const float* __restrict__ W,
                                             float* sm, FragC acc[2][4],
                                             int wm, int wn)
{
    const int tid = threadIdx.x;
#pragma unroll
    for (int mi = 0; mi < 2; mi++)
#pragma unroll
        for (int ni = 0; ni < 4; ni++)
            wmma::fill_fragment(acc[mi][ni], 0.0f);

    float4 pa[4], pw[4];
#pragma unroll
    for (int i = 0; i < 4; i++) {
        int idx = tid + i * 256;
        int r = idx >> 3, c = (idx & 7) * 4;
        pa[i] = *(const float4*)(A + (size_t)r * HIDDEN + c);
        pw[i] = *(const float4*)(W + (size_t)r * HIDDEN + c);
    }

    int s = 0;
    for (int kb = 0; kb < HIDDEN / BK; kb++) {
        float* As = sm + s * GSTG;
        float* Ws = As + 128 * LDA;
#pragma unroll
        for (int i = 0; i < 4; i++) {
            int idx = tid + i * 256;
            int r = idx >> 3, c = (idx & 7) * 4;
            As[r * LDA + c + 0] = wmma::__float_to_tf32(pa[i].x);
            As[r * LDA + c + 1] = wmma::__float_to_tf32(pa[i].y);
            As[r * LDA + c + 2] = wmma::__float_to_tf32(pa[i].z);
            As[r * LDA + c + 3] = wmma::__float_to_tf32(pa[i].w);
            Ws[r * LDA + c + 0] = wmma::__float_to_tf32(pw[i].x);
            Ws[r * LDA + c + 1] = wmma::__float_to_tf32(pw[i].y);
            Ws[r * LDA + c + 2] = wmma::__float_to_tf32(pw[i].z);
            Ws[r * LDA + c + 3] = wmma::__float_to_tf32(pw[i].w);
        }
        if (kb + 1 < HIDDEN / BK) {
#pragma unroll
            for (int i = 0; i < 4; i++) {
                int idx = tid + i * 256;
                int r = idx >> 3, c = (idx & 7) * 4;
                pa[i] = *(const float4*)(A + (size_t)r * HIDDEN + (kb + 1) * BK + c);
                pw[i] = *(const float4*)(W + (size_t)r * HIDDEN + (kb + 1) * BK + c);
            }
        }
        __syncthreads();
#pragma unroll
        for (int kk = 0; kk < BK; kk += 8) {
            FragA af[2];
            FragB bf[4];
#pragma unroll
            for (int mi = 0; mi < 2; mi++)
                wmma::load_matrix_sync(af[mi], &As[(wm * 32 + mi * 16) * LDA + kk], LDA);
#pragma unroll
            for (int ni = 0; ni < 4; ni++)
                wmma::load_matrix_sync(bf[ni], &Ws[(wn * 64 + ni * 16) * LDA + kk], LDA);
#pragma unroll
            for (int mi = 0; mi < 2; mi++)
#pragma unroll
                for (int ni = 0; ni < 4; ni++)
                    wmma::mma_sync(acc[mi][ni], af[mi], bf[ni], acc[mi][ni]);
        }
        s ^= 1;
        __syncthreads();
    }
}

// ---------------------------------------------------------------------------
__global__ void __launch_bounds__(256)
qkv_mma(const float* __restrict__ X,
        const float* __restrict__ Wq,
        const float* __restrict__ Wk,
        const float* __restrict__ Wv)
{
    extern __shared__ float gsm[];
    const int tid = threadIdx.x, wid = tid >> 5;
    const int wm = wid & 3, wn = wid >> 2;
    const int m0 = blockIdx.y * 128, n0 = blockIdx.x * 128;

    const float* W; float* dst;
    if      (blockIdx.z == 0) { W = Wq; dst = g_q; }
    else if (blockIdx.z == 1) { W = Wk; dst = g_k; }
    else                      { W = Wv; dst = g_v; }

    FragC acc[2][4];
    mma_mainloop(X + (size_t)m0 * HIDDEN, W + (size_t)n0 * HIDDEN, gsm, acc, wm, wn);

#pragma unroll
    for (int mi = 0; mi < 2; mi++) {
#pragma unroll
        for (int ni = 0; ni < 4; ni++) {
            int m = m0 + wm * 32 + mi * 16;
            int n = n0 + wn * 64 + ni * 16;
            int b = m >> 11, s = m & (SEQ - 1);
            int h = n >> 6,  d = n & 63;
            float* p = dst + (((size_t)(b * HEADS + h)) * SEQ + s) * HEAD_DIM + d;
            wmma::store_matrix_sync(p, acc[mi][ni], HEAD_DIM, wmma::mem_row_major);
        }
    }
}

// ---------------------------------------------------------------------------
__global__ void __launch_bounds__(256)
out_mma(const float* __restrict__ Wo, float* __restrict__ out)
{
    extern __shared__ float gsm[];
    const int tid = threadIdx.x, wid = tid >> 5;
    const int wm = wid & 3, wn = wid >> 2;
    const int m0 = blockIdx.y * 128, n0 = blockIdx.x * 128;

    FragC acc[2][4];
    mma_mainloop(g_ao + (size_t)m0 * HIDDEN, Wo + (size_t)n0 * HIDDEN, gsm, acc, wm, wn);

#pragma unroll
    for (int mi = 0; mi < 2; mi++) {
#pragma unroll
        for (int ni = 0; ni < 4; ni++) {
            int m = m0 + wm * 32 + mi * 16;
            int n = n0 + wn * 64 + ni * 16;
            wmma::store_matrix_sync(out + (size_t)m * HIDDEN + n,
                                    acc[mi][ni], HIDDEN, wmma::mem_row_major);
        }
    }
}

__global__ void out_bias_kernel(const float* __restrict__ bo, float* __restrict__ out)
{
    int idx = blockIdx.x * blockDim.x + threadIdx.x;
    out[idx] += bo[idx & (HIDDEN - 1)];
}

// ---------------------------------------------------------------------------
// Bias + RoPE in-place on g_q (pre-scaled by 1/8), g_k; bias for g_v.
// ---------------------------------------------------------------------------
__global__ void rope_bias_kernel(const float* __restrict__ bq,
                                 const float* __restrict__ bk,
                                 const float* __restrict__ bv)
{
    int t = blockIdx.x * blockDim.x + threadIdx.x;
    int i  = t & 31;
    int s  = (t >> 5) & (SEQ - 1);
    int bh = t >> 16;
    int h  = bh & (HEADS - 1);

    float inv = powf(10000.0f, -(float)i * (1.0f / 32.0f));
    float ang = (float)s * inv;
    float c, sn;
    sincosf(ang, &sn, &c);

    size_t base = ((size_t)bh * SEQ + s) * HEAD_DIM + i;
    int nb = h * HEAD_DIM + i;

    float q1 = g_q[base] + bq[nb], q2 = g_q[base + 32] + bq[nb + 32];
    g_q[base]      = (q1 * c - q2 * sn) * 0.125f;
    g_q[base + 32] = (q2 * c + q1 * sn) * 0.125f;

    float k1 = g_k[base] + bk[nb], k2 = g_k[base + 32] + bk[nb + 32];
    g_k[base]      = k1 * c - k2 * sn;
    g_k[base + 32] = k2 * c + k1 * sn;

    g_v[base]      += bv[nb];
    g_v[base + 32] += bv[nb + 32];
}

// ---------------------------------------------------------------------------
// Flash attention, raw mma.sync m16n8k8 tf32.
// grid (SEQ/128, BHN), 256 threads / 8 warps; warp wid owns q-rows [wid*16, +16).
// Q in registers (whole kernel), O accumulators in registers, softmax in regs.
// K/V double-buffered smem via cp.async. P: one smem store + A-frag reload.
// ---------------------------------------------------------------------------
#define FPAD 68
#define KVSTG (64*FPAD)

__global__ void __launch_bounds__(256)
flash_mma()
{
    extern __shared__ float fsm[];
    float* KsB = fsm;                 // 2 stages [64][FPAD]
    float* VsB = fsm + 2 * KVSTG;     // 2 stages [64][FPAD]
    float* Ps  = fsm + 4 * KVSTG;     // [128][FPAD]

    const int tid = threadIdx.x, wid = tid >> 5, lane = tid & 31;
    const int g = lane >> 2, t = lane & 3;
    const int bh = blockIdx.y;
    const int q0 = blockIdx.x * 128;
    const int r0 = wid * 16;

    // ---- Q into A-fragments (RN tf32), held for the whole kernel ----
    const float* qb = g_q + ((size_t)bh * SEQ + q0 + r0) * HEAD_DIM;
    float qa[8][4];
#pragma unroll
    for (int kb = 0; kb < 8; kb++) {
        qa[kb][0] = wmma::__float_to_tf32(qb[(g    ) * 64 + kb * 8 + t    ]);
        qa[kb][1] = wmma::__float_to_tf32(qb[(g + 8) * 64 + kb * 8 + t    ]);
        qa[kb][2] = wmma::__float_to_tf32(qb[(g    ) * 64 + kb * 8 + t + 4]);
        qa[kb][3] = wmma::__float_to_tf32(qb[(g + 8) * 64 + kb * 8 + t + 4]);
    }

    float oacc[8][4];
#pragma unroll
    for (int nb = 0; nb < 8; nb++)
#pragma unroll
        for (int e = 0; e < 4; e++) oacc[nb][e] = 0.f;
    float mA = -1e30f, mB = -1e30f, lA = 0.f, lB = 0.f;

    // K/V tile loader (cp.async)
    const float* kbase = g_k + (size_t)bh * SEQ * HEAD_DIM;
    const float* vbase = g_v + (size_t)bh * SEQ * HEAD_DIM;
    auto issue = [&](int kt, int s) {
        float* Kd = KsB + s * KVSTG;
        float* Vd = VsB + s * KVSTG;
        const float* ks = kbase + (size_t)kt * 64 * HEAD_DIM;
        const float* vs = vbase + (size_t)kt * 64 * HEAD_DIM;
#pragma unroll
        for (int i = 0; i < 4; i++) {
            int idx = tid + i * 256;              // 1024 float4s
            int r = idx >> 4, c = (idx & 15) * 4;
            cp16((uint32_t)__cvta_generic_to_shared(Kd + r * FPAD + c), ks + r * 64 + c);
            cp16((uint32_t)__cvta_generic_to_shared(Vd + r * FPAD + c), vs + r * 64 + c);
        }
        cp_commit();
    };

    issue(0, 0);

    for (int kt = 0; kt < SEQ / 64; kt++) {
        int s = kt & 1;
        cp_wait0();
        __syncthreads();
        if (kt + 1 < SEQ / 64) issue(kt + 1, s ^ 1);

        const float* K = KsB + s * KVSTG;
        const float* V = VsB + s * KVSTG;

        // ---- S = Q K^T  (16 rows x 64 keys per warp) ----
        float sacc[8][4];
#pragma unroll
        for (int nb = 0; nb < 8; nb++)
#pragma unroll
            for (int e = 0; e < 4; e++) sacc[nb][e] = 0.f;

#pragma unroll
        for (int kb = 0; kb < 8; kb++) {
#pragma unroll
            for (int nb = 0; nb < 8; nb++) {
                float b0 = K[(nb * 8 + g) * FPAD + kb * 8 + t    ];
                float b1 = K[(nb * 8 + g) * FPAD + kb * 8 + t + 4];
                mma8(sacc[nb], qa[kb], b0, b1);
            }
        }

        // ---- online softmax in registers (rows rA=g, rB=g+8 of warp tile) ----
        float rmA = -1e30f, rmB = -1e30f;
#pragma unroll
        for (int nb = 0; nb < 8; nb++) {
            rmA = fmaxf(rmA, fmaxf(sacc[nb][0], sacc[nb][1]));
            rmB = fmaxf(rmB, fmaxf(sacc[nb][2], sacc[nb][3]));
        }
        rmA = fmaxf(rmA, __shfl_xor_sync(0xffffffffu, rmA, 1));
        rmA = fmaxf(rmA, __shfl_xor_sync(0xffffffffu, rmA, 2));
        rmB = fmaxf(rmB, __shfl_xor_sync(0xffffffffu, rmB, 1));
        rmB = fmaxf(rmB, __shfl_xor_sync(0xffffffffu, rmB, 2));

        float mnA = fmaxf(mA, rmA), mnB = fmaxf(mB, rmB);
        float aA = __expf(mA - mnA), aB = __expf(mB - mnB);
        float rsA = 0.f, rsB = 0.f;
#pragma unroll
        for (int nb = 0; nb < 8; nb++) {
            sacc[nb][0] = __expf(sacc[nb][0] - mnA);
            sacc[nb][1] = __expf(sacc[nb][1] - mnA);
            sacc[nb][2] = __expf(sacc[nb][2] - mnB);
            sacc[nb][3] = __expf(sacc[nb][3] - mnB);
            rsA += sacc[nb][0] + sacc[nb][1];
            rsB += sacc[nb][2] + sacc[nb][3];
        }
        rsA += __shfl_xor_sync(0xffffffffu, rsA, 1);
        rsA += __shfl_xor_sync(0xffffffffu, rsA, 2);
        rsB += __shfl_xor_sync(0xffffffffu, rsB, 1);
        rsB += __shfl_xor_sync(0xffffffffu, rsB, 2);

        lA = lA * aA + rsA;  mA = mnA;
        lB = lB * aB + rsB;  mB = mnB;
#pragma unroll
        for (int nb = 0; nb < 8; nb++) {
            oacc[nb][0] *= aA; oacc[nb][1] *= aA;
            oacc[nb][2] *= aB; oacc[nb][3] *= aB;
        }

        // ---- store P to smem (own rows only) ----
#pragma unroll
        for (int nb = 0; nb < 8; nb++) {
            *(float2*)&Ps[(r0 + g    ) * FPAD + nb * 8 + 2 * t] =
                make_float2(sacc[nb][0], sacc[nb][1]);
            *(float2*)&Ps[(r0 + g + 8) * FPAD + nb * 8 + 2 * t] =
                make_float2(sacc[nb][2], sacc[nb][3]);
        }
        __syncwarp();

        // ---- O += P V ----
#pragma unroll
        for (int kb = 0; kb < 8; kb++) {
            float pa[4];
            pa[0] = Ps[(r0 + g    ) * FPAD + kb * 8 + t    ];
            pa[1] = Ps[(r0 + g + 8) * FPAD + kb * 8 + t    ];
            pa[2] = Ps[(r0 + g    ) * FPAD + kb * 8 + t + 4];
            pa[3] = Ps[(r0 + g + 8) * FPAD + kb * 8 + t + 4];
#pragma unroll
            for (int nb = 0; nb < 8; nb++) {
                float b0 = V[(kb * 8 + t    ) * FPAD + nb * 8 + g];
                float b1 = V[(kb * 8 + t + 4) * FPAD + nb * 8 + g];
                mma8(oacc[nb], pa, b0, b1);
            }
        }
        // (no trailing sync needed: next iteration's top __syncthreads orders
        //  stage reuse; issue() targets the opposite stage.)
    }

    // ---- epilogue: normalize + write to g_ao ----
    const int b = bh >> 4, h = bh & 15;
    float invA = 1.0f / lA, invB = 1.0f / lB;
    int rA = q0 + r0 + g, rB = rA + 8;
#pragma unroll
    for (int nb = 0; nb < 8; nb++) {
        int col = h * HEAD_DIM + nb * 8 + 2 * t;
        *(float2*)&g_ao[((size_t)(b * SEQ + rA)) * HIDDEN + col] =
            make_float2(oacc[nb][0] * invA, oacc[nb][1] * invA);
        *(float2*)&g_ao[((size_t)(b * SEQ + rB)) * HIDDEN + col] =
            make_float2(oacc[nb][2] * invB, oacc[nb][3] * invB);
    }
}

// ---------------------------------------------------------------------------
extern "C" void kernel_launch(void* const* d_in, const int* in_sizes, int n_in,
                              void* d_out, int out_size)
{
    const float* X  = (const float*)d_in[0];
    const float* Wq = (const float*)d_in[1];
    const float* bq = (const float*)d_in[2];
    const float* Wk = (const float*)d_in[3];
    const float* bk = (const float*)d_in[4];
    const float* Wv = (const float*)d_in[5];
    const float* bv = (const float*)d_in[6];
    const float* Wo = (const float*)d_in[7];
    const float* bo = (const float*)d_in[8];
    float* out = (float*)d_out;

    static const int GEMM_SMEM  = 2 * GSTG * 4;               // 73728 B
    static const int FLASH_SMEM = (4 * KVSTG + 128 * FPAD) * 4; // 104448 B
    cudaFuncSetAttribute(qkv_mma,  cudaFuncAttributeMaxDynamicSharedMemorySize, GEMM_SMEM);
    cudaFuncSetAttribute(out_mma,  cudaFuncAttributeMaxDynamicSharedMemorySize, GEMM_SMEM);
    cudaFuncSetAttribute(flash_mma, cudaFuncAttributeMaxDynamicSharedMemorySize, FLASH_SMEM);

    dim3 gq(HIDDEN / 128, MTOT / 128, 3);
    qkv_mma<<<gq, 256, GEMM_SMEM>>>(X, Wq, Wk, Wv);

    rope_bias_kernel<<<(BHN * SEQ * 32) / 256, 256>>>(bq, bk, bv);

    dim3 gf(SEQ / 128, BHN);
    flash_mma<<<gf, 256, FLASH_SMEM>>>();

    dim3 go(HIDDEN / 128, MTOT / 128, 1);
    out_mma<<<go, 256, GEMM_SMEM>>>(Wo, out);
    out_bias_kernel<<<(MTOT * HIDDEN) / 256, 256>>>(bo, out);
}

// round 7
// speedup vs baseline: 2.1067x; 1.0477x over previous
#include <cuda_runtime.h>
#include <mma.h>
#include <math.h>
#include <cstdint>

using namespace nvcuda;

#define BATCH    2
#define SEQ      2048
#define HIDDEN   1024
#define HEADS    16
#define HEAD_DIM 64
#define MTOT     (BATCH*SEQ)      // 4096
#define BHN      (BATCH*HEADS)    // 32
#define HH       (HIDDEN*HIDDEN)

// scratch (allocation-free rule: __device__ globals)
static __device__ float g_xt[MTOT*HIDDEN];        // X pre-rounded to tf32
static __device__ float g_wt[4*HH];               // Wq,Wk,Wv,Wo pre-rounded
static __device__ float g_rt[SEQ*64];             // rope table: [s][0:32)=cos,[32:64)=sin
static __device__ float g_q [BHN*SEQ*HEAD_DIM];   // [B,H,S,D] (tf32 bits)
static __device__ float g_k [BHN*SEQ*HEAD_DIM];
static __device__ float g_v [BHN*SEQ*HEAD_DIM];
static __device__ float g_ao[MTOT*HIDDEN];        // attention out (tf32 bits)

// ---------------------------------------------------------------------------
// helpers
// ---------------------------------------------------------------------------
__device__ __forceinline__ float tf32rn(float x) {
    uint32_t u;
    asm("cvt.rna.tf32.f32 %0, %1;" : "=r"(u) : "f"(x));
    return __uint_as_float(u);
}
__device__ __forceinline__ void cp16(uint32_t dst, const void* src) {
    asm volatile("cp.async.cg.shared.global [%0], [%1], 16;" :: "r"(dst), "l"(src));
}
__device__ __forceinline__ void cp_commit() {
    asm volatile("cp.async.commit_group;" ::: "memory");
}
__device__ __forceinline__ void cp_wait0() {
    asm volatile("cp.async.wait_group 0;" ::: "memory");
}
__device__ __forceinline__ void cp_wait1() {
    asm volatile("cp.async.wait_group 1;" ::: "memory");
}
__device__ __forceinline__ void mma8(float d[4], const float a[4], float b0, float b1)
{
    asm volatile(
        "mma.sync.aligned.m16n8k8.row.col.f32.tf32.tf32.f32 "
        "{%0,%1,%2,%3}, {%4,%5,%6,%7}, {%8,%9}, {%0,%1,%2,%3};"
        : "+f"(d[0]), "+f"(d[1]), "+f"(d[2]), "+f"(d[3])
        : "r"(__float_as_uint(a[0])), "r"(__float_as_uint(a[1])),
          "r"(__float_as_uint(a[2])), "r"(__float_as_uint(a[3])),
          "r"(__float_as_uint(b0)),  "r"(__float_as_uint(b1)));
}

// ---------------------------------------------------------------------------
// setup kernels: tf32 pre-conversion + rope table
// ---------------------------------------------------------------------------
#define XN4 (MTOT*HIDDEN/4)       // 1048576
#define WN4 (HH/4)                // 262144
__global__ void conv_kernel(const float* __restrict__ X,
                            const float* __restrict__ Wq,
                            const float* __restrict__ Wk,
                            const float* __restrict__ Wv,
                            const float* __restrict__ Wo)
{
    int gid = blockIdx.x * blockDim.x + threadIdx.x;
    const float4* s4; float4* d4;
    if (gid < XN4) {
        s4 = (const float4*)X + gid;
        d4 = (float4*)g_xt + gid;
    } else {
        int w = gid - XN4;
        int sel = w >> 18;          // WN4 = 2^18
        int off = w & (WN4 - 1);
        const float* W = (sel == 0) ? Wq : (sel == 1) ? Wk : (sel == 2) ? Wv : Wo;
        s4 = (const float4*)W + off;
        d4 = (float4*)g_wt + (size_t)sel * WN4 + off;
    }
    float4 v = *s4;
    v.x = tf32rn(v.x); v.y = tf32rn(v.y); v.z = tf32rn(v.z); v.w = tf32rn(v.w);
    *d4 = v;
}

__global__ void ropetab_kernel()
{
    int t = blockIdx.x * blockDim.x + threadIdx.x;   // < SEQ*32
    int i = t & 31, s = t >> 5;
    float inv = powf(10000.0f, -(float)i * (1.0f / 32.0f));
    float c, sn;
    sincosf((float)s * inv, &sn, &c);
    g_rt[s * 64 + i]      = c;
    g_rt[s * 64 + 32 + i] = sn;
}

// ---------------------------------------------------------------------------
// wmma tf32 GEMM: C(128x128) = A(128xK)*W(128xK)^T, K=1024, BK=32.
// cp.async 2-stage pipeline, inputs pre-rounded to tf32.
// 8 warps: wm=wid&3 (32 rows), wn=wid>>2 (64 cols).
// ---------------------------------------------------------------------------
#define LDA 36
#define STG (2*128*LDA)           // floats per stage (A+W) = 9216
#define LDC 132

using FragA = wmma::fragment<wmma::matrix_a, 16, 16, 8, wmma::precision::tf32, wmma::row_major>;
using FragB = wmma::fragment<wmma::matrix_b, 16, 16, 8, wmma::precision::tf32, wmma::col_major>;
using FragC = wmma::fragment<wmma::accumulator, 16, 16, 8, float>;

__device__ __forceinline__ void gemm_issue(const float* __restrict__ A,
                                           const float* __restrict__ W,
                                           float* sm, int kb, int s, int tid)
{
    float* As = sm + s * STG;
    float* Ws = As + 128 * LDA;
#pragma unroll
    for (int i = 0; i < 4; i++) {
        int idx = tid + i * 256;
        int r = idx >> 3, c = (idx & 7) * 4;
        cp16((uint32_t)__cvta_generic_to_shared(As + r * LDA + c),
             A + (size_t)r * HIDDEN + kb * 32 + c);
        cp16((uint32_t)__cvta_generic_to_shared(Ws + r * LDA + c),
             W + (size_t)r * HIDDEN + kb * 32 + c);
    }
    cp_commit();
}

__device__ __forceinline__ void mma_mainloop(const float* __restrict__ A,
                                             const float* __restrict__ W,
                                             float* sm, FragC acc[2][4],
                                             int wm, int wn)
{
    const int tid = threadIdx.x;
#pragma unroll
    for (int mi = 0; mi < 2; mi++)
#pragma unroll
        for (int ni = 0; ni < 4; ni++)
            wmma::fill_fragment(acc[mi][ni], 0.0f);

    gemm_issue(A, W, sm, 0, 0, tid);
    gemm_issue(A, W, sm, 1, 1, tid);

    for (int kb = 0; kb < 32; kb++) {
        int s = kb & 1;
        if (kb < 31) cp_wait1(); else cp_wait0();
        __syncthreads();
        float* As = sm + s * STG;
        float* Ws = As + 128 * LDA;
#pragma unroll
        for (int kk = 0; kk < 32; kk += 8) {
            FragA af[2];
            FragB bf[4];
#pragma unroll
            for (int mi = 0; mi < 2; mi++)
                wmma::load_matrix_sync(af[mi], &As[(wm * 32 + mi * 16) * LDA + kk], LDA);
#pragma unroll
            for (int ni = 0; ni < 4; ni++)
                wmma::load_matrix_sync(bf[ni], &Ws[(wn * 64 + ni * 16) * LDA + kk], LDA);
#pragma unroll
            for (int mi = 0; mi < 2; mi++)
#pragma unroll
                for (int ni = 0; ni < 4; ni++)
                    wmma::mma_sync(acc[mi][ni], af[mi], bf[ni], acc[mi][ni]);
        }
        __syncthreads();
        if (kb + 2 < 32) gemm_issue(A, W, sm, kb + 2, s, tid);
    }
}

// store acc tile into smem C buffer (reuses pipeline smem)
__device__ __forceinline__ void stage_C(float* Cs, FragC acc[2][4], int wm, int wn)
{
#pragma unroll
    for (int mi = 0; mi < 2; mi++)
#pragma unroll
        for (int ni = 0; ni < 4; ni++)
            wmma::store_matrix_sync(Cs + (wm * 32 + mi * 16) * LDC + wn * 64 + ni * 16,
                                    acc[mi][ni], LDC, wmma::mem_row_major);
}

// ---------------------------------------------------------------------------
// QKV projection + bias + RoPE fused epilogue. grid (8, 32, 3).
// ---------------------------------------------------------------------------
__global__ void __launch_bounds__(256, 2)
qkv_mma(const float* __restrict__ bq,
        const float* __restrict__ bk,
        const float* __restrict__ bv)
{
    extern __shared__ float gsm[];
    const int tid = threadIdx.x, wid = tid >> 5;
    const int wm = wid & 3, wn = wid >> 2;
    const int m0 = blockIdx.y * 128, n0 = blockIdx.x * 128;
    const int z = blockIdx.z;

    const float* W = g_wt + (size_t)z * HH;
    const float* bias = (z == 0) ? bq : (z == 1) ? bk : bv;
    float* dst = (z == 0) ? g_q : (z == 1) ? g_k : g_v;

    FragC acc[2][4];
    mma_mainloop(g_xt + (size_t)m0 * HIDDEN, W + (size_t)n0 * HIDDEN, gsm, acc, wm, wn);

    // epilogue through smem
    float* Cs = gsm;
    stage_C(Cs, acc, wm, wn);
    __syncthreads();

    const int r = tid >> 1, hh = tid & 1;
    const int m = m0 + r;
    const int b = m >> 11, s = m & (SEQ - 1);
    const int h = (n0 >> 6) + hh;
    const float* crow = Cs + r * LDC + hh * 64;
    const float* brow = bias + n0 + hh * 64;
    float* drow = dst + (((size_t)(b * HEADS + h)) * SEQ + s) * HEAD_DIM;

    if (z < 2) {
        const float* rt = g_rt + s * 64;
        const float scale = (z == 0) ? 0.125f : 1.0f;
#pragma unroll
        for (int d0 = 0; d0 < 32; d0 += 4) {
            float4 x1 = *(const float4*)(crow + d0);
            float4 x2 = *(const float4*)(crow + d0 + 32);
            float4 b1 = *(const float4*)(brow + d0);
            float4 b2 = *(const float4*)(brow + d0 + 32);
            float4 cc = *(const float4*)(rt + d0);
            float4 ss = *(const float4*)(rt + 32 + d0);
            x1.x += b1.x; x1.y += b1.y; x1.z += b1.z; x1.w += b1.w;
            x2.x += b2.x; x2.y += b2.y; x2.z += b2.z; x2.w += b2.w;
            float4 o1, o2;
            o1.x = tf32rn((x1.x * cc.x - x2.x * ss.x) * scale);
            o1.y = tf32rn((x1.y * cc.y - x2.y * ss.y) * scale);
            o1.z = tf32rn((x1.z * cc.z - x2.z * ss.z) * scale);
            o1.w = tf32rn((x1.w * cc.w - x2.w * ss.w) * scale);
            o2.x = tf32rn((x2.x * cc.x + x1.x * ss.x) * scale);
            o2.y = tf32rn((x2.y * cc.y + x1.y * ss.y) * scale);
            o2.z = tf32rn((x2.z * cc.z + x1.z * ss.z) * scale);
            o2.w = tf32rn((x2.w * cc.w + x1.w * ss.w) * scale);
            *(float4*)(drow + d0)      = o1;
            *(float4*)(drow + d0 + 32) = o2;
        }
    } else {
#pragma unroll
        for (int d0 = 0; d0 < 64; d0 += 4) {
            float4 x = *(const float4*)(crow + d0);
            float4 bb = *(const float4*)(brow + d0);
            x.x = tf32rn(x.x + bb.x); x.y = tf32rn(x.y + bb.y);
            x.z = tf32rn(x.z + bb.z); x.w = tf32rn(x.w + bb.w);
            *(float4*)(drow + d0) = x;
        }
    }
}

// ---------------------------------------------------------------------------
// Output projection + bias fused epilogue. grid (8, 32).
// ---------------------------------------------------------------------------
__global__ void __launch_bounds__(256, 2)
out_mma(const float* __restrict__ bo, float* __restrict__ out)
{
    extern __shared__ float gsm[];
    const int tid = threadIdx.x, wid = tid >> 5;
    const int wm = wid & 3, wn = wid >> 2;
    const int m0 = blockIdx.y * 128, n0 = blockIdx.x * 128;

    FragC acc[2][4];
    mma_mainloop(g_ao + (size_t)m0 * HIDDEN,
                 g_wt + 3 * (size_t)HH + (size_t)n0 * HIDDEN, gsm, acc, wm, wn);

    float* Cs = gsm;
    stage_C(Cs, acc, wm, wn);
    __syncthreads();

    const int r = tid >> 1, half = tid & 1;
    const float* crow = Cs + r * LDC + half * 64;
    const float* brow = bo + n0 + half * 64;
    float* orow = out + (size_t)(m0 + r) * HIDDEN + n0 + half * 64;
#pragma unroll
    for (int j = 0; j < 64; j += 4) {
        float4 x = *(const float4*)(crow + j);
        float4 bb = *(const float4*)(brow + j);
        x.x += bb.x; x.y += bb.y; x.z += bb.z; x.w += bb.w;
        *(float4*)(orow + j) = x;
    }
}

// ---------------------------------------------------------------------------
// Flash attention, raw mma.sync m16n8k8 tf32.
// grid (SEQ/128, BHN), 256 threads / 8 warps; warp owns q-rows [wid*16,+16).
// ---------------------------------------------------------------------------
#define FPAD 68
#define KVSTG (64*FPAD)

__global__ void __launch_bounds__(256)
flash_mma()
{
    extern __shared__ float fsm[];
    float* KsB = fsm;                 // 2 stages [64][FPAD]
    float* VsB = fsm + 2 * KVSTG;     // 2 stages [64][FPAD]
    float* Ps  = fsm + 4 * KVSTG;     // [128][FPAD]

    const int tid = threadIdx.x, wid = tid >> 5, lane = tid & 31;
    const int g = lane >> 2, t = lane & 3;
    const int bh = blockIdx.y;
    const int q0 = blockIdx.x * 128;
    const int r0 = wid * 16;

    const float* qb = g_q + ((size_t)bh * SEQ + q0 + r0) * HEAD_DIM;
    float qa[8][4];
#pragma unroll
    for (int kb = 0; kb < 8; kb++) {
        qa[kb][0] = qb[(g    ) * 64 + kb * 8 + t    ];
        qa[kb][1] = qb[(g + 8) * 64 + kb * 8 + t    ];
        qa[kb][2] = qb[(g    ) * 64 + kb * 8 + t + 4];
        qa[kb][3] = qb[(g + 8) * 64 + kb * 8 + t + 4];
    }

    float oacc[8][4];
#pragma unroll
    for (int nb = 0; nb < 8; nb++)
#pragma unroll
        for (int e = 0; e < 4; e++) oacc[nb][e] = 0.f;
    float mA = -1e30f, mB = -1e30f, lA = 0.f, lB = 0.f;

    const float* kbase = g_k + (size_t)bh * SEQ * HEAD_DIM;
    const float* vbase = g_v + (size_t)bh * SEQ * HEAD_DIM;
    auto issue = [&](int kt, int s) {
        float* Kd = KsB + s * KVSTG;
        float* Vd = VsB + s * KVSTG;
        const float* ks = kbase + (size_t)kt * 64 * HEAD_DIM;
        const float* vs = vbase + (size_t)kt * 64 * HEAD_DIM;
#pragma unroll
        for (int i = 0; i < 4; i++) {
            int idx = tid + i * 256;
            int r = idx >> 4, c = (idx & 15) * 4;
            cp16((uint32_t)__cvta_generic_to_shared(Kd + r * FPAD + c), ks + r * 64 + c);
            cp16((uint32_t)__cvta_generic_to_shared(Vd + r * FPAD + c), vs + r * 64 + c);
        }
        cp_commit();
    };

    issue(0, 0);

    for (int kt = 0; kt < SEQ / 64; kt++) {
        int s = kt & 1;
        cp_wait0();
        __syncthreads();
        if (kt + 1 < SEQ / 64) issue(kt + 1, s ^ 1);

        const float* K = KsB + s * KVSTG;
        const float* V = VsB + s * KVSTG;

        float sacc[8][4];
#pragma unroll
        for (int nb = 0; nb < 8; nb++)
#pragma unroll
            for (int e = 0; e < 4; e++) sacc[nb][e] = 0.f;

#pragma unroll
        for (int kb = 0; kb < 8; kb++) {
#pragma unroll
            for (int nb = 0; nb < 8; nb++) {
                float b0 = K[(nb * 8 + g) * FPAD + kb * 8 + t    ];
                float b1 = K[(nb * 8 + g) * FPAD + kb * 8 + t + 4];
                mma8(sacc[nb], qa[kb], b0, b1);
            }
        }

        float rmA = -1e30f, rmB = -1e30f;
#pragma unroll
        for (int nb = 0; nb < 8; nb++) {
            rmA = fmaxf(rmA, fmaxf(sacc[nb][0], sacc[nb][1]));
            rmB = fmaxf(rmB, fmaxf(sacc[nb][2], sacc[nb][3]));
        }
        rmA = fmaxf(rmA, __shfl_xor_sync(0xffffffffu, rmA, 1));
        rmA = fmaxf(rmA, __shfl_xor_sync(0xffffffffu, rmA, 2));
        rmB = fmaxf(rmB, __shfl_xor_sync(0xffffffffu, rmB, 1));
        rmB = fmaxf(rmB, __shfl_xor_sync(0xffffffffu, rmB, 2));

        float mnA = fmaxf(mA, rmA), mnB = fmaxf(mB, rmB);
        float aA = __expf(mA - mnA), aB = __expf(mB - mnB);
        float rsA = 0.f, rsB = 0.f;
#pragma unroll
        for (int nb = 0; nb < 8; nb++) {
            sacc[nb][0] = __expf(sacc[nb][0] - mnA);
            sacc[nb][1] = __expf(sacc[nb][1] - mnA);
            sacc[nb][2] = __expf(sacc[nb][2] - mnB);
            sacc[nb][3] = __expf(sacc[nb][3] - mnB);
            rsA += sacc[nb][0] + sacc[nb][1];
            rsB += sacc[nb][2] + sacc[nb][3];
        }
        rsA += __shfl_xor_sync(0xffffffffu, rsA, 1);
        rsA += __shfl_xor_sync(0xffffffffu, rsA, 2);
        rsB += __shfl_xor_sync(0xffffffffu, rsB, 1);
        rsB += __shfl_xor_sync(0xffffffffu, rsB, 2);

        lA = lA * aA + rsA;  mA = mnA;
        lB = lB * aB + rsB;  mB = mnB;
#pragma unroll
        for (int nb = 0; nb < 8; nb++) {
            oacc[nb][0] *= aA; oacc[nb][1] *= aA;
            oacc[nb][2] *= aB; oacc[nb][3] *= aB;
        }

#pragma unroll
        for (int nb = 0; nb < 8; nb++) {
            *(float2*)&Ps[(r0 + g    ) * FPAD + nb * 8 + 2 * t] =
                make_float2(tf32rn(sacc[nb][0]), tf32rn(sacc[nb][1]));
            *(float2*)&Ps[(r0 + g + 8) * FPAD + nb * 8 + 2 * t] =
                make_float2(tf32rn(sacc[nb][2]), tf32rn(sacc[nb][3]));
        }
        __syncwarp();

#pragma unroll
        for (int kb = 0; kb < 8; kb++) {
            float pa[4];
            pa[0] = Ps[(r0 + g    ) * FPAD + kb * 8 + t    ];
            pa[1] = Ps[(r0 + g + 8) * FPAD + kb * 8 + t    ];
            pa[2] = Ps[(r0 + g    ) * FPAD + kb * 8 + t + 4];
            pa[3] = Ps[(r0 + g + 8) * FPAD + kb * 8 + t + 4];
#pragma unroll
            for (int nb = 0; nb < 8; nb++) {
                float b0 = V[(kb * 8 + t    ) * FPAD + nb * 8 + g];
                float b1 = V[(kb * 8 + t + 4) * FPAD + nb * 8 + g];
                mma8(oacc[nb], pa, b0, b1);
            }
        }
    }

    const int b = bh >> 4, h = bh & 15;
    float invA = 1.0f / lA, invB = 1.0f / lB;
    int rA = q0 + r0 + g, rB = rA + 8;
#pragma unroll
    for (int nb = 0; nb < 8; nb++) {
        int col = h * HEAD_DIM + nb * 8 + 2 * t;
        *(float2*)&g_ao[((size_t)(b * SEQ + rA)) * HIDDEN + col] =
            make_float2(tf32rn(oacc[nb][0] * invA), tf32rn(oacc[nb][1] * invA));
        *(float2*)&g_ao[((size_t)(b * SEQ + rB)) * HIDDEN + col] =
            make_float2(tf32rn(oacc[nb][2] * invB), tf32rn(oacc[nb][3] * invB));
    }
}

// ---------------------------------------------------------------------------
extern "C" void kernel_launch(void* const* d_in, const int* in_sizes, int n_in,
                              void* d_out, int out_size)
{
    const float* X  = (const float*)d_in[0];
    const float* Wq = (const float*)d_in[1];
    const float* bq = (const float*)d_in[2];
    const float* Wk = (const float*)d_in[3];
    const float* bk = (const float*)d_in[4];
    const float* Wv = (const float*)d_in[5];
    const float* bv = (const float*)d_in[6];
    const float* Wo = (const float*)d_in[7];
    const float* bo = (const float*)d_in[8];
    float* out = (float*)d_out;

    static const int GEMM_SMEM  = 2 * STG * 4;                  // 73728 B
    static const int FLASH_SMEM = (4 * KVSTG + 128 * FPAD) * 4; // 104448 B
    cudaFuncSetAttribute(qkv_mma,  cudaFuncAttributeMaxDynamicSharedMemorySize, GEMM_SMEM);
    cudaFuncSetAttribute(out_mma,  cudaFuncAttributeMaxDynamicSharedMemorySize, GEMM_SMEM);
    cudaFuncSetAttribute(flash_mma, cudaFuncAttributeMaxDynamicSharedMemorySize, FLASH_SMEM);

    ropetab_kernel<<<(SEQ * 32) / 256, 256>>>();
    conv_kernel<<<(XN4 + 4 * WN4) / 256, 256>>>(X, Wq, Wk, Wv, Wo);

    dim3 gq(HIDDEN / 128, MTOT / 128, 3);
    qkv_mma<<<gq, 256, GEMM_SMEM>>>(bq, bk, bv);

    dim3 gf(SEQ / 128, BHN);
    flash_mma<<<gf, 256, FLASH_SMEM>>>();

    dim3 go(HIDDEN / 128, MTOT / 128, 1);
    out_mma<<<go, 256, GEMM_SMEM>>>(bo, out);
}

// round 9
// speedup vs baseline: 5.8310x; 2.7678x over previous
#include <cuda_runtime.h>
#include <cuda_fp16.h>
#include <mma.h>
#include <math.h>
#include <cstdint>

using namespace nvcuda;

#define BATCH    2
#define SEQ      2048
#define HIDDEN   1024
#define HEADS    16
#define HEAD_DIM 64
#define MTOT     (BATCH*SEQ)      // 4096
#define BHN      (BATCH*HEADS)    // 32
#define HH       (HIDDEN*HIDDEN)

// scratch (allocation-free rule: __device__ globals)
static __device__ __half g_xh[MTOT*HIDDEN];        // X in fp16
static __device__ __half g_wh[4*HH];               // Wq,Wk,Wv,Wo in fp16
static __device__ float  g_rt[SEQ*64];             // rope: [s][0:32)=cos,[32:64)=sin
static __device__ __half g_q [BHN*SEQ*HEAD_DIM];   // [B,H,S,D] fp16 (q pre-scaled)
static __device__ __half g_k [BHN*SEQ*HEAD_DIM];
static __device__ __half g_v [BHN*SEQ*HEAD_DIM];
static __device__ __half g_ao[MTOT*HIDDEN];        // attention out fp16

// ---------------------------------------------------------------------------
// helpers
// ---------------------------------------------------------------------------
__device__ __forceinline__ void cp16(uint32_t dst, const void* src) {
    asm volatile("cp.async.cg.shared.global [%0], [%1], 16;" :: "r"(dst), "l"(src));
}
__device__ __forceinline__ void cp_commit() {
    asm volatile("cp.async.commit_group;" ::: "memory");
}
__device__ __forceinline__ void cp_wait0() {
    asm volatile("cp.async.wait_group 0;" ::: "memory");
}
__device__ __forceinline__ void cp_wait1() {
    asm volatile("cp.async.wait_group 1;" ::: "memory");
}
__device__ __forceinline__ uint32_t sm_u32(const void* p) {
    return (uint32_t)__cvta_generic_to_shared(p);
}
__device__ __forceinline__ uint32_t pack_h2(float lo, float hi) {
    __half2 h = __floats2half2_rn(lo, hi);
    return *reinterpret_cast<uint32_t*>(&h);       // correct 32-bit pack
}
__device__ __forceinline__ void mma16(float d[4], const uint32_t a[4],
                                      uint32_t b0, uint32_t b1)
{
    asm volatile(
        "mma.sync.aligned.m16n8k16.row.col.f32.f16.f16.f32 "
        "{%0,%1,%2,%3}, {%4,%5,%6,%7}, {%8,%9}, {%0,%1,%2,%3};"
        : "+f"(d[0]), "+f"(d[1]), "+f"(d[2]), "+f"(d[3])
        : "r"(a[0]), "r"(a[1]), "r"(a[2]), "r"(a[3]), "r"(b0), "r"(b1));
}
__device__ __forceinline__ void ldsm_x2(uint32_t& r0, uint32_t& r1, uint32_t addr) {
    asm volatile("ldmatrix.sync.aligned.m8n8.x2.shared.b16 {%0,%1}, [%2];"
                 : "=r"(r0), "=r"(r1) : "r"(addr));
}
__device__ __forceinline__ void ldsm_x2_t(uint32_t& r0, uint32_t& r1, uint32_t addr) {
    asm volatile("ldmatrix.sync.aligned.m8n8.x2.trans.shared.b16 {%0,%1}, [%2];"
                 : "=r"(r0), "=r"(r1) : "r"(addr));
}

// ---------------------------------------------------------------------------
// setup: fp16 conversion + rope table
// ---------------------------------------------------------------------------
#define XN4 (MTOT*HIDDEN/4)       // 1048576
#define WN4 (HH/4)                // 262144
__global__ void conv_kernel(const float* __restrict__ X,
                            const float* __restrict__ Wq,
                            const float* __restrict__ Wk,
                            const float* __restrict__ Wv,
                            const float* __restrict__ Wo)
{
    int gid = blockIdx.x * blockDim.x + threadIdx.x;
    const float4* s4; __half2* d2;
    if (gid < XN4) {
        s4 = (const float4*)X + gid;
        d2 = (__half2*)g_xh + (size_t)gid * 2;
    } else {
        int w = gid - XN4;
        int sel = w >> 18;          // WN4 = 2^18
        int off = w & (WN4 - 1);
        const float* W = (sel == 0) ? Wq : (sel == 1) ? Wk : (sel == 2) ? Wv : Wo;
        s4 = (const float4*)W + off;
        d2 = (__half2*)g_wh + ((size_t)sel * WN4 + off) * 2;
    }
    float4 v = *s4;
    d2[0] = __floats2half2_rn(v.x, v.y);
    d2[1] = __floats2half2_rn(v.z, v.w);
}

__global__ void ropetab_kernel()
{
    int t = blockIdx.x * blockDim.x + threadIdx.x;   // < SEQ*32
    int i = t & 31, s = t >> 5;
    float inv = powf(10000.0f, -(float)i * (1.0f / 32.0f));
    float c, sn;
    sincosf((float)s * inv, &sn, &c);
    g_rt[s * 64 + i]      = c;
    g_rt[s * 64 + 32 + i] = sn;
}

// ---------------------------------------------------------------------------
// fp16 wmma GEMM: C(128x128) = A(128xK)*W(128xK)^T, K=1024, BK=32 halves.
// cp.async 2-stage. 8 warps: wm=wid&3 (32 rows), wn=wid>>2 (64 cols).
// ---------------------------------------------------------------------------
#define LDAH 40                   // halves; 80B row stride
#define STGH (2*128*LDAH)         // halves per stage (A+W) = 10240
#define LDC  132

using HFragA = wmma::fragment<wmma::matrix_a, 16, 16, 16, __half, wmma::row_major>;
using HFragB = wmma::fragment<wmma::matrix_b, 16, 16, 16, __half, wmma::col_major>;
using HFragC = wmma::fragment<wmma::accumulator, 16, 16, 16, float>;

__device__ __forceinline__ void hgemm_issue(const __half* __restrict__ A,
                                            const __half* __restrict__ W,
                                            __half* sm, int kb, int s, int tid)
{
    __half* As = sm + s * STGH;
    __half* Ws = As + 128 * LDAH;
#pragma unroll
    for (int i = 0; i < 2; i++) {
        int idx = tid + i * 256;            // 0..511
        int r = idx >> 2, c = (idx & 3) * 8;
        cp16(sm_u32(As + r * LDAH + c), A + (size_t)r * HIDDEN + kb * 32 + c);
        cp16(sm_u32(Ws + r * LDAH + c), W + (size_t)r * HIDDEN + kb * 32 + c);
    }
    cp_commit();
}

__device__ __forceinline__ void hgemm_mainloop(const __half* __restrict__ A,
                                               const __half* __restrict__ W,
                                               __half* sm, HFragC acc[2][4],
                                               int wm, int wn)
{
    const int tid = threadIdx.x;
#pragma unroll
    for (int mi = 0; mi < 2; mi++)
#pragma unroll
        for (int ni = 0; ni < 4; ni++)
            wmma::fill_fragment(acc[mi][ni], 0.0f);

    hgemm_issue(A, W, sm, 0, 0, tid);
    hgemm_issue(A, W, sm, 1, 1, tid);

    for (int kb = 0; kb < 32; kb++) {
        int s = kb & 1;
        if (kb < 31) cp_wait1(); else cp_wait0();
        __syncthreads();
        __half* As = sm + s * STGH;
        __half* Ws = As + 128 * LDAH;
#pragma unroll
        for (int kk = 0; kk < 32; kk += 16) {
            HFragA af[2];
            HFragB bf[4];
#pragma unroll
            for (int mi = 0; mi < 2; mi++)
                wmma::load_matrix_sync(af[mi], &As[(wm * 32 + mi * 16) * LDAH + kk], LDAH);
#pragma unroll
            for (int ni = 0; ni < 4; ni++)
                wmma::load_matrix_sync(bf[ni], &Ws[(wn * 64 + ni * 16) * LDAH + kk], LDAH);
#pragma unroll
            for (int mi = 0; mi < 2; mi++)
#pragma unroll
                for (int ni = 0; ni < 4; ni++)
                    wmma::mma_sync(acc[mi][ni], af[mi], bf[ni], acc[mi][ni]);
        }
        __syncthreads();
        if (kb + 2 < 32) hgemm_issue(A, W, sm, kb + 2, s, tid);
    }
}

__device__ __forceinline__ void stage_C(float* Cs, HFragC acc[2][4], int wm, int wn)
{
#pragma unroll
    for (int mi = 0; mi < 2; mi++)
#pragma unroll
        for (int ni = 0; ni < 4; ni++)
            wmma::store_matrix_sync(Cs + (wm * 32 + mi * 16) * LDC + wn * 64 + ni * 16,
                                    acc[mi][ni], LDC, wmma::mem_row_major);
}

// ---------------------------------------------------------------------------
// QKV projection + bias + RoPE fused epilogue -> fp16. grid (8, 32, 3).
// ---------------------------------------------------------------------------
__global__ void __launch_bounds__(256, 2)
qkv_mma(const float* __restrict__ bq,
        const float* __restrict__ bk,
        const float* __restrict__ bv)
{
    extern __shared__ char smraw[];
    const int tid = threadIdx.x, wid = tid >> 5;
    const int wm = wid & 3, wn = wid >> 2;
    const int m0 = blockIdx.y * 128, n0 = blockIdx.x * 128;
    const int z = blockIdx.z;

    const __half* W = g_wh + (size_t)z * HH;
    const float* bias = (z == 0) ? bq : (z == 1) ? bk : bv;
    __half* dst = (z == 0) ? g_q : (z == 1) ? g_k : g_v;

    HFragC acc[2][4];
    hgemm_mainloop(g_xh + (size_t)m0 * HIDDEN, W + (size_t)n0 * HIDDEN,
                   (__half*)smraw, acc, wm, wn);

    float* Cs = (float*)smraw;
    stage_C(Cs, acc, wm, wn);
    __syncthreads();

    const int r = tid >> 1, hh = tid & 1;
    const int m = m0 + r;
    const int b = m >> 11, s = m & (SEQ - 1);
    const int h = (n0 >> 6) + hh;
    const float* crow = Cs + r * LDC + hh * 64;
    const float* brow = bias + n0 + hh * 64;
    __half* drow = dst + (((size_t)(b * HEADS + h)) * SEQ + s) * HEAD_DIM;

    if (z < 2) {
        const float* rt = g_rt + s * 64;
        const float scale = (z == 0) ? 0.125f : 1.0f;
#pragma unroll
        for (int d0 = 0; d0 < 32; d0 += 4) {
            float4 x1 = *(const float4*)(crow + d0);
            float4 x2 = *(const float4*)(crow + d0 + 32);
            float4 b1 = *(const float4*)(brow + d0);
            float4 b2 = *(const float4*)(brow + d0 + 32);
            float4 cc = *(const float4*)(rt + d0);
            float4 ss = *(const float4*)(rt + 32 + d0);
            x1.x += b1.x; x1.y += b1.y; x1.z += b1.z; x1.w += b1.w;
            x2.x += b2.x; x2.y += b2.y; x2.z += b2.z; x2.w += b2.w;
            float o1x = (x1.x * cc.x - x2.x * ss.x) * scale;
            float o1y = (x1.y * cc.y - x2.y * ss.y) * scale;
            float o1z = (x1.z * cc.z - x2.z * ss.z) * scale;
            float o1w = (x1.w * cc.w - x2.w * ss.w) * scale;
            float o2x = (x2.x * cc.x + x1.x * ss.x) * scale;
            float o2y = (x2.y * cc.y + x1.y * ss.y) * scale;
            float o2z = (x2.z * cc.z + x1.z * ss.z) * scale;
            float o2w = (x2.w * cc.w + x1.w * ss.w) * scale;
            *(__half2*)(drow + d0)      = __floats2half2_rn(o1x, o1y);
            *(__half2*)(drow + d0 + 2)  = __floats2half2_rn(o1z, o1w);
            *(__half2*)(drow + d0 + 32) = __floats2half2_rn(o2x, o2y);
            *(__half2*)(drow + d0 + 34) = __floats2half2_rn(o2z, o2w);
        }
    } else {
#pragma unroll
        for (int d0 = 0; d0 < 64; d0 += 4) {
            float4 x = *(const float4*)(crow + d0);
            float4 bb = *(const float4*)(brow + d0);
            *(__half2*)(drow + d0)     = __floats2half2_rn(x.x + bb.x, x.y + bb.y);
            *(__half2*)(drow + d0 + 2) = __floats2half2_rn(x.z + bb.z, x.w + bb.w);
        }
    }
}

// ---------------------------------------------------------------------------
// Output projection + bias. grid (8, 32).
// ---------------------------------------------------------------------------
__global__ void __launch_bounds__(256, 2)
out_mma(const float* __restrict__ bo, float* __restrict__ out)
{
    extern __shared__ char smraw[];
    const int tid = threadIdx.x, wid = tid >> 5;
    const int wm = wid & 3, wn = wid >> 2;
    const int m0 = blockIdx.y * 128, n0 = blockIdx.x * 128;

    HFragC acc[2][4];
    hgemm_mainloop(g_ao + (size_t)m0 * HIDDEN,
                   g_wh + 3 * (size_t)HH + (size_t)n0 * HIDDEN,
                   (__half*)smraw, acc, wm, wn);

    float* Cs = (float*)smraw;
    stage_C(Cs, acc, wm, wn);
    __syncthreads();

    const int r = tid >> 1, half = tid & 1;
    const float* crow = Cs + r * LDC + half * 64;
    const float* brow = bo + n0 + half * 64;
    float* orow = out + (size_t)(m0 + r) * HIDDEN + n0 + half * 64;
#pragma unroll
    for (int j = 0; j < 64; j += 4) {
        float4 x = *(const float4*)(crow + j);
        float4 bb = *(const float4*)(brow + j);
        x.x += bb.x; x.y += bb.y; x.z += bb.z; x.w += bb.w;
        *(float4*)(orow + j) = x;
    }
}

// ---------------------------------------------------------------------------
// Flash attention fp16: mma.m16n8k16, ldmatrix K/V, register-resident P.
// grid (SEQ/128, BHN), 256 threads / 8 warps; warp owns q-rows [wid*16,+16).
// ---------------------------------------------------------------------------
#define FPH 72                    // halves; 144B row stride (16B-aligned rows)
#define KVH (64*FPH)              // halves per K (or V) tile

__global__ void __launch_bounds__(256, 2)
flash_mma()
{
    extern __shared__ char smraw[];
    __half* KsB = (__half*)smraw;            // 2 stages [64][FPH]
    __half* VsB = KsB + 2 * KVH;             // 2 stages [64][FPH]

    const int tid = threadIdx.x, wid = tid >> 5, lane = tid & 31;
    const int g = lane >> 2, t = lane & 3;
    const int lk = lane & 15;
    const int bh = blockIdx.y;
    const int q0 = blockIdx.x * 128;
    const int r0 = wid * 16;

    // ldsm address offsets (halves)
    const int koff = (lk & 7) * FPH + (lk >> 3) * 8;          // K: 8 keys x (d, d+8)
    const int voff = ((lk >> 3) * 8 + (lk & 7)) * FPH;        // V: keys 0-15 rows

    // ---- Q A-fragments from global (fp16, pre-scaled) ----
    const __half* q0p = g_q + ((size_t)(bh * SEQ + q0 + r0 + g)) * HEAD_DIM;
    const __half* q8p = q0p + 8 * HEAD_DIM;
    uint32_t qa[4][4];
#pragma unroll
    for (int kb = 0; kb < 4; kb++) {
        qa[kb][0] = *(const uint32_t*)(q0p + kb * 16 + 2 * t);
        qa[kb][1] = *(const uint32_t*)(q8p + kb * 16 + 2 * t);
        qa[kb][2] = *(const uint32_t*)(q0p + kb * 16 + 8 + 2 * t);
        qa[kb][3] = *(const uint32_t*)(q8p + kb * 16 + 8 + 2 * t);
    }

    float oacc[8][4];
#pragma unroll
    for (int nb = 0; nb < 8; nb++)
#pragma unroll
        for (int e = 0; e < 4; e++) oacc[nb][e] = 0.f;
    float mA = -1e30f, mB = -1e30f, lA = 0.f, lB = 0.f;

    const __half* kbase = g_k + (size_t)bh * SEQ * HEAD_DIM;
    const __half* vbase = g_v + (size_t)bh * SEQ * HEAD_DIM;
    auto issue = [&](int kt, int s) {
        __half* Kd = KsB + s * KVH;
        __half* Vd = VsB + s * KVH;
        const __half* ks = kbase + (size_t)kt * 64 * HEAD_DIM;
        const __half* vs = vbase + (size_t)kt * 64 * HEAD_DIM;
#pragma unroll
        for (int i = 0; i < 2; i++) {
            int idx = tid + i * 256;            // 0..511
            int r = idx >> 3, c = (idx & 7) * 8;
            cp16(sm_u32(Kd + r * FPH + c), ks + r * 64 + c);
            cp16(sm_u32(Vd + r * FPH + c), vs + r * 64 + c);
        }
        cp_commit();
    };

    issue(0, 0);

    for (int kt = 0; kt < SEQ / 64; kt++) {
        int s = kt & 1;
        cp_wait0();
        __syncthreads();
        if (kt + 1 < SEQ / 64) issue(kt + 1, s ^ 1);

        const uint32_t Ku = sm_u32(KsB + s * KVH);
        const uint32_t Vu = sm_u32(VsB + s * KVH);

        // ---- S = Q K^T ----
        float sacc[8][4];
#pragma unroll
        for (int nb = 0; nb < 8; nb++)
#pragma unroll
            for (int e = 0; e < 4; e++) sacc[nb][e] = 0.f;

#pragma unroll
        for (int nb = 0; nb < 8; nb++) {
#pragma unroll
            for (int kb = 0; kb < 4; kb++) {
                uint32_t b0, b1;
                ldsm_x2(b0, b1, Ku + (uint32_t)(nb * 8 * FPH + kb * 16 + koff) * 2);
                mma16(sacc[nb], qa[kb], b0, b1);
            }
        }

        // ---- online softmax (rows g, g+8 of warp tile) ----
        float rmA = -1e30f, rmB = -1e30f;
#pragma unroll
        for (int nb = 0; nb < 8; nb++) {
            rmA = fmaxf(rmA, fmaxf(sacc[nb][0], sacc[nb][1]));
            rmB = fmaxf(rmB, fmaxf(sacc[nb][2], sacc[nb][3]));
        }
        rmA = fmaxf(rmA, __shfl_xor_sync(0xffffffffu, rmA, 1));
        rmA = fmaxf(rmA, __shfl_xor_sync(0xffffffffu, rmA, 2));
        rmB = fmaxf(rmB, __shfl_xor_sync(0xffffffffu, rmB, 1));
        rmB = fmaxf(rmB, __shfl_xor_sync(0xffffffffu, rmB, 2));

        float mnA = fmaxf(mA, rmA), mnB = fmaxf(mB, rmB);
        float aA = __expf(mA - mnA), aB = __expf(mB - mnB);
        float rsA = 0.f, rsB = 0.f;
#pragma unroll
        for (int nb = 0; nb < 8; nb++) {
            sacc[nb][0] = __expf(sacc[nb][0] - mnA);
            sacc[nb][1] = __expf(sacc[nb][1] - mnA);
            sacc[nb][2] = __expf(sacc[nb][2] - mnB);
            sacc[nb][3] = __expf(sacc[nb][3] - mnB);
            rsA += sacc[nb][0] + sacc[nb][1];
            rsB += sacc[nb][2] + sacc[nb][3];
        }
        rsA += __shfl_xor_sync(0xffffffffu, rsA, 1);
        rsA += __shfl_xor_sync(0xffffffffu, rsA, 2);
        rsB += __shfl_xor_sync(0xffffffffu, rsB, 1);
        rsB += __shfl_xor_sync(0xffffffffu, rsB, 2);

        lA = lA * aA + rsA;  mA = mnA;
        lB = lB * aB + rsB;  mB = mnB;
#pragma unroll
        for (int nb = 0; nb < 8; nb++) {
            oacc[nb][0] *= aA; oacc[nb][1] *= aA;
            oacc[nb][2] *= aB; oacc[nb][3] *= aB;
        }

        // ---- O += P V : P packs straight from sacc into A-fragments ----
#pragma unroll
        for (int kb2 = 0; kb2 < 4; kb2++) {
            uint32_t pa[4];
            pa[0] = pack_h2(sacc[2*kb2][0],   sacc[2*kb2][1]);
            pa[1] = pack_h2(sacc[2*kb2][2],   sacc[2*kb2][3]);
            pa[2] = pack_h2(sacc[2*kb2+1][0], sacc[2*kb2+1][1]);
            pa[3] = pack_h2(sacc[2*kb2+1][2], sacc[2*kb2+1][3]);
#pragma unroll
            for (int nb = 0; nb < 8; nb++) {
                uint32_t b0, b1;
                ldsm_x2_t(b0, b1, Vu + (uint32_t)(kb2 * 16 * FPH + voff + nb * 8) * 2);
                mma16(oacc[nb], pa, b0, b1);
            }
        }
    }

    // ---- epilogue: normalize + write fp16 to g_ao ----
    const int b = bh >> 4, h = bh & 15;
    float invA = 1.0f / lA, invB = 1.0f / lB;
    int rA = q0 + r0 + g, rB = rA + 8;
#pragma unroll
    for (int nb = 0; nb < 8; nb++) {
        int col = h * HEAD_DIM + nb * 8 + 2 * t;
        *(__half2*)&g_ao[((size_t)(b * SEQ + rA)) * HIDDEN + col] =
            __floats2half2_rn(oacc[nb][0] * invA, oacc[nb][1] * invA);
        *(__half2*)&g_ao[((size_t)(b * SEQ + rB)) * HIDDEN + col] =
            __floats2half2_rn(oacc[nb][2] * invB, oacc[nb][3] * invB);
    }
}

// ---------------------------------------------------------------------------
extern "C" void kernel_launch(void* const* d_in, const int* in_sizes, int n_in,
                              void* d_out, int out_size)
{
    const float* X  = (const float*)d_in[0];
    const float* Wq = (const float*)d_in[1];
    const float* bq = (const float*)d_in[2];
    const float* Wk = (const float*)d_in[3];
    const float* bk = (const float*)d_in[4];
    const float* Wv = (const float*)d_in[5];
    const float* bv = (const float*)d_in[6];
    const float* Wo = (const float*)d_in[7];
    const float* bo = (const float*)d_in[8];
    float* out = (float*)d_out;

    static const int GEMM_SMEM  = 128 * LDC * 4;      // 67584 (covers pipeline 40960)
    static const int FLASH_SMEM = 4 * KVH * 2;        // 36864
    cudaFuncSetAttribute(qkv_mma,  cudaFuncAttributeMaxDynamicSharedMemorySize, GEMM_SMEM);
    cudaFuncSetAttribute(out_mma,  cudaFuncAttributeMaxDynamicSharedMemorySize, GEMM_SMEM);
    cudaFuncSetAttribute(flash_mma, cudaFuncAttributeMaxDynamicSharedMemorySize, FLASH_SMEM);

    ropetab_kernel<<<(SEQ * 32) / 256, 256>>>();
    conv_kernel<<<(XN4 + 4 * WN4) / 256, 256>>>(X, Wq, Wk, Wv, Wo);

    dim3 gq(HIDDEN / 128, MTOT / 128, 3);
    qkv_mma<<<gq, 256, GEMM_SMEM>>>(bq, bk, bv);

    dim3 gf(SEQ / 128, BHN);
    flash_mma<<<gf, 256, FLASH_SMEM>>>();

    dim3 go(HIDDEN / 128, MTOT / 128, 1);
    out_mma<<<go, 256, GEMM_SMEM>>>(bo, out);
}

// round 10
// speedup vs baseline: 5.9486x; 1.0202x over previous
#include <cuda_runtime.h>
#include <cuda_fp16.h>
#include <mma.h>
#include <math.h>
#include <cstdint>

using namespace nvcuda;

#define BATCH    2
#define SEQ      2048
#define HIDDEN   1024
#define HEADS    16
#define HEAD_DIM 64
#define MTOT     (BATCH*SEQ)      // 4096
#define BHN      (BATCH*HEADS)    // 32
#define HH       (HIDDEN*HIDDEN)

// scratch (allocation-free rule: __device__ globals)
static __device__ __half g_xh[MTOT*HIDDEN];        // X in fp16
static __device__ __half g_wh[4*HH];               // Wq,Wk,Wv,Wo in fp16
static __device__ float  g_rt[SEQ*64];             // rope: [s][0:32)=cos,[32:64)=sin
static __device__ __half g_q [BHN*SEQ*HEAD_DIM];   // [B,H,S,D] fp16 (q pre-scaled)
static __device__ __half g_k [BHN*SEQ*HEAD_DIM];
static __device__ __half g_v [BHN*SEQ*HEAD_DIM];
static __device__ __half g_ao[MTOT*HIDDEN];        // attention out fp16

// ---------------------------------------------------------------------------
// helpers
// ---------------------------------------------------------------------------
__device__ __forceinline__ void cp16(uint32_t dst, const void* src) {
    asm volatile("cp.async.cg.shared.global [%0], [%1], 16;" :: "r"(dst), "l"(src));
}
__device__ __forceinline__ void cp_commit() {
    asm volatile("cp.async.commit_group;" ::: "memory");
}
__device__ __forceinline__ void cp_wait0() {
    asm volatile("cp.async.wait_group 0;" ::: "memory");
}
__device__ __forceinline__ void cp_wait1() {
    asm volatile("cp.async.wait_group 1;" ::: "memory");
}
__device__ __forceinline__ void cp_wait2() {
    asm volatile("cp.async.wait_group 2;" ::: "memory");
}
__device__ __forceinline__ uint32_t sm_u32(const void* p) {
    return (uint32_t)__cvta_generic_to_shared(p);
}
__device__ __forceinline__ uint32_t pack_h2(float lo, float hi) {
    __half2 h = __floats2half2_rn(lo, hi);
    return *reinterpret_cast<uint32_t*>(&h);
}
__device__ __forceinline__ void mma16(float d[4], const uint32_t a[4],
                                      uint32_t b0, uint32_t b1)
{
    asm volatile(
        "mma.sync.aligned.m16n8k16.row.col.f32.f16.f16.f32 "
        "{%0,%1,%2,%3}, {%4,%5,%6,%7}, {%8,%9}, {%0,%1,%2,%3};"
        : "+f"(d[0]), "+f"(d[1]), "+f"(d[2]), "+f"(d[3])
        : "r"(a[0]), "r"(a[1]), "r"(a[2]), "r"(a[3]), "r"(b0), "r"(b1));
}
__device__ __forceinline__ void ldsm_x4(uint32_t& r0, uint32_t& r1,
                                        uint32_t& r2, uint32_t& r3, uint32_t addr) {
    asm volatile("ldmatrix.sync.aligned.m8n8.x4.shared.b16 {%0,%1,%2,%3}, [%4];"
                 : "=r"(r0), "=r"(r1), "=r"(r2), "=r"(r3) : "r"(addr));
}
__device__ __forceinline__ void ldsm_x4_t(uint32_t& r0, uint32_t& r1,
                                          uint32_t& r2, uint32_t& r3, uint32_t addr) {
    asm volatile("ldmatrix.sync.aligned.m8n8.x4.trans.shared.b16 {%0,%1,%2,%3}, [%4];"
                 : "=r"(r0), "=r"(r1), "=r"(r2), "=r"(r3) : "r"(addr));
}

// ---------------------------------------------------------------------------
// setup: fp16 conversion + rope table
// ---------------------------------------------------------------------------
#define XN4 (MTOT*HIDDEN/4)       // 1048576
#define WN4 (HH/4)                // 262144
__global__ void conv_kernel(const float* __restrict__ X,
                            const float* __restrict__ Wq,
                            const float* __restrict__ Wk,
                            const float* __restrict__ Wv,
                            const float* __restrict__ Wo)
{
    int gid = blockIdx.x * blockDim.x + threadIdx.x;
    const float4* s4; __half2* d2;
    if (gid < XN4) {
        s4 = (const float4*)X + gid;
        d2 = (__half2*)g_xh + (size_t)gid * 2;
    } else {
        int w = gid - XN4;
        int sel = w >> 18;          // WN4 = 2^18
        int off = w & (WN4 - 1);
        const float* W = (sel == 0) ? Wq : (sel == 1) ? Wk : (sel == 2) ? Wv : Wo;
        s4 = (const float4*)W + off;
        d2 = (__half2*)g_wh + ((size_t)sel * WN4 + off) * 2;
    }
    float4 v = *s4;
    d2[0] = __floats2half2_rn(v.x, v.y);
    d2[1] = __floats2half2_rn(v.z, v.w);
}

__global__ void ropetab_kernel()
{
    int t = blockIdx.x * blockDim.x + threadIdx.x;   // < SEQ*32
    int i = t & 31, s = t >> 5;
    float inv = powf(10000.0f, -(float)i * (1.0f / 32.0f));
    float c, sn;
    sincosf((float)s * inv, &sn, &c);
    g_rt[s * 64 + i]      = c;
    g_rt[s * 64 + 32 + i] = sn;
}

// ---------------------------------------------------------------------------
// fp16 wmma GEMM: C(128x128) = A(128xK)*W(128xK)^T, K=1024, BK=32 halves.
// 3-stage cp.async pipeline. 8 warps: wm=wid&3 (32 rows), wn=wid>>2 (64 cols).
// ---------------------------------------------------------------------------
#define LDAH 40                   // halves; 80B row stride
#define STGH (2*128*LDAH)         // halves per stage (A+W) = 10240
#define LDC  132

using HFragA = wmma::fragment<wmma::matrix_a, 16, 16, 16, __half, wmma::row_major>;
using HFragB = wmma::fragment<wmma::matrix_b, 16, 16, 16, __half, wmma::col_major>;
using HFragC = wmma::fragment<wmma::accumulator, 16, 16, 16, float>;

__device__ __forceinline__ void hgemm_issue(const __half* __restrict__ A,
                                            const __half* __restrict__ W,
                                            __half* sm, int kb, int s, int tid)
{
    __half* As = sm + s * STGH;
    __half* Ws = As + 128 * LDAH;
#pragma unroll
    for (int i = 0; i < 2; i++) {
        int idx = tid + i * 256;            // 0..511
        int r = idx >> 2, c = (idx & 3) * 8;
        cp16(sm_u32(As + r * LDAH + c), A + (size_t)r * HIDDEN + kb * 32 + c);
        cp16(sm_u32(Ws + r * LDAH + c), W + (size_t)r * HIDDEN + kb * 32 + c);
    }
    cp_commit();
}

__device__ __forceinline__ void hgemm_mainloop(const __half* __restrict__ A,
                                               const __half* __restrict__ W,
                                               __half* sm, HFragC acc[2][4],
                                               int wm, int wn)
{
    const int tid = threadIdx.x;
#pragma unroll
    for (int mi = 0; mi < 2; mi++)
#pragma unroll
        for (int ni = 0; ni < 4; ni++)
            wmma::fill_fragment(acc[mi][ni], 0.0f);

    hgemm_issue(A, W, sm, 0, 0, tid);
    hgemm_issue(A, W, sm, 1, 1, tid);
    hgemm_issue(A, W, sm, 2, 2, tid);

    int s = 0;
    for (int kb = 0; kb < 32; kb++) {
        if      (kb < 30) cp_wait2();
        else if (kb == 30) cp_wait1();
        else               cp_wait0();
        __syncthreads();
        __half* As = sm + s * STGH;
        __half* Ws = As + 128 * LDAH;
#pragma unroll
        for (int kk = 0; kk < 32; kk += 16) {
            HFragA af[2];
            HFragB bf[4];
#pragma unroll
            for (int mi = 0; mi < 2; mi++)
                wmma::load_matrix_sync(af[mi], &As[(wm * 32 + mi * 16) * LDAH + kk], LDAH);
#pragma unroll
            for (int ni = 0; ni < 4; ni++)
                wmma::load_matrix_sync(bf[ni], &Ws[(wn * 64 + ni * 16) * LDAH + kk], LDAH);
#pragma unroll
            for (int mi = 0; mi < 2; mi++)
#pragma unroll
                for (int ni = 0; ni < 4; ni++)
                    wmma::mma_sync(acc[mi][ni], af[mi], bf[ni], acc[mi][ni]);
        }
        __syncthreads();
        if (kb + 3 < 32) hgemm_issue(A, W, sm, kb + 3, s, tid);
        s = (s == 2) ? 0 : s + 1;
    }
}

__device__ __forceinline__ void stage_C(float* Cs, HFragC acc[2][4], int wm, int wn)
{
#pragma unroll
    for (int mi = 0; mi < 2; mi++)
#pragma unroll
        for (int ni = 0; ni < 4; ni++)
            wmma::store_matrix_sync(Cs + (wm * 32 + mi * 16) * LDC + wn * 64 + ni * 16,
                                    acc[mi][ni], LDC, wmma::mem_row_major);
}

// ---------------------------------------------------------------------------
// QKV projection + bias + RoPE fused epilogue -> fp16. grid (8, 32, 3).
// ---------------------------------------------------------------------------
__global__ void __launch_bounds__(256, 2)
qkv_mma(const float* __restrict__ bq,
        const float* __restrict__ bk,
        const float* __restrict__ bv)
{
    extern __shared__ char smraw[];
    const int tid = threadIdx.x, wid = tid >> 5;
    const int wm = wid & 3, wn = wid >> 2;
    const int m0 = blockIdx.y * 128, n0 = blockIdx.x * 128;
    const int z = blockIdx.z;

    const __half* W = g_wh + (size_t)z * HH;
    const float* bias = (z == 0) ? bq : (z == 1) ? bk : bv;
    __half* dst = (z == 0) ? g_q : (z == 1) ? g_k : g_v;

    HFragC acc[2][4];
    hgemm_mainloop(g_xh + (size_t)m0 * HIDDEN, W + (size_t)n0 * HIDDEN,
                   (__half*)smraw, acc, wm, wn);

    float* Cs = (float*)smraw;
    stage_C(Cs, acc, wm, wn);
    __syncthreads();

    const int r = tid >> 1, hh = tid & 1;
    const int m = m0 + r;
    const int b = m >> 11, s = m & (SEQ - 1);
    const int h = (n0 >> 6) + hh;
    const float* crow = Cs + r * LDC + hh * 64;
    const float* brow = bias + n0 + hh * 64;
    __half* drow = dst + (((size_t)(b * HEADS + h)) * SEQ + s) * HEAD_DIM;

    if (z < 2) {
        const float* rt = g_rt + s * 64;
        const float scale = (z == 0) ? 0.125f : 1.0f;
#pragma unroll
        for (int d0 = 0; d0 < 32; d0 += 4) {
            float4 x1 = *(const float4*)(crow + d0);
            float4 x2 = *(const float4*)(crow + d0 + 32);
            float4 b1 = *(const float4*)(brow + d0);
            float4 b2 = *(const float4*)(brow + d0 + 32);
            float4 cc = *(const float4*)(rt + d0);
            float4 ss = *(const float4*)(rt + 32 + d0);
            x1.x += b1.x; x1.y += b1.y; x1.z += b1.z; x1.w += b1.w;
            x2.x += b2.x; x2.y += b2.y; x2.z += b2.z; x2.w += b2.w;
            float o1x = (x1.x * cc.x - x2.x * ss.x) * scale;
            float o1y = (x1.y * cc.y - x2.y * ss.y) * scale;
            float o1z = (x1.z * cc.z - x2.z * ss.z) * scale;
            float o1w = (x1.w * cc.w - x2.w * ss.w) * scale;
            float o2x = (x2.x * cc.x + x1.x * ss.x) * scale;
            float o2y = (x2.y * cc.y + x1.y * ss.y) * scale;
            float o2z = (x2.z * cc.z + x1.z * ss.z) * scale;
            float o2w = (x2.w * cc.w + x1.w * ss.w) * scale;
            *(__half2*)(drow + d0)      = __floats2half2_rn(o1x, o1y);
            *(__half2*)(drow + d0 + 2)  = __floats2half2_rn(o1z, o1w);
            *(__half2*)(drow + d0 + 32) = __floats2half2_rn(o2x, o2y);
            *(__half2*)(drow + d0 + 34) = __floats2half2_rn(o2z, o2w);
        }
    } else {
#pragma unroll
        for (int d0 = 0; d0 < 64; d0 += 4) {
            float4 x = *(const float4*)(crow + d0);
            float4 bb = *(const float4*)(brow + d0);
            *(__half2*)(drow + d0)     = __floats2half2_rn(x.x + bb.x, x.y + bb.y);
            *(__half2*)(drow + d0 + 2) = __floats2half2_rn(x.z + bb.z, x.w + bb.w);
        }
    }
}

// ---------------------------------------------------------------------------
// Output projection + bias. grid (8, 32).
// ---------------------------------------------------------------------------
__global__ void __launch_bounds__(256, 2)
out_mma(const float* __restrict__ bo, float* __restrict__ out)
{
    extern __shared__ char smraw[];
    const int tid = threadIdx.x, wid = tid >> 5;
    const int wm = wid & 3, wn = wid >> 2;
    const int m0 = blockIdx.y * 128, n0 = blockIdx.x * 128;

    HFragC acc[2][4];
    hgemm_mainloop(g_ao + (size_t)m0 * HIDDEN,
                   g_wh + 3 * (size_t)HH + (size_t)n0 * HIDDEN,
                   (__half*)smraw, acc, wm, wn);

    float* Cs = (float*)smraw;
    stage_C(Cs, acc, wm, wn);
    __syncthreads();

    const int r = tid >> 1, half = tid & 1;
    const float* crow = Cs + r * LDC + half * 64;
    const float* brow = bo + n0 + half * 64;
    float* orow = out + (size_t)(m0 + r) * HIDDEN + n0 + half * 64;
#pragma unroll
    for (int j = 0; j < 64; j += 4) {
        float4 x = *(const float4*)(crow + j);
        float4 bb = *(const float4*)(brow + j);
        x.x += bb.x; x.y += bb.y; x.z += bb.z; x.w += bb.w;
        *(float4*)(orow + j) = x;
    }
}

// ---------------------------------------------------------------------------
// Flash attention fp16: mma.m16n8k16, ldmatrix.x4 K/V, register-resident P.
// grid (SEQ/128, BHN), 256 threads / 8 warps; warp owns q-rows [wid*16,+16).
// ---------------------------------------------------------------------------
#define FPH 72                    // halves; 144B row stride
#define KVH (64*FPH)              // halves per K (or V) tile

__global__ void __launch_bounds__(256, 2)
flash_mma()
{
    extern __shared__ char smraw[];
    __half* KsB = (__half*)smraw;            // 2 stages [64][FPH]
    __half* VsB = KsB + 2 * KVH;             // 2 stages [64][FPH]

    const int tid = threadIdx.x, wid = tid >> 5, lane = tid & 31;
    const int g = lane >> 2, t = lane & 3;
    const int bh = blockIdx.y;
    const int q0 = blockIdx.x * 128;
    const int r0 = wid * 16;

    // ldsm.x4 per-lane base offsets (halves)
    // K x4: matrix m=lane>>3 -> keys (m>>1)*8, k-half (m&1)*8
    const int k4off = ((lane >> 4) * 8 + (lane & 7)) * FPH + ((lane >> 3) & 1) * 8;
    // V x4 trans: matrix m -> key-half (m&1)*8, d-block (m>>1)*8
    const int v4off = (((lane >> 3) & 1) * 8 + (lane & 7)) * FPH + (lane >> 4) * 8;

    // ---- Q A-fragments from global (fp16, pre-scaled) ----
    const __half* q0p = g_q + ((size_t)(bh * SEQ + q0 + r0 + g)) * HEAD_DIM;
    const __half* q8p = q0p + 8 * HEAD_DIM;
    uint32_t qa[4][4];
#pragma unroll
    for (int kb = 0; kb < 4; kb++) {
        qa[kb][0] = *(const uint32_t*)(q0p + kb * 16 + 2 * t);
        qa[kb][1] = *(const uint32_t*)(q8p + kb * 16 + 2 * t);
        qa[kb][2] = *(const uint32_t*)(q0p + kb * 16 + 8 + 2 * t);
        qa[kb][3] = *(const uint32_t*)(q8p + kb * 16 + 8 + 2 * t);
    }

    float oacc[8][4];
#pragma unroll
    for (int nb = 0; nb < 8; nb++)
#pragma unroll
        for (int e = 0; e < 4; e++) oacc[nb][e] = 0.f;
    float mA = -1e30f, mB = -1e30f, lA = 0.f, lB = 0.f;

    const __half* kbase = g_k + (size_t)bh * SEQ * HEAD_DIM;
    const __half* vbase = g_v + (size_t)bh * SEQ * HEAD_DIM;
    auto issue = [&](int kt, int s) {
        __half* Kd = KsB + s * KVH;
        __half* Vd = VsB + s * KVH;
        const __half* ks = kbase + (size_t)kt * 64 * HEAD_DIM;
        const __half* vs = vbase + (size_t)kt * 64 * HEAD_DIM;
#pragma unroll
        for (int i = 0; i < 2; i++) {
            int idx = tid + i * 256;            // 0..511
            int r = idx >> 3, c = (idx & 7) * 8;
            cp16(sm_u32(Kd + r * FPH + c), ks + r * 64 + c);
            cp16(sm_u32(Vd + r * FPH + c), vs + r * 64 + c);
        }
        cp_commit();
    };

    issue(0, 0);

    for (int kt = 0; kt < SEQ / 64; kt++) {
        int s = kt & 1;
        cp_wait0();
        __syncthreads();
        if (kt + 1 < SEQ / 64) issue(kt + 1, s ^ 1);

        const uint32_t Ku = sm_u32(KsB + s * KVH);
        const uint32_t Vu = sm_u32(VsB + s * KVH);

        // ---- S = Q K^T ----
        float sacc[8][4];
#pragma unroll
        for (int nb = 0; nb < 8; nb++)
#pragma unroll
            for (int e = 0; e < 4; e++) sacc[nb][e] = 0.f;

#pragma unroll
        for (int nb2 = 0; nb2 < 4; nb2++) {
#pragma unroll
            for (int kb = 0; kb < 4; kb++) {
                uint32_t b0, b1, b2, b3;
                ldsm_x4(b0, b1, b2, b3,
                        Ku + (uint32_t)(nb2 * 16 * FPH + kb * 16 + k4off) * 2);
                mma16(sacc[2 * nb2],     qa[kb], b0, b1);
                mma16(sacc[2 * nb2 + 1], qa[kb], b2, b3);
            }
        }

        // ---- online softmax (rows g, g+8 of warp tile) ----
        float rmA = -1e30f, rmB = -1e30f;
#pragma unroll
        for (int nb = 0; nb < 8; nb++) {
            rmA = fmaxf(rmA, fmaxf(sacc[nb][0], sacc[nb][1]));
            rmB = fmaxf(rmB, fmaxf(sacc[nb][2], sacc[nb][3]));
        }
        rmA = fmaxf(rmA, __shfl_xor_sync(0xffffffffu, rmA, 1));
        rmA = fmaxf(rmA, __shfl_xor_sync(0xffffffffu, rmA, 2));
        rmB = fmaxf(rmB, __shfl_xor_sync(0xffffffffu, rmB, 1));
        rmB = fmaxf(rmB, __shfl_xor_sync(0xffffffffu, rmB, 2));

        float mnA = fmaxf(mA, rmA), mnB = fmaxf(mB, rmB);
        float aA = __expf(mA - mnA), aB = __expf(mB - mnB);
        float rsA = 0.f, rsB = 0.f;
#pragma unroll
        for (int nb = 0; nb < 8; nb++) {
            sacc[nb][0] = __expf(sacc[nb][0] - mnA);
            sacc[nb][1] = __expf(sacc[nb][1] - mnA);
            sacc[nb][2] = __expf(sacc[nb][2] - mnB);
            sacc[nb][3] = __expf(sacc[nb][3] - mnB);
            rsA += sacc[nb][0] + sacc[nb][1];
            rsB += sacc[nb][2] + sacc[nb][3];
        }
        rsA += __shfl_xor_sync(0xffffffffu, rsA, 1);
        rsA += __shfl_xor_sync(0xffffffffu, rsA, 2);
        rsB += __shfl_xor_sync(0xffffffffu, rsB, 1);
        rsB += __shfl_xor_sync(0xffffffffu, rsB, 2);

        lA = lA * aA + rsA;  mA = mnA;
        lB = lB * aB + rsB;  mB = mnB;
#pragma unroll
        for (int nb = 0; nb < 8; nb++) {
            oacc[nb][0] *= aA; oacc[nb][1] *= aA;
            oacc[nb][2] *= aB; oacc[nb][3] *= aB;
        }

        // ---- O += P V : P packs straight from sacc into A-fragments ----
#pragma unroll
        for (int kb2 = 0; kb2 < 4; kb2++) {
            uint32_t pa[4];
            pa[0] = pack_h2(sacc[2*kb2][0],   sacc[2*kb2][1]);
            pa[1] = pack_h2(sacc[2*kb2][2],   sacc[2*kb2][3]);
            pa[2] = pack_h2(sacc[2*kb2+1][0], sacc[2*kb2+1][1]);
            pa[3] = pack_h2(sacc[2*kb2+1][2], sacc[2*kb2+1][3]);
#pragma unroll
            for (int nb2 = 0; nb2 < 4; nb2++) {
                uint32_t b0, b1, b2, b3;
                ldsm_x4_t(b0, b1, b2, b3,
                          Vu + (uint32_t)(kb2 * 16 * FPH + v4off + nb2 * 16) * 2);
                mma16(oacc[2 * nb2],     pa, b0, b1);
                mma16(oacc[2 * nb2 + 1], pa, b2, b3);
            }
        }
    }

    // ---- epilogue: normalize + write fp16 to g_ao ----
    const int b = bh >> 4, h = bh & 15;
    float invA = 1.0f / lA, invB = 1.0f / lB;
    int rA = q0 + r0 + g, rB = rA + 8;
#pragma unroll
    for (int nb = 0; nb < 8; nb++) {
        int col = h * HEAD_DIM + nb * 8 + 2 * t;
        *(__half2*)&g_ao[((size_t)(b * SEQ + rA)) * HIDDEN + col] =
            __floats2half2_rn(oacc[nb][0] * invA, oacc[nb][1] * invA);
        *(__half2*)&g_ao[((size_t)(b * SEQ + rB)) * HIDDEN + col] =
            __floats2half2_rn(oacc[nb][2] * invB, oacc[nb][3] * invB);
    }
}

// ---------------------------------------------------------------------------
extern "C" void kernel_launch(void* const* d_in, const int* in_sizes, int n_in,
                              void* d_out, int out_size)
{
    const float* X  = (const float*)d_in[0];
    const float* Wq = (const float*)d_in[1];
    const float* bq = (const float*)d_in[2];
    const float* Wk = (const float*)d_in[3];
    const float* bk = (const float*)d_in[4];
    const float* Wv = (const float*)d_in[5];
    const float* bv = (const float*)d_in[6];
    const float* Wo = (const float*)d_in[7];
    const float* bo = (const float*)d_in[8];
    float* out = (float*)d_out;

    static const int GEMM_SMEM  = 128 * LDC * 4;      // 67584 (covers 3-stage 61440)
    static const int FLASH_SMEM = 4 * KVH * 2;        // 36864
    cudaFuncSetAttribute(qkv_mma,  cudaFuncAttributeMaxDynamicSharedMemorySize, GEMM_SMEM);
    cudaFuncSetAttribute(out_mma,  cudaFuncAttributeMaxDynamicSharedMemorySize, GEMM_SMEM);
    cudaFuncSetAttribute(flash_mma, cudaFuncAttributeMaxDynamicSharedMemorySize, FLASH_SMEM);

    ropetab_kernel<<<(SEQ * 32) / 256, 256>>>();
    conv_kernel<<<(XN4 + 4 * WN4) / 256, 256>>>(X, Wq, Wk, Wv, Wo);

    dim3 gq(HIDDEN / 128, MTOT / 128, 3);
    qkv_mma<<<gq, 256, GEMM_SMEM>>>(bq, bk, bv);

    dim3 gf(SEQ / 128, BHN);
    flash_mma<<<gf, 256, FLASH_SMEM>>>();

    dim3 go(HIDDEN / 128, MTOT / 128, 1);
    out_mma<<<go, 256, GEMM_SMEM>>>(bo, out);
}

// round 11
// speedup vs baseline: 6.2116x; 1.0442x over previous
#include <cuda_runtime.h>
#include <cuda_fp16.h>
#include <mma.h>
#include <math.h>
#include <cstdint>

using namespace nvcuda;

#define BATCH    2
#define SEQ      2048
#define HIDDEN   1024
#define HEADS    16
#define HEAD_DIM 64
#define MTOT     (BATCH*SEQ)      // 4096
#define BHN      (BATCH*HEADS)    // 32
#define HH       (HIDDEN*HIDDEN)

// scratch (allocation-free rule: __device__ globals)
static __device__ __half g_xh[MTOT*HIDDEN];        // X in fp16
static __device__ __half g_wh[4*HH];               // Wq,Wk,Wv,Wo in fp16
static __device__ float  g_rt[SEQ*64];             // rope: [s][0:32)=cos,[32:64)=sin
static __device__ __half g_q [BHN*SEQ*HEAD_DIM];   // [B,H,S,D] fp16 (q scaled by 1/8*log2e)
static __device__ __half g_k [BHN*SEQ*HEAD_DIM];
static __device__ __half g_v [BHN*SEQ*HEAD_DIM];
static __device__ __half g_ao[MTOT*HIDDEN];        // attention out fp16

// ---------------------------------------------------------------------------
// helpers
// ---------------------------------------------------------------------------
__device__ __forceinline__ void cp16(uint32_t dst, const void* src) {
    asm volatile("cp.async.cg.shared.global [%0], [%1], 16;" :: "r"(dst), "l"(src));
}
__device__ __forceinline__ void cp_commit() {
    asm volatile("cp.async.commit_group;" ::: "memory");
}
__device__ __forceinline__ void cp_wait0() {
    asm volatile("cp.async.wait_group 0;" ::: "memory");
}
__device__ __forceinline__ void cp_wait1() {
    asm volatile("cp.async.wait_group 1;" ::: "memory");
}
__device__ __forceinline__ void cp_wait2() {
    asm volatile("cp.async.wait_group 2;" ::: "memory");
}
__device__ __forceinline__ uint32_t sm_u32(const void* p) {
    return (uint32_t)__cvta_generic_to_shared(p);
}
__device__ __forceinline__ uint32_t pack_h2(float lo, float hi) {
    __half2 h = __floats2half2_rn(lo, hi);
    return *reinterpret_cast<uint32_t*>(&h);
}
__device__ __forceinline__ float ex2(float x) {
    float y;
    asm("ex2.approx.ftz.f32 %0, %1;" : "=f"(y) : "f"(x));
    return y;
}
__device__ __forceinline__ void mma16(float d[4], const uint32_t a[4],
                                      uint32_t b0, uint32_t b1)
{
    asm volatile(
        "mma.sync.aligned.m16n8k16.row.col.f32.f16.f16.f32 "
        "{%0,%1,%2,%3}, {%4,%5,%6,%7}, {%8,%9}, {%0,%1,%2,%3};"
        : "+f"(d[0]), "+f"(d[1]), "+f"(d[2]), "+f"(d[3])
        : "r"(a[0]), "r"(a[1]), "r"(a[2]), "r"(a[3]), "r"(b0), "r"(b1));
}
__device__ __forceinline__ void ldsm_x4(uint32_t& r0, uint32_t& r1,
                                        uint32_t& r2, uint32_t& r3, uint32_t addr) {
    asm volatile("ldmatrix.sync.aligned.m8n8.x4.shared.b16 {%0,%1,%2,%3}, [%4];"
                 : "=r"(r0), "=r"(r1), "=r"(r2), "=r"(r3) : "r"(addr));
}
__device__ __forceinline__ void ldsm_x4_t(uint32_t& r0, uint32_t& r1,
                                          uint32_t& r2, uint32_t& r3, uint32_t addr) {
    asm volatile("ldmatrix.sync.aligned.m8n8.x4.trans.shared.b16 {%0,%1,%2,%3}, [%4];"
                 : "=r"(r0), "=r"(r1), "=r"(r2), "=r"(r3) : "r"(addr));
}

// ---------------------------------------------------------------------------
// setup: fp16 conversion + rope table
// ---------------------------------------------------------------------------
#define XN4 (MTOT*HIDDEN/4)       // 1048576
#define WN4 (HH/4)                // 262144
__global__ void conv_kernel(const float* __restrict__ X,
                            const float* __restrict__ Wq,
                            const float* __restrict__ Wk,
                            const float* __restrict__ Wv,
                            const float* __restrict__ Wo)
{
    int gid = blockIdx.x * blockDim.x + threadIdx.x;
    const float4* s4; __half2* d2;
    if (gid < XN4) {
        s4 = (const float4*)X + gid;
        d2 = (__half2*)g_xh + (size_t)gid * 2;
    } else {
        int w = gid - XN4;
        int sel = w >> 18;          // WN4 = 2^18
        int off = w & (WN4 - 1);
        const float* W = (sel == 0) ? Wq : (sel == 1) ? Wk : (sel == 2) ? Wv : Wo;
        s4 = (const float4*)W + off;
        d2 = (__half2*)g_wh + ((size_t)sel * WN4 + off) * 2;
    }
    float4 v = *s4;
    d2[0] = __floats2half2_rn(v.x, v.y);
    d2[1] = __floats2half2_rn(v.z, v.w);
}

__global__ void ropetab_kernel()
{
    int t = blockIdx.x * blockDim.x + threadIdx.x;   // < SEQ*32
    int i = t & 31, s = t >> 5;
    float inv = powf(10000.0f, -(float)i * (1.0f / 32.0f));
    float c, sn;
    sincosf((float)s * inv, &sn, &c);
    g_rt[s * 64 + i]      = c;
    g_rt[s * 64 + 32 + i] = sn;
}

// ---------------------------------------------------------------------------
// fp16 wmma GEMM: C(128x128) = A(128xK)*W(128xK)^T, K=1024, BK=32 halves.
// 3-stage cp.async pipeline. 8 warps: wm=wid&3 (32 rows), wn=wid>>2 (64 cols).
// ---------------------------------------------------------------------------
#define LDAH 40                   // halves; 80B row stride
#define STGH (2*128*LDAH)         // halves per stage (A+W) = 10240
#define LDC  132

using HFragA = wmma::fragment<wmma::matrix_a, 16, 16, 16, __half, wmma::row_major>;
using HFragB = wmma::fragment<wmma::matrix_b, 16, 16, 16, __half, wmma::col_major>;
using HFragC = wmma::fragment<wmma::accumulator, 16, 16, 16, float>;

__device__ __forceinline__ void hgemm_issue(const __half* __restrict__ A,
                                            const __half* __restrict__ W,
                                            __half* sm, int kb, int s, int tid)
{
    __half* As = sm + s * STGH;
    __half* Ws = As + 128 * LDAH;
#pragma unroll
    for (int i = 0; i < 2; i++) {
        int idx = tid + i * 256;            // 0..511
        int r = idx >> 2, c = (idx & 3) * 8;
        cp16(sm_u32(As + r * LDAH + c), A + (size_t)r * HIDDEN + kb * 32 + c);
        cp16(sm_u32(Ws + r * LDAH + c), W + (size_t)r * HIDDEN + kb * 32 + c);
    }
    cp_commit();
}

__device__ __forceinline__ void hgemm_mainloop(const __half* __restrict__ A,
                                               const __half* __restrict__ W,
                                               __half* sm, HFragC acc[2][4],
                                               int wm, int wn)
{
    const int tid = threadIdx.x;
#pragma unroll
    for (int mi = 0; mi < 2; mi++)
#pragma unroll
        for (int ni = 0; ni < 4; ni++)
            wmma::fill_fragment(acc[mi][ni], 0.0f);

    hgemm_issue(A, W, sm, 0, 0, tid);
    hgemm_issue(A, W, sm, 1, 1, tid);
    hgemm_issue(A, W, sm, 2, 2, tid);

    int s = 0;
    for (int kb = 0; kb < 32; kb++) {
        if      (kb < 30) cp_wait2();
        else if (kb == 30) cp_wait1();
        else               cp_wait0();
        __syncthreads();
        __half* As = sm + s * STGH;
        __half* Ws = As + 128 * LDAH;
#pragma unroll
        for (int kk = 0; kk < 32; kk += 16) {
            HFragA af[2];
            HFragB bf[4];
#pragma unroll
            for (int mi = 0; mi < 2; mi++)
                wmma::load_matrix_sync(af[mi], &As[(wm * 32 + mi * 16) * LDAH + kk], LDAH);
#pragma unroll
            for (int ni = 0; ni < 4; ni++)
                wmma::load_matrix_sync(bf[ni], &Ws[(wn * 64 + ni * 16) * LDAH + kk], LDAH);
#pragma unroll
            for (int mi = 0; mi < 2; mi++)
#pragma unroll
                for (int ni = 0; ni < 4; ni++)
                    wmma::mma_sync(acc[mi][ni], af[mi], bf[ni], acc[mi][ni]);
        }
        __syncthreads();
        if (kb + 3 < 32) hgemm_issue(A, W, sm, kb + 3, s, tid);
        s = (s == 2) ? 0 : s + 1;
    }
}

__device__ __forceinline__ void stage_C(float* Cs, HFragC acc[2][4], int wm, int wn)
{
#pragma unroll
    for (int mi = 0; mi < 2; mi++)
#pragma unroll
        for (int ni = 0; ni < 4; ni++)
            wmma::store_matrix_sync(Cs + (wm * 32 + mi * 16) * LDC + wn * 64 + ni * 16,
                                    acc[mi][ni], LDC, wmma::mem_row_major);
}

// ---------------------------------------------------------------------------
// QKV projection + bias + RoPE fused epilogue -> fp16. grid (8, 32, 3).
// q additionally scaled by 1/8 * log2(e) so flash can use ex2 directly.
// ---------------------------------------------------------------------------
__global__ void __launch_bounds__(256, 2)
qkv_mma(const float* __restrict__ bq,
        const float* __restrict__ bk,
        const float* __restrict__ bv)
{
    extern __shared__ char smraw[];
    const int tid = threadIdx.x, wid = tid >> 5;
    const int wm = wid & 3, wn = wid >> 2;
    const int m0 = blockIdx.y * 128, n0 = blockIdx.x * 128;
    const int z = blockIdx.z;

    const __half* W = g_wh + (size_t)z * HH;
    const float* bias = (z == 0) ? bq : (z == 1) ? bk : bv;
    __half* dst = (z == 0) ? g_q : (z == 1) ? g_k : g_v;

    HFragC acc[2][4];
    hgemm_mainloop(g_xh + (size_t)m0 * HIDDEN, W + (size_t)n0 * HIDDEN,
                   (__half*)smraw, acc, wm, wn);

    float* Cs = (float*)smraw;
    stage_C(Cs, acc, wm, wn);
    __syncthreads();

    const int r = tid >> 1, hh = tid & 1;
    const int m = m0 + r;
    const int b = m >> 11, s = m & (SEQ - 1);
    const int h = (n0 >> 6) + hh;
    const float* crow = Cs + r * LDC + hh * 64;
    const float* brow = bias + n0 + hh * 64;
    __half* drow = dst + (((size_t)(b * HEADS + h)) * SEQ + s) * HEAD_DIM;

    if (z < 2) {
        const float* rt = g_rt + s * 64;
        // q: fold 1/sqrt(64) * log2(e)  (flash uses ex2)
        const float scale = (z == 0) ? 0.125f * 1.44269504088896f : 1.0f;
#pragma unroll
        for (int d0 = 0; d0 < 32; d0 += 4) {
            float4 x1 = *(const float4*)(crow + d0);
            float4 x2 = *(const float4*)(crow + d0 + 32);
            float4 b1 = *(const float4*)(brow + d0);
            float4 b2 = *(const float4*)(brow + d0 + 32);
            float4 cc = *(const float4*)(rt + d0);
            float4 ss = *(const float4*)(rt + 32 + d0);
            x1.x += b1.x; x1.y += b1.y; x1.z += b1.z; x1.w += b1.w;
            x2.x += b2.x; x2.y += b2.y; x2.z += b2.z; x2.w += b2.w;
            float o1x = (x1.x * cc.x - x2.x * ss.x) * scale;
            float o1y = (x1.y * cc.y - x2.y * ss.y) * scale;
            float o1z = (x1.z * cc.z - x2.z * ss.z) * scale;
            float o1w = (x1.w * cc.w - x2.w * ss.w) * scale;
            float o2x = (x2.x * cc.x + x1.x * ss.x) * scale;
            float o2y = (x2.y * cc.y + x1.y * ss.y) * scale;
            float o2z = (x2.z * cc.z + x1.z * ss.z) * scale;
            float o2w = (x2.w * cc.w + x1.w * ss.w) * scale;
            *(__half2*)(drow + d0)      = __floats2half2_rn(o1x, o1y);
            *(__half2*)(drow + d0 + 2)  = __floats2half2_rn(o1z, o1w);
            *(__half2*)(drow + d0 + 32) = __floats2half2_rn(o2x, o2y);
            *(__half2*)(drow + d0 + 34) = __floats2half2_rn(o2z, o2w);
        }
    } else {
#pragma unroll
        for (int d0 = 0; d0 < 64; d0 += 4) {
            float4 x = *(const float4*)(crow + d0);
            float4 bb = *(const float4*)(brow + d0);
            *(__half2*)(drow + d0)     = __floats2half2_rn(x.x + bb.x, x.y + bb.y);
            *(__half2*)(drow + d0 + 2) = __floats2half2_rn(x.z + bb.z, x.w + bb.w);
        }
    }
}

// ---------------------------------------------------------------------------
// Output projection + bias. grid (8, 32).
// ---------------------------------------------------------------------------
__global__ void __launch_bounds__(256, 2)
out_mma(const float* __restrict__ bo, float* __restrict__ out)
{
    extern __shared__ char smraw[];
    const int tid = threadIdx.x, wid = tid >> 5;
    const int wm = wid & 3, wn = wid >> 2;
    const int m0 = blockIdx.y * 128, n0 = blockIdx.x * 128;

    HFragC acc[2][4];
    hgemm_mainloop(g_ao + (size_t)m0 * HIDDEN,
                   g_wh + 3 * (size_t)HH + (size_t)n0 * HIDDEN,
                   (__half*)smraw, acc, wm, wn);

    float* Cs = (float*)smraw;
    stage_C(Cs, acc, wm, wn);
    __syncthreads();

    const int r = tid >> 1, half = tid & 1;
    const float* crow = Cs + r * LDC + half * 64;
    const float* brow = bo + n0 + half * 64;
    float* orow = out + (size_t)(m0 + r) * HIDDEN + n0 + half * 64;
#pragma unroll
    for (int j = 0; j < 64; j += 4) {
        float4 x = *(const float4*)(crow + j);
        float4 bb = *(const float4*)(brow + j);
        x.x += bb.x; x.y += bb.y; x.z += bb.z; x.w += bb.w;
        *(float4*)(orow + j) = x;
    }
}

// ---------------------------------------------------------------------------
// Flash attention fp16: mma.m16n8k16, ldmatrix.x4, register-resident P, ex2.
// grid (SEQ/128, BHN), 256 threads / 8 warps; warp owns q-rows [wid*16,+16).
// K/V staged 128 keys at a time (double-buffered), computed in two 64-key halves.
// ---------------------------------------------------------------------------
#define FPH 72                    // halves; 144B row stride
#define KROWS 128                 // keys per stage
#define KVH (KROWS*FPH)           // halves per K (or V) stage

__global__ void __launch_bounds__(256, 2)
flash_mma()
{
    extern __shared__ char smraw[];
    __half* KsB = (__half*)smraw;            // 2 stages [128][FPH]
    __half* VsB = KsB + 2 * KVH;             // 2 stages [128][FPH]

    const int tid = threadIdx.x, wid = tid >> 5, lane = tid & 31;
    const int g = lane >> 2, t = lane & 3;
    const int bh = blockIdx.y;
    const int q0 = blockIdx.x * 128;
    const int r0 = wid * 16;

    // ldsm.x4 per-lane base offsets (halves)
    const int k4off = ((lane >> 4) * 8 + (lane & 7)) * FPH + ((lane >> 3) & 1) * 8;
    const int v4off = (((lane >> 3) & 1) * 8 + (lane & 7)) * FPH + (lane >> 4) * 8;

    // ---- Q A-fragments from global (fp16, pre-scaled incl log2e) ----
    const __half* q0p = g_q + ((size_t)(bh * SEQ + q0 + r0 + g)) * HEAD_DIM;
    const __half* q8p = q0p + 8 * HEAD_DIM;
    uint32_t qa[4][4];
#pragma unroll
    for (int kb = 0; kb < 4; kb++) {
        qa[kb][0] = *(const uint32_t*)(q0p + kb * 16 + 2 * t);
        qa[kb][1] = *(const uint32_t*)(q8p + kb * 16 + 2 * t);
        qa[kb][2] = *(const uint32_t*)(q0p + kb * 16 + 8 + 2 * t);
        qa[kb][3] = *(const uint32_t*)(q8p + kb * 16 + 8 + 2 * t);
    }

    float oacc[8][4];
#pragma unroll
    for (int nb = 0; nb < 8; nb++)
#pragma unroll
        for (int e = 0; e < 4; e++) oacc[nb][e] = 0.f;
    float mA = -1e30f, mB = -1e30f, lA = 0.f, lB = 0.f;

    const __half* kbase = g_k + (size_t)bh * SEQ * HEAD_DIM;
    const __half* vbase = g_v + (size_t)bh * SEQ * HEAD_DIM;
    auto issue = [&](int kt, int s) {
        __half* Kd = KsB + s * KVH;
        __half* Vd = VsB + s * KVH;
        const __half* ks = kbase + (size_t)kt * KROWS * HEAD_DIM;
        const __half* vs = vbase + (size_t)kt * KROWS * HEAD_DIM;
#pragma unroll
        for (int i = 0; i < 4; i++) {
            int idx = tid + i * 256;            // 0..1023
            int r = idx >> 3, c = (idx & 7) * 8;
            cp16(sm_u32(Kd + r * FPH + c), ks + r * 64 + c);
            cp16(sm_u32(Vd + r * FPH + c), vs + r * 64 + c);
        }
        cp_commit();
    };

    issue(0, 0);

    for (int kt = 0; kt < SEQ / KROWS; kt++) {
        int s = kt & 1;
        cp_wait0();
        __syncthreads();
        if (kt + 1 < SEQ / KROWS) issue(kt + 1, s ^ 1);

#pragma unroll
        for (int hlf = 0; hlf < 2; hlf++) {
            const uint32_t Ku = sm_u32(KsB + s * KVH + hlf * 64 * FPH);
            const uint32_t Vu = sm_u32(VsB + s * KVH + hlf * 64 * FPH);

            // ---- S = Q K^T (scores in log2 domain) ----
            float sacc[8][4];
#pragma unroll
            for (int nb = 0; nb < 8; nb++)
#pragma unroll
                for (int e = 0; e < 4; e++) sacc[nb][e] = 0.f;

#pragma unroll
            for (int nb2 = 0; nb2 < 4; nb2++) {
#pragma unroll
                for (int kb = 0; kb < 4; kb++) {
                    uint32_t b0, b1, b2, b3;
                    ldsm_x4(b0, b1, b2, b3,
                            Ku + (uint32_t)(nb2 * 16 * FPH + kb * 16 + k4off) * 2);
                    mma16(sacc[2 * nb2],     qa[kb], b0, b1);
                    mma16(sacc[2 * nb2 + 1], qa[kb], b2, b3);
                }
            }

            // ---- online softmax (rows g, g+8 of warp tile), base-2 ----
            float rmA = -1e30f, rmB = -1e30f;
#pragma unroll
            for (int nb = 0; nb < 8; nb++) {
                rmA = fmaxf(rmA, fmaxf(sacc[nb][0], sacc[nb][1]));
                rmB = fmaxf(rmB, fmaxf(sacc[nb][2], sacc[nb][3]));
            }
            rmA = fmaxf(rmA, __shfl_xor_sync(0xffffffffu, rmA, 1));
            rmA = fmaxf(rmA, __shfl_xor_sync(0xffffffffu, rmA, 2));
            rmB = fmaxf(rmB, __shfl_xor_sync(0xffffffffu, rmB, 1));
            rmB = fmaxf(rmB, __shfl_xor_sync(0xffffffffu, rmB, 2));

            float mnA = fmaxf(mA, rmA), mnB = fmaxf(mB, rmB);
            float aA = ex2(mA - mnA), aB = ex2(mB - mnB);
            float rsA = 0.f, rsB = 0.f;
#pragma unroll
            for (int nb = 0; nb < 8; nb++) {
                sacc[nb][0] = ex2(sacc[nb][0] - mnA);
                sacc[nb][1] = ex2(sacc[nb][1] - mnA);
                sacc[nb][2] = ex2(sacc[nb][2] - mnB);
                sacc[nb][3] = ex2(sacc[nb][3] - mnB);
                rsA += sacc[nb][0] + sacc[nb][1];
                rsB += sacc[nb][2] + sacc[nb][3];
            }
            rsA += __shfl_xor_sync(0xffffffffu, rsA, 1);
            rsA += __shfl_xor_sync(0xffffffffu, rsA, 2);
            rsB += __shfl_xor_sync(0xffffffffu, rsB, 1);
            rsB += __shfl_xor_sync(0xffffffffu, rsB, 2);

            lA = lA * aA + rsA;  mA = mnA;
            lB = lB * aB + rsB;  mB = mnB;
#pragma unroll
            for (int nb = 0; nb < 8; nb++) {
                oacc[nb][0] *= aA; oacc[nb][1] *= aA;
                oacc[nb][2] *= aB; oacc[nb][3] *= aB;
            }

            // ---- O += P V : P packs straight from sacc into A-fragments ----
#pragma unroll
            for (int kb2 = 0; kb2 < 4; kb2++) {
                uint32_t pa[4];
                pa[0] = pack_h2(sacc[2*kb2][0],   sacc[2*kb2][1]);
                pa[1] = pack_h2(sacc[2*kb2][2],   sacc[2*kb2][3]);
                pa[2] = pack_h2(sacc[2*kb2+1][0], sacc[2*kb2+1][1]);
                pa[3] = pack_h2(sacc[2*kb2+1][2], sacc[2*kb2+1][3]);
#pragma unroll
                for (int nb2 = 0; nb2 < 4; nb2++) {
                    uint32_t b0, b1, b2, b3;
                    ldsm_x4_t(b0, b1, b2, b3,
                              Vu + (uint32_t)(kb2 * 16 * FPH + v4off + nb2 * 16) * 2);
                    mma16(oacc[2 * nb2],     pa, b0, b1);
                    mma16(oacc[2 * nb2 + 1], pa, b2, b3);
                }
            }
        }
    }

    // ---- epilogue: normalize + write fp16 to g_ao ----
    const int b = bh >> 4, h = bh & 15;
    float invA = 1.0f / lA, invB = 1.0f / lB;
    int rA = q0 + r0 + g, rB = rA + 8;
#pragma unroll
    for (int nb = 0; nb < 8; nb++) {
        int col = h * HEAD_DIM + nb * 8 + 2 * t;
        *(__half2*)&g_ao[((size_t)(b * SEQ + rA)) * HIDDEN + col] =
            __floats2half2_rn(oacc[nb][0] * invA, oacc[nb][1] * invA);
        *(__half2*)&g_ao[((size_t)(b * SEQ + rB)) * HIDDEN + col] =
            __floats2half2_rn(oacc[nb][2] * invB, oacc[nb][3] * invB);
    }
}

// ---------------------------------------------------------------------------
extern "C" void kernel_launch(void* const* d_in, const int* in_sizes, int n_in,
                              void* d_out, int out_size)
{
    const float* X  = (const float*)d_in[0];
    const float* Wq = (const float*)d_in[1];
    const float* bq = (const float*)d_in[2];
    const float* Wk = (const float*)d_in[3];
    const float* bk = (const float*)d_in[4];
    const float* Wv = (const float*)d_in[5];
    const float* bv = (const float*)d_in[6];
    const float* Wo = (const float*)d_in[7];
    const float* bo = (const float*)d_in[8];
    float* out = (float*)d_out;

    static const int GEMM_SMEM  = 128 * LDC * 4;      // 67584 (covers 3-stage 61440)
    static const int FLASH_SMEM = 4 * KVH * 2;        // 73728
    cudaFuncSetAttribute(qkv_mma,  cudaFuncAttributeMaxDynamicSharedMemorySize, GEMM_SMEM);
    cudaFuncSetAttribute(out_mma,  cudaFuncAttributeMaxDynamicSharedMemorySize, GEMM_SMEM);
    cudaFuncSetAttribute(flash_mma, cudaFuncAttributeMaxDynamicSharedMemorySize, FLASH_SMEM);

    ropetab_kernel<<<(SEQ * 32) / 256, 256>>>();
    conv_kernel<<<(XN4 + 4 * WN4) / 256, 256>>>(X, Wq, Wk, Wv, Wo);

    dim3 gq(HIDDEN / 128, MTOT / 128, 3);
    qkv_mma<<<gq, 256, GEMM_SMEM>>>(bq, bk, bv);

    dim3 gf(SEQ / 128, BHN);
    flash_mma<<<gf, 256, FLASH_SMEM>>>();

    dim3 go(HIDDEN / 128, MTOT / 128, 1);
    out_mma<<<go, 256, GEMM_SMEM>>>(bo, out);
}

// round 12
// speedup vs baseline: 6.4833x; 1.0437x over previous
#include <cuda_runtime.h>
#include <cuda_fp16.h>
#include <mma.h>
#include <math.h>
#include <cstdint>

using namespace nvcuda;

#define BATCH    2
#define SEQ      2048
#define HIDDEN   1024
#define HEADS    16
#define HEAD_DIM 64
#define MTOT     (BATCH*SEQ)      // 4096
#define BHN      (BATCH*HEADS)    // 32
#define HH       (HIDDEN*HIDDEN)

// scratch (allocation-free rule: __device__ globals)
static __device__ __half g_xh[MTOT*HIDDEN];        // X in fp16
static __device__ __half g_wh[4*HH];               // Wq,Wk,Wv,Wo in fp16
static __device__ float  g_rt[SEQ*64];             // rope: [s][0:32)=cos,[32:64)=sin
static __device__ __half g_q [BHN*SEQ*HEAD_DIM];   // [B,H,S,D] fp16 (q scaled by 1/8*log2e)
static __device__ __half g_k [BHN*SEQ*HEAD_DIM];
static __device__ __half g_v [BHN*SEQ*HEAD_DIM];
static __device__ __half g_ao[MTOT*HIDDEN];        // attention out fp16

// ---------------------------------------------------------------------------
// helpers
// ---------------------------------------------------------------------------
__device__ __forceinline__ void cp16(uint32_t dst, const void* src) {
    asm volatile("cp.async.cg.shared.global [%0], [%1], 16;" :: "r"(dst), "l"(src));
}
__device__ __forceinline__ void cp_commit() {
    asm volatile("cp.async.commit_group;" ::: "memory");
}
__device__ __forceinline__ void cp_wait0() {
    asm volatile("cp.async.wait_group 0;" ::: "memory");
}
__device__ __forceinline__ void cp_wait1() {
    asm volatile("cp.async.wait_group 1;" ::: "memory");
}
__device__ __forceinline__ void cp_wait2() {
    asm volatile("cp.async.wait_group 2;" ::: "memory");
}
__device__ __forceinline__ uint32_t sm_u32(const void* p) {
    return (uint32_t)__cvta_generic_to_shared(p);
}
__device__ __forceinline__ uint32_t pack_h2(float lo, float hi) {
    __half2 h = __floats2half2_rn(lo, hi);
    return *reinterpret_cast<uint32_t*>(&h);
}
__device__ __forceinline__ float ex2(float x) {
    float y;
    asm("ex2.approx.ftz.f32 %0, %1;" : "=f"(y) : "f"(x));
    return y;
}
__device__ __forceinline__ void mma16(float d[4], const uint32_t a[4],
                                      uint32_t b0, uint32_t b1)
{
    asm volatile(
        "mma.sync.aligned.m16n8k16.row.col.f32.f16.f16.f32 "
        "{%0,%1,%2,%3}, {%4,%5,%6,%7}, {%8,%9}, {%0,%1,%2,%3};"
        : "+f"(d[0]), "+f"(d[1]), "+f"(d[2]), "+f"(d[3])
        : "r"(a[0]), "r"(a[1]), "r"(a[2]), "r"(a[3]), "r"(b0), "r"(b1));
}
__device__ __forceinline__ void ldsm_x4(uint32_t& r0, uint32_t& r1,
                                        uint32_t& r2, uint32_t& r3, uint32_t addr) {
    asm volatile("ldmatrix.sync.aligned.m8n8.x4.shared.b16 {%0,%1,%2,%3}, [%4];"
                 : "=r"(r0), "=r"(r1), "=r"(r2), "=r"(r3) : "r"(addr));
}
__device__ __forceinline__ void ldsm_x4_t(uint32_t& r0, uint32_t& r1,
                                          uint32_t& r2, uint32_t& r3, uint32_t addr) {
    asm volatile("ldmatrix.sync.aligned.m8n8.x4.trans.shared.b16 {%0,%1,%2,%3}, [%4];"
                 : "=r"(r0), "=r"(r1), "=r"(r2), "=r"(r3) : "r"(addr));
}

// ---------------------------------------------------------------------------
// setup: fp16 conversion + rope table (merged, one launch)
// ---------------------------------------------------------------------------
#define XN4 (MTOT*HIDDEN/4)       // 1048576
#define WN4 (HH/4)                // 262144
#define CONVN (XN4 + 4*WN4)       // 2097152
__global__ void conv_kernel(const float* __restrict__ X,
                            const float* __restrict__ Wq,
                            const float* __restrict__ Wk,
                            const float* __restrict__ Wv,
                            const float* __restrict__ Wo)
{
    int gid = blockIdx.x * blockDim.x + threadIdx.x;
    if (gid < CONVN) {
        const float4* s4; __half2* d2;
        if (gid < XN4) {
            s4 = (const float4*)X + gid;
            d2 = (__half2*)g_xh + (size_t)gid * 2;
        } else {
            int w = gid - XN4;
            int sel = w >> 18;          // WN4 = 2^18
            int off = w & (WN4 - 1);
            const float* W = (sel == 0) ? Wq : (sel == 1) ? Wk : (sel == 2) ? Wv : Wo;
            s4 = (const float4*)W + off;
            d2 = (__half2*)g_wh + ((size_t)sel * WN4 + off) * 2;
        }
        float4 v = *s4;
        d2[0] = __floats2half2_rn(v.x, v.y);
        d2[1] = __floats2half2_rn(v.z, v.w);
    } else {
        int t = gid - CONVN;            // < SEQ*32
        int i = t & 31, s = t >> 5;
        float inv = powf(10000.0f, -(float)i * (1.0f / 32.0f));
        float c, sn;
        sincosf((float)s * inv, &sn, &c);
        g_rt[s * 64 + i]      = c;
        g_rt[s * 64 + 32 + i] = sn;
    }
}

// ---------------------------------------------------------------------------
// fp16 wmma GEMM: C(128x128) = A(128xK)*W(128xK)^T, K=1024, BK=32 halves.
// 4-stage cp.async pipeline, ONE __syncthreads per iteration.
// 8 warps: wm=wid&3 (32 rows), wn=wid>>2 (64 cols).
// ---------------------------------------------------------------------------
#define LDAH 40                   // halves; 80B row stride
#define STGH (2*128*LDAH)         // halves per stage (A+W) = 10240
#define LDC  132

using HFragA = wmma::fragment<wmma::matrix_a, 16, 16, 16, __half, wmma::row_major>;
using HFragB = wmma::fragment<wmma::matrix_b, 16, 16, 16, __half, wmma::col_major>;
using HFragC = wmma::fragment<wmma::accumulator, 16, 16, 16, float>;

__device__ __forceinline__ void hgemm_issue(const __half* __restrict__ A,
                                            const __half* __restrict__ W,
                                            __half* sm, int kb, int s, int tid)
{
    __half* As = sm + s * STGH;
    __half* Ws = As + 128 * LDAH;
#pragma unroll
    for (int i = 0; i < 2; i++) {
        int idx = tid + i * 256;            // 0..511
        int r = idx >> 2, c = (idx & 3) * 8;
        cp16(sm_u32(As + r * LDAH + c), A + (size_t)r * HIDDEN + kb * 32 + c);
        cp16(sm_u32(Ws + r * LDAH + c), W + (size_t)r * HIDDEN + kb * 32 + c);
    }
    cp_commit();
}

__device__ __forceinline__ void hgemm_mainloop(const __half* __restrict__ A,
                                               const __half* __restrict__ W,
                                               __half* sm, HFragC acc[2][4],
                                               int wm, int wn)
{
    const int tid = threadIdx.x;
#pragma unroll
    for (int mi = 0; mi < 2; mi++)
#pragma unroll
        for (int ni = 0; ni < 4; ni++)
            wmma::fill_fragment(acc[mi][ni], 0.0f);

    hgemm_issue(A, W, sm, 0, 0, tid);
    hgemm_issue(A, W, sm, 1, 1, tid);
    hgemm_issue(A, W, sm, 2, 2, tid);

    for (int kb = 0; kb < 32; kb++) {
        int s = kb & 3;
        if      (kb < 30)  cp_wait2();
        else if (kb == 30) cp_wait1();
        else               cp_wait0();
        __syncthreads();
        // issue next tile into stage (kb+3)&3 = (kb-1)&3 — consumed at iter kb-1,
        // which every warp has passed once it crossed the sync above.
        if (kb + 3 < 32) hgemm_issue(A, W, sm, kb + 3, (kb + 3) & 3, tid);

        __half* As = sm + s * STGH;
        __half* Ws = As + 128 * LDAH;
#pragma unroll
        for (int kk = 0; kk < 32; kk += 16) {
            HFragA af[2];
            HFragB bf[4];
#pragma unroll
            for (int mi = 0; mi < 2; mi++)
                wmma::load_matrix_sync(af[mi], &As[(wm * 32 + mi * 16) * LDAH + kk], LDAH);
#pragma unroll
            for (int ni = 0; ni < 4; ni++)
                wmma::load_matrix_sync(bf[ni], &Ws[(wn * 64 + ni * 16) * LDAH + kk], LDAH);
#pragma unroll
            for (int mi = 0; mi < 2; mi++)
#pragma unroll
                for (int ni = 0; ni < 4; ni++)
                    wmma::mma_sync(acc[mi][ni], af[mi], bf[ni], acc[mi][ni]);
        }
    }
    __syncthreads();   // before epilogue reuses smem
}

__device__ __forceinline__ void stage_C(float* Cs, HFragC acc[2][4], int wm, int wn)
{
#pragma unroll
    for (int mi = 0; mi < 2; mi++)
#pragma unroll
        for (int ni = 0; ni < 4; ni++)
            wmma::store_matrix_sync(Cs + (wm * 32 + mi * 16) * LDC + wn * 64 + ni * 16,
                                    acc[mi][ni], LDC, wmma::mem_row_major);
}

// ---------------------------------------------------------------------------
// QKV projection + bias + RoPE fused epilogue -> fp16. grid (8, 32, 3).
// q additionally scaled by 1/8 * log2(e) so flash can use ex2 directly.
// ---------------------------------------------------------------------------
__global__ void __launch_bounds__(256, 2)
qkv_mma(const float* __restrict__ bq,
        const float* __restrict__ bk,
        const float* __restrict__ bv)
{
    extern __shared__ char smraw[];
    const int tid = threadIdx.x, wid = tid >> 5;
    const int wm = wid & 3, wn = wid >> 2;
    const int m0 = blockIdx.y * 128, n0 = blockIdx.x * 128;
    const int z = blockIdx.z;

    const __half* W = g_wh + (size_t)z * HH;
    const float* bias = (z == 0) ? bq : (z == 1) ? bk : bv;
    __half* dst = (z == 0) ? g_q : (z == 1) ? g_k : g_v;

    HFragC acc[2][4];
    hgemm_mainloop(g_xh + (size_t)m0 * HIDDEN, W + (size_t)n0 * HIDDEN,
                   (__half*)smraw, acc, wm, wn);

    float* Cs = (float*)smraw;
    stage_C(Cs, acc, wm, wn);
    __syncthreads();

    const int r = tid >> 1, hh = tid & 1;
    const int m = m0 + r;
    const int b = m >> 11, s = m & (SEQ - 1);
    const int h = (n0 >> 6) + hh;
    const float* crow = Cs + r * LDC + hh * 64;
    const float* brow = bias + n0 + hh * 64;
    __half* drow = dst + (((size_t)(b * HEADS + h)) * SEQ + s) * HEAD_DIM;

    if (z < 2) {
        const float* rt = g_rt + s * 64;
        const float scale = (z == 0) ? 0.125f * 1.44269504088896f : 1.0f;
#pragma unroll
        for (int d0 = 0; d0 < 32; d0 += 4) {
            float4 x1 = *(const float4*)(crow + d0);
            float4 x2 = *(const float4*)(crow + d0 + 32);
            float4 b1 = *(const float4*)(brow + d0);
            float4 b2 = *(const float4*)(brow + d0 + 32);
            float4 cc = *(const float4*)(rt + d0);
            float4 ss = *(const float4*)(rt + 32 + d0);
            x1.x += b1.x; x1.y += b1.y; x1.z += b1.z; x1.w += b1.w;
            x2.x += b2.x; x2.y += b2.y; x2.z += b2.z; x2.w += b2.w;
            float o1x = (x1.x * cc.x - x2.x * ss.x) * scale;
            float o1y = (x1.y * cc.y - x2.y * ss.y) * scale;
            float o1z = (x1.z * cc.z - x2.z * ss.z) * scale;
            float o1w = (x1.w * cc.w - x2.w * ss.w) * scale;
            float o2x = (x2.x * cc.x + x1.x * ss.x) * scale;
            float o2y = (x2.y * cc.y + x1.y * ss.y) * scale;
            float o2z = (x2.z * cc.z + x1.z * ss.z) * scale;
            float o2w = (x2.w * cc.w + x1.w * ss.w) * scale;
            *(__half2*)(drow + d0)      = __floats2half2_rn(o1x, o1y);
            *(__half2*)(drow + d0 + 2)  = __floats2half2_rn(o1z, o1w);
            *(__half2*)(drow + d0 + 32) = __floats2half2_rn(o2x, o2y);
            *(__half2*)(drow + d0 + 34) = __floats2half2_rn(o2z, o2w);
        }
    } else {
#pragma unroll
        for (int d0 = 0; d0 < 64; d0 += 4) {
            float4 x = *(const float4*)(crow + d0);
            float4 bb = *(const float4*)(brow + d0);
            *(__half2*)(drow + d0)     = __floats2half2_rn(x.x + bb.x, x.y + bb.y);
            *(__half2*)(drow + d0 + 2) = __floats2half2_rn(x.z + bb.z, x.w + bb.w);
        }
    }
}

// ---------------------------------------------------------------------------
// Output projection + bias. grid (8, 32).
// ---------------------------------------------------------------------------
__global__ void __launch_bounds__(256, 2)
out_mma(const float* __restrict__ bo, float* __restrict__ out)
{
    extern __shared__ char smraw[];
    const int tid = threadIdx.x, wid = tid >> 5;
    const int wm = wid & 3, wn = wid >> 2;
    const int m0 = blockIdx.y * 128, n0 = blockIdx.x * 128;

    HFragC acc[2][4];
    hgemm_mainloop(g_ao + (size_t)m0 * HIDDEN,
                   g_wh + 3 * (size_t)HH + (size_t)n0 * HIDDEN,
                   (__half*)smraw, acc, wm, wn);

    float* Cs = (float*)smraw;
    stage_C(Cs, acc, wm, wn);
    __syncthreads();

    const int r = tid >> 1, half = tid & 1;
    const float* crow = Cs + r * LDC + half * 64;
    const float* brow = bo + n0 + half * 64;
    float* orow = out + (size_t)(m0 + r) * HIDDEN + n0 + half * 64;
#pragma unroll
    for (int j = 0; j < 64; j += 4) {
        float4 x = *(const float4*)(crow + j);
        float4 bb = *(const float4*)(brow + j);
        x.x += bb.x; x.y += bb.y; x.z += bb.z; x.w += bb.w;
        *(float4*)(orow + j) = x;
    }
}

// ---------------------------------------------------------------------------
// Flash attention fp16: mma.m16n8k16, ldmatrix.x4, register-resident P, ex2.
// grid (SEQ/128, BHN), 256 threads / 8 warps; warp owns q-rows [wid*16,+16).
// K/V staged 128 keys at a time (double-buffered), two 64-key halves each.
// ---------------------------------------------------------------------------
#define FPH 72                    // halves; 144B row stride
#define KROWS 128                 // keys per stage
#define KVH (KROWS*FPH)           // halves per K (or V) stage

__global__ void __launch_bounds__(256, 2)
flash_mma()
{
    extern __shared__ char smraw[];
    __half* KsB = (__half*)smraw;            // 2 stages [128][FPH]
    __half* VsB = KsB + 2 * KVH;             // 2 stages [128][FPH]

    const int tid = threadIdx.x, wid = tid >> 5, lane = tid & 31;
    const int g = lane >> 2, t = lane & 3;
    const int bh = blockIdx.y;
    const int q0 = blockIdx.x * 128;
    const int r0 = wid * 16;

    const int k4off = ((lane >> 4) * 8 + (lane & 7)) * FPH + ((lane >> 3) & 1) * 8;
    const int v4off = (((lane >> 3) & 1) * 8 + (lane & 7)) * FPH + (lane >> 4) * 8;

    const __half* q0p = g_q + ((size_t)(bh * SEQ + q0 + r0 + g)) * HEAD_DIM;
    const __half* q8p = q0p + 8 * HEAD_DIM;
    uint32_t qa[4][4];
#pragma unroll
    for (int kb = 0; kb < 4; kb++) {
        qa[kb][0] = *(const uint32_t*)(q0p + kb * 16 + 2 * t);
        qa[kb][1] = *(const uint32_t*)(q8p + kb * 16 + 2 * t);
        qa[kb][2] = *(const uint32_t*)(q0p + kb * 16 + 8 + 2 * t);
        qa[kb][3] = *(const uint32_t*)(q8p + kb * 16 + 8 + 2 * t);
    }

    float oacc[8][4];
#pragma unroll
    for (int nb = 0; nb < 8; nb++)
#pragma unroll
        for (int e = 0; e < 4; e++) oacc[nb][e] = 0.f;
    float mA = -1e30f, mB = -1e30f, lA = 0.f, lB = 0.f;

    const __half* kbase = g_k + (size_t)bh * SEQ * HEAD_DIM;
    const __half* vbase = g_v + (size_t)bh * SEQ * HEAD_DIM;
    auto issue = [&](int kt, int s) {
        __half* Kd = KsB + s * KVH;
        __half* Vd = VsB + s * KVH;
        const __half* ks = kbase + (size_t)kt * KROWS * HEAD_DIM;
        const __half* vs = vbase + (size_t)kt * KROWS * HEAD_DIM;
#pragma unroll
        for (int i = 0; i < 4; i++) {
            int idx = tid + i * 256;            // 0..1023
            int r = idx >> 3, c = (idx & 7) * 8;
            cp16(sm_u32(Kd + r * FPH + c), ks + r * 64 + c);
            cp16(sm_u32(Vd + r * FPH + c), vs + r * 64 + c);
        }
        cp_commit();
    };

    issue(0, 0);

    for (int kt = 0; kt < SEQ / KROWS; kt++) {
        int s = kt & 1;
        cp_wait0();
        __syncthreads();
        if (kt + 1 < SEQ / KROWS) issue(kt + 1, s ^ 1);

#pragma unroll
        for (int hlf = 0; hlf < 2; hlf++) {
            const uint32_t Ku = sm_u32(KsB + s * KVH + hlf * 64 * FPH);
            const uint32_t Vu = sm_u32(VsB + s * KVH + hlf * 64 * FPH);

            float sacc[8][4];
#pragma unroll
            for (int nb = 0; nb < 8; nb++)
#pragma unroll
                for (int e = 0; e < 4; e++) sacc[nb][e] = 0.f;

#pragma unroll
            for (int nb2 = 0; nb2 < 4; nb2++) {
#pragma unroll
                for (int kb = 0; kb < 4; kb++) {
                    uint32_t b0, b1, b2, b3;
                    ldsm_x4(b0, b1, b2, b3,
                            Ku + (uint32_t)(nb2 * 16 * FPH + kb * 16 + k4off) * 2);
                    mma16(sacc[2 * nb2],     qa[kb], b0, b1);
                    mma16(sacc[2 * nb2 + 1], qa[kb], b2, b3);
                }
            }

            float rmA = -1e30f, rmB = -1e30f;
#pragma unroll
            for (int nb = 0; nb < 8; nb++) {
                rmA = fmaxf(rmA, fmaxf(sacc[nb][0], sacc[nb][1]));
                rmB = fmaxf(rmB, fmaxf(sacc[nb][2], sacc[nb][3]));
            }
            rmA = fmaxf(rmA, __shfl_xor_sync(0xffffffffu, rmA, 1));
            rmA = fmaxf(rmA, __shfl_xor_sync(0xffffffffu, rmA, 2));
            rmB = fmaxf(rmB, __shfl_xor_sync(0xffffffffu, rmB, 1));
            rmB = fmaxf(rmB, __shfl_xor_sync(0xffffffffu, rmB, 2));

            float mnA = fmaxf(mA, rmA), mnB = fmaxf(mB, rmB);
            float aA = ex2(mA - mnA), aB = ex2(mB - mnB);
            float rsA = 0.f, rsB = 0.f;
#pragma unroll
            for (int nb = 0; nb < 8; nb++) {
                sacc[nb][0] = ex2(sacc[nb][0] - mnA);
                sacc[nb][1] = ex2(sacc[nb][1] - mnA);
                sacc[nb][2] = ex2(sacc[nb][2] - mnB);
                sacc[nb][3] = ex2(sacc[nb][3] - mnB);
                rsA += sacc[nb][0] + sacc[nb][1];
                rsB += sacc[nb][2] + sacc[nb][3];
            }
            rsA += __shfl_xor_sync(0xffffffffu, rsA, 1);
            rsA += __shfl_xor_sync(0xffffffffu, rsA, 2);
            rsB += __shfl_xor_sync(0xffffffffu, rsB, 1);
            rsB += __shfl_xor_sync(0xffffffffu, rsB, 2);

            lA = lA * aA + rsA;  mA = mnA;
            lB = lB * aB + rsB;  mB = mnB;
#pragma unroll
            for (int nb = 0; nb < 8; nb++) {
                oacc[nb][0] *= aA; oacc[nb][1] *= aA;
                oacc[nb][2] *= aB; oacc[nb][3] *= aB;
            }

#pragma unroll
            for (int kb2 = 0; kb2 < 4; kb2++) {
                uint32_t pa[4];
                pa[0] = pack_h2(sacc[2*kb2][0],   sacc[2*kb2][1]);
                pa[1] = pack_h2(sacc[2*kb2][2],   sacc[2*kb2][3]);
                pa[2] = pack_h2(sacc[2*kb2+1][0], sacc[2*kb2+1][1]);
                pa[3] = pack_h2(sacc[2*kb2+1][2], sacc[2*kb2+1][3]);
#pragma unroll
                for (int nb2 = 0; nb2 < 4; nb2++) {
                    uint32_t b0, b1, b2, b3;
                    ldsm_x4_t(b0, b1, b2, b3,
                              Vu + (uint32_t)(kb2 * 16 * FPH + v4off + nb2 * 16) * 2);
                    mma16(oacc[2 * nb2],     pa, b0, b1);
                    mma16(oacc[2 * nb2 + 1], pa, b2, b3);
                }
            }
        }
    }

    const int b = bh >> 4, h = bh & 15;
    float invA = 1.0f / lA, invB = 1.0f / lB;
    int rA = q0 + r0 + g, rB = rA + 8;
#pragma unroll
    for (int nb = 0; nb < 8; nb++) {
        int col = h * HEAD_DIM + nb * 8 + 2 * t;
        *(__half2*)&g_ao[((size_t)(b * SEQ + rA)) * HIDDEN + col] =
            __floats2half2_rn(oacc[nb][0] * invA, oacc[nb][1] * invA);
        *(__half2*)&g_ao[((size_t)(b * SEQ + rB)) * HIDDEN + col] =
            __floats2half2_rn(oacc[nb][2] * invB, oacc[nb][3] * invB);
    }
}

// ---------------------------------------------------------------------------
extern "C" void kernel_launch(void* const* d_in, const int* in_sizes, int n_in,
                              void* d_out, int out_size)
{
    const float* X  = (const float*)d_in[0];
    const float* Wq = (const float*)d_in[1];
    const float* bq = (const float*)d_in[2];
    const float* Wk = (const float*)d_in[3];
    const float* bk = (const float*)d_in[4];
    const float* Wv = (const float*)d_in[5];
    const float* bv = (const float*)d_in[6];
    const float* Wo = (const float*)d_in[7];
    const float* bo = (const float*)d_in[8];
    float* out = (float*)d_out;

    static const int GEMM_SMEM  = 4 * STGH * 2;       // 81920 (4-stage; covers Cs 67584)
    static const int FLASH_SMEM = 4 * KVH * 2;        // 73728
    cudaFuncSetAttribute(qkv_mma,  cudaFuncAttributeMaxDynamicSharedMemorySize, GEMM_SMEM);
    cudaFuncSetAttribute(out_mma,  cudaFuncAttributeMaxDynamicSharedMemorySize, GEMM_SMEM);
    cudaFuncSetAttribute(flash_mma, cudaFuncAttributeMaxDynamicSharedMemorySize, FLASH_SMEM);

    conv_kernel<<<(CONVN + SEQ * 32) / 256, 256>>>(X, Wq, Wk, Wv, Wo);

    dim3 gq(HIDDEN / 128, MTOT / 128, 3);
    qkv_mma<<<gq, 256, GEMM_SMEM>>>(bq, bk, bv);

    dim3 gf(SEQ / 128, BHN);
    flash_mma<<<gf, 256, FLASH_SMEM>>>();

    dim3 go(HIDDEN / 128, MTOT / 128, 1);
    out_mma<<<go, 256, GEMM_SMEM>>>(bo, out);
}

// round 13
// speedup vs baseline: 6.6201x; 1.0211x over previous
#include <cuda_runtime.h>
#include <cuda_fp16.h>
#include <mma.h>
#include <math.h>
#include <cstdint>

using namespace nvcuda;

#define BATCH    2
#define SEQ      2048
#define HIDDEN   1024
#define HEADS    16
#define HEAD_DIM 64
#define MTOT     (BATCH*SEQ)      // 4096
#define BHN      (BATCH*HEADS)    // 32
#define HH       (HIDDEN*HIDDEN)

// scratch (allocation-free rule: __device__ globals)
static __device__ __half g_xh[MTOT*HIDDEN];        // X in fp16
static __device__ __half g_wh[4*HH];               // Wq,Wk,Wv,Wo in fp16
static __device__ float  g_rt[SEQ*64];             // rope: [s][0:32)=cos,[32:64)=sin
static __device__ __half g_q [BHN*SEQ*HEAD_DIM];   // [B,H,S,D] fp16 (q scaled by 1/8*log2e)
static __device__ __half g_k [BHN*SEQ*HEAD_DIM];
static __device__ __half g_v [BHN*SEQ*HEAD_DIM];
static __device__ __half g_ao[MTOT*HIDDEN];        // attention out fp16

// ---------------------------------------------------------------------------
// helpers
// ---------------------------------------------------------------------------
__device__ __forceinline__ void cp16(uint32_t dst, const void* src) {
    asm volatile("cp.async.cg.shared.global [%0], [%1], 16;" :: "r"(dst), "l"(src));
}
__device__ __forceinline__ void cp_commit() {
    asm volatile("cp.async.commit_group;" ::: "memory");
}
__device__ __forceinline__ void cp_wait0() {
    asm volatile("cp.async.wait_group 0;" ::: "memory");
}
__device__ __forceinline__ void cp_wait1() {
    asm volatile("cp.async.wait_group 1;" ::: "memory");
}
__device__ __forceinline__ void cp_wait2() {
    asm volatile("cp.async.wait_group 2;" ::: "memory");
}
__device__ __forceinline__ uint32_t sm_u32(const void* p) {
    return (uint32_t)__cvta_generic_to_shared(p);
}
__device__ __forceinline__ uint32_t pack_h2(float lo, float hi) {
    __half2 h = __floats2half2_rn(lo, hi);
    return *reinterpret_cast<uint32_t*>(&h);
}
__device__ __forceinline__ float ex2(float x) {
    float y;
    asm("ex2.approx.ftz.f32 %0, %1;" : "=f"(y) : "f"(x));
    return y;
}
__device__ __forceinline__ uint32_t ex2_h2(uint32_t x) {
    uint32_t y;
    asm("ex2.approx.f16x2 %0, %1;" : "=r"(y) : "r"(x));
    return y;
}
__device__ __forceinline__ void mma16(float d[4], const uint32_t a[4],
                                      uint32_t b0, uint32_t b1)
{
    asm volatile(
        "mma.sync.aligned.m16n8k16.row.col.f32.f16.f16.f32 "
        "{%0,%1,%2,%3}, {%4,%5,%6,%7}, {%8,%9}, {%0,%1,%2,%3};"
        : "+f"(d[0]), "+f"(d[1]), "+f"(d[2]), "+f"(d[3])
        : "r"(a[0]), "r"(a[1]), "r"(a[2]), "r"(a[3]), "r"(b0), "r"(b1));
}
__device__ __forceinline__ void ldsm_x4(uint32_t& r0, uint32_t& r1,
                                        uint32_t& r2, uint32_t& r3, uint32_t addr) {
    asm volatile("ldmatrix.sync.aligned.m8n8.x4.shared.b16 {%0,%1,%2,%3}, [%4];"
                 : "=r"(r0), "=r"(r1), "=r"(r2), "=r"(r3) : "r"(addr));
}
__device__ __forceinline__ void ldsm_x4_t(uint32_t& r0, uint32_t& r1,
                                          uint32_t& r2, uint32_t& r3, uint32_t addr) {
    asm volatile("ldmatrix.sync.aligned.m8n8.x4.trans.shared.b16 {%0,%1,%2,%3}, [%4];"
                 : "=r"(r0), "=r"(r1), "=r"(r2), "=r"(r3) : "r"(addr));
}

// ---------------------------------------------------------------------------
// setup: fp16 conversion + rope table (merged, one launch)
// ---------------------------------------------------------------------------
#define XN4 (MTOT*HIDDEN/4)       // 1048576
#define WN4 (HH/4)                // 262144
#define CONVN (XN4 + 4*WN4)       // 2097152
__global__ void conv_kernel(const float* __restrict__ X,
                            const float* __restrict__ Wq,
                            const float* __restrict__ Wk,
                            const float* __restrict__ Wv,
                            const float* __restrict__ Wo)
{
    int gid = blockIdx.x * blockDim.x + threadIdx.x;
    if (gid < CONVN) {
        const float4* s4; __half2* d2;
        if (gid < XN4) {
            s4 = (const float4*)X + gid;
            d2 = (__half2*)g_xh + (size_t)gid * 2;
        } else {
            int w = gid - XN4;
            int sel = w >> 18;          // WN4 = 2^18
            int off = w & (WN4 - 1);
            const float* W = (sel == 0) ? Wq : (sel == 1) ? Wk : (sel == 2) ? Wv : Wo;
            s4 = (const float4*)W + off;
            d2 = (__half2*)g_wh + ((size_t)sel * WN4 + off) * 2;
        }
        float4 v = *s4;
        d2[0] = __floats2half2_rn(v.x, v.y);
        d2[1] = __floats2half2_rn(v.z, v.w);
    } else {
        int t = gid - CONVN;            // < SEQ*32
        int i = t & 31, s = t >> 5;
        float inv = powf(10000.0f, -(float)i * (1.0f / 32.0f));
        float c, sn;
        sincosf((float)s * inv, &sn, &c);
        g_rt[s * 64 + i]      = c;
        g_rt[s * 64 + 32 + i] = sn;
    }
}

// ---------------------------------------------------------------------------
// fp16 wmma GEMM: C(128x128) = A(128xK)*W(128xK)^T, K=1024, BK=32 halves.
// 4-stage cp.async pipeline, ONE __syncthreads per iteration.
// ---------------------------------------------------------------------------
#define LDAH 40                   // halves; 80B row stride
#define STGH (2*128*LDAH)         // halves per stage (A+W) = 10240
#define LDC  132

using HFragA = wmma::fragment<wmma::matrix_a, 16, 16, 16, __half, wmma::row_major>;
using HFragB = wmma::fragment<wmma::matrix_b, 16, 16, 16, __half, wmma::col_major>;
using HFragC = wmma::fragment<wmma::accumulator, 16, 16, 16, float>;

__device__ __forceinline__ void hgemm_issue(const __half* __restrict__ A,
                                            const __half* __restrict__ W,
                                            __half* sm, int kb, int s, int tid)
{
    __half* As = sm + s * STGH;
    __half* Ws = As + 128 * LDAH;
#pragma unroll
    for (int i = 0; i < 2; i++) {
        int idx = tid + i * 256;            // 0..511
        int r = idx >> 2, c = (idx & 3) * 8;
        cp16(sm_u32(As + r * LDAH + c), A + (size_t)r * HIDDEN + kb * 32 + c);
        cp16(sm_u32(Ws + r * LDAH + c), W + (size_t)r * HIDDEN + kb * 32 + c);
    }
    cp_commit();
}

__device__ __forceinline__ void hgemm_mainloop(const __half* __restrict__ A,
                                               const __half* __restrict__ W,
                                               __half* sm, HFragC acc[2][4],
                                               int wm, int wn)
{
    const int tid = threadIdx.x;
#pragma unroll
    for (int mi = 0; mi < 2; mi++)
#pragma unroll
        for (int ni = 0; ni < 4; ni++)
            wmma::fill_fragment(acc[mi][ni], 0.0f);

    hgemm_issue(A, W, sm, 0, 0, tid);
    hgemm_issue(A, W, sm, 1, 1, tid);
    hgemm_issue(A, W, sm, 2, 2, tid);

    for (int kb = 0; kb < 32; kb++) {
        int s = kb & 3;
        if      (kb < 30)  cp_wait2();
        else if (kb == 30) cp_wait1();
        else               cp_wait0();
        __syncthreads();
        if (kb + 3 < 32) hgemm_issue(A, W, sm, kb + 3, (kb + 3) & 3, tid);

        __half* As = sm + s * STGH;
        __half* Ws = As + 128 * LDAH;
#pragma unroll
        for (int kk = 0; kk < 32; kk += 16) {
            HFragA af[2];
            HFragB bf[4];
#pragma unroll
            for (int mi = 0; mi < 2; mi++)
                wmma::load_matrix_sync(af[mi], &As[(wm * 32 + mi * 16) * LDAH + kk], LDAH);
#pragma unroll
            for (int ni = 0; ni < 4; ni++)
                wmma::load_matrix_sync(bf[ni], &Ws[(wn * 64 + ni * 16) * LDAH + kk], LDAH);
#pragma unroll
            for (int mi = 0; mi < 2; mi++)
#pragma unroll
                for (int ni = 0; ni < 4; ni++)
                    wmma::mma_sync(acc[mi][ni], af[mi], bf[ni], acc[mi][ni]);
        }
    }
    __syncthreads();   // before epilogue reuses smem
}

__device__ __forceinline__ void stage_C(float* Cs, HFragC acc[2][4], int wm, int wn)
{
#pragma unroll
    for (int mi = 0; mi < 2; mi++)
#pragma unroll
        for (int ni = 0; ni < 4; ni++)
            wmma::store_matrix_sync(Cs + (wm * 32 + mi * 16) * LDC + wn * 64 + ni * 16,
                                    acc[mi][ni], LDC, wmma::mem_row_major);
}

// ---------------------------------------------------------------------------
// QKV projection + bias + RoPE fused epilogue -> fp16. grid (8, 32, 3).
// ---------------------------------------------------------------------------
__global__ void __launch_bounds__(256, 2)
qkv_mma(const float* __restrict__ bq,
        const float* __restrict__ bk,
        const float* __restrict__ bv)
{
    extern __shared__ char smraw[];
    const int tid = threadIdx.x, wid = tid >> 5;
    const int wm = wid & 3, wn = wid >> 2;
    const int m0 = blockIdx.y * 128, n0 = blockIdx.x * 128;
    const int z = blockIdx.z;

    const __half* W = g_wh + (size_t)z * HH;
    const float* bias = (z == 0) ? bq : (z == 1) ? bk : bv;
    __half* dst = (z == 0) ? g_q : (z == 1) ? g_k : g_v;

    HFragC acc[2][4];
    hgemm_mainloop(g_xh + (size_t)m0 * HIDDEN, W + (size_t)n0 * HIDDEN,
                   (__half*)smraw, acc, wm, wn);

    float* Cs = (float*)smraw;
    stage_C(Cs, acc, wm, wn);
    __syncthreads();

    const int r = tid >> 1, hh = tid & 1;
    const int m = m0 + r;
    const int b = m >> 11, s = m & (SEQ - 1);
    const int h = (n0 >> 6) + hh;
    const float* crow = Cs + r * LDC + hh * 64;
    const float* brow = bias + n0 + hh * 64;
    __half* drow = dst + (((size_t)(b * HEADS + h)) * SEQ + s) * HEAD_DIM;

    if (z < 2) {
        const float* rt = g_rt + s * 64;
        const float scale = (z == 0) ? 0.125f * 1.44269504088896f : 1.0f;
#pragma unroll
        for (int d0 = 0; d0 < 32; d0 += 4) {
            float4 x1 = *(const float4*)(crow + d0);
            float4 x2 = *(const float4*)(crow + d0 + 32);
            float4 b1 = *(const float4*)(brow + d0);
            float4 b2 = *(const float4*)(brow + d0 + 32);
            float4 cc = *(const float4*)(rt + d0);
            float4 ss = *(const float4*)(rt + 32 + d0);
            x1.x += b1.x; x1.y += b1.y; x1.z += b1.z; x1.w += b1.w;
            x2.x += b2.x; x2.y += b2.y; x2.z += b2.z; x2.w += b2.w;
            float o1x = (x1.x * cc.x - x2.x * ss.x) * scale;
            float o1y = (x1.y * cc.y - x2.y * ss.y) * scale;
            float o1z = (x1.z * cc.z - x2.z * ss.z) * scale;
            float o1w = (x1.w * cc.w - x2.w * ss.w) * scale;
            float o2x = (x2.x * cc.x + x1.x * ss.x) * scale;
            float o2y = (x2.y * cc.y + x1.y * ss.y) * scale;
            float o2z = (x2.z * cc.z + x1.z * ss.z) * scale;
            float o2w = (x2.w * cc.w + x1.w * ss.w) * scale;
            *(__half2*)(drow + d0)      = __floats2half2_rn(o1x, o1y);
            *(__half2*)(drow + d0 + 2)  = __floats2half2_rn(o1z, o1w);
            *(__half2*)(drow + d0 + 32) = __floats2half2_rn(o2x, o2y);
            *(__half2*)(drow + d0 + 34) = __floats2half2_rn(o2z, o2w);
        }
    } else {
#pragma unroll
        for (int d0 = 0; d0 < 64; d0 += 4) {
            float4 x = *(const float4*)(crow + d0);
            float4 bb = *(const float4*)(brow + d0);
            *(__half2*)(drow + d0)     = __floats2half2_rn(x.x + bb.x, x.y + bb.y);
            *(__half2*)(drow + d0 + 2) = __floats2half2_rn(x.z + bb.z, x.w + bb.w);
        }
    }
}

// ---------------------------------------------------------------------------
// Output projection + bias. grid (8, 32).
// ---------------------------------------------------------------------------
__global__ void __launch_bounds__(256, 2)
out_mma(const float* __restrict__ bo, float* __restrict__ out)
{
    extern __shared__ char smraw[];
    const int tid = threadIdx.x, wid = tid >> 5;
    const int wm = wid & 3, wn = wid >> 2;
    const int m0 = blockIdx.y * 128, n0 = blockIdx.x * 128;

    HFragC acc[2][4];
    hgemm_mainloop(g_ao + (size_t)m0 * HIDDEN,
                   g_wh + 3 * (size_t)HH + (size_t)n0 * HIDDEN,
                   (__half*)smraw, acc, wm, wn);

    float* Cs = (float*)smraw;
    stage_C(Cs, acc, wm, wn);
    __syncthreads();

    const int r = tid >> 1, half = tid & 1;
    const float* crow = Cs + r * LDC + half * 64;
    const float* brow = bo + n0 + half * 64;
    float* orow = out + (size_t)(m0 + r) * HIDDEN + n0 + half * 64;
#pragma unroll
    for (int j = 0; j < 64; j += 4) {
        float4 x = *(const float4*)(crow + j);
        float4 bb = *(const float4*)(brow + j);
        x.x += bb.x; x.y += bb.y; x.z += bb.z; x.w += bb.w;
        *(float4*)(orow + j) = x;
    }
}

// ---------------------------------------------------------------------------
// Flash attention fp16: mma.m16n8k16, ldmatrix.x4, register-resident P.
// Softmax: ex2.f16x2 (paired MUFU) + row-sums via ones-MMA (no sum shuffles).
// grid (SEQ/128, BHN), 256 threads / 8 warps; warp owns q-rows [wid*16,+16).
// ---------------------------------------------------------------------------
#define FPH 72                    // halves; 144B row stride
#define KROWS 128                 // keys per stage
#define KVH (KROWS*FPH)           // halves per K (or V) stage
#define ONES_H2 0x3C003C00u       // (1.0h, 1.0h)

__global__ void __launch_bounds__(256, 2)
flash_mma()
{
    extern __shared__ char smraw[];
    __half* KsB = (__half*)smraw;            // 2 stages [128][FPH]
    __half* VsB = KsB + 2 * KVH;             // 2 stages [128][FPH]

    const int tid = threadIdx.x, wid = tid >> 5, lane = tid & 31;
    const int g = lane >> 2, t = lane & 3;
    const int bh = blockIdx.y;
    const int q0 = blockIdx.x * 128;
    const int r0 = wid * 16;

    const int k4off = ((lane >> 4) * 8 + (lane & 7)) * FPH + ((lane >> 3) & 1) * 8;
    const int v4off = (((lane >> 3) & 1) * 8 + (lane & 7)) * FPH + (lane >> 4) * 8;

    const __half* q0p = g_q + ((size_t)(bh * SEQ + q0 + r0 + g)) * HEAD_DIM;
    const __half* q8p = q0p + 8 * HEAD_DIM;
    uint32_t qa[4][4];
#pragma unroll
    for (int kb = 0; kb < 4; kb++) {
        qa[kb][0] = *(const uint32_t*)(q0p + kb * 16 + 2 * t);
        qa[kb][1] = *(const uint32_t*)(q8p + kb * 16 + 2 * t);
        qa[kb][2] = *(const uint32_t*)(q0p + kb * 16 + 8 + 2 * t);
        qa[kb][3] = *(const uint32_t*)(q8p + kb * 16 + 8 + 2 * t);
    }

    float oacc[8][4];
#pragma unroll
    for (int nb = 0; nb < 8; nb++)
#pragma unroll
        for (int e = 0; e < 4; e++) oacc[nb][e] = 0.f;
    float mA = -1e30f, mB = -1e30f, lA = 0.f, lB = 0.f;

    const __half* kbase = g_k + (size_t)bh * SEQ * HEAD_DIM;
    const __half* vbase = g_v + (size_t)bh * SEQ * HEAD_DIM;
    auto issue = [&](int kt, int s) {
        __half* Kd = KsB + s * KVH;
        __half* Vd = VsB + s * KVH;
        const __half* ks = kbase + (size_t)kt * KROWS * HEAD_DIM;
        const __half* vs = vbase + (size_t)kt * KROWS * HEAD_DIM;
#pragma unroll
        for (int i = 0; i < 4; i++) {
            int idx = tid + i * 256;            // 0..1023
            int r = idx >> 3, c = (idx & 7) * 8;
            cp16(sm_u32(Kd + r * FPH + c), ks + r * 64 + c);
            cp16(sm_u32(Vd + r * FPH + c), vs + r * 64 + c);
        }
        cp_commit();
    };

    issue(0, 0);

    for (int kt = 0; kt < SEQ / KROWS; kt++) {
        int s = kt & 1;
        cp_wait0();
        __syncthreads();
        if (kt + 1 < SEQ / KROWS) issue(kt + 1, s ^ 1);

#pragma unroll
        for (int hlf = 0; hlf < 2; hlf++) {
            const uint32_t Ku = sm_u32(KsB + s * KVH + hlf * 64 * FPH);
            const uint32_t Vu = sm_u32(VsB + s * KVH + hlf * 64 * FPH);

            // ---- S = Q K^T (log2 domain) ----
            float sacc[8][4];
#pragma unroll
            for (int nb = 0; nb < 8; nb++)
#pragma unroll
                for (int e = 0; e < 4; e++) sacc[nb][e] = 0.f;

#pragma unroll
            for (int nb2 = 0; nb2 < 4; nb2++) {
#pragma unroll
                for (int kb = 0; kb < 4; kb++) {
                    uint32_t b0, b1, b2, b3;
                    ldsm_x4(b0, b1, b2, b3,
                            Ku + (uint32_t)(nb2 * 16 * FPH + kb * 16 + k4off) * 2);
                    mma16(sacc[2 * nb2],     qa[kb], b0, b1);
                    mma16(sacc[2 * nb2 + 1], qa[kb], b2, b3);
                }
            }

            // ---- row max (2 shfls per row-group) ----
            float rmA = -1e30f, rmB = -1e30f;
#pragma unroll
            for (int nb = 0; nb < 8; nb++) {
                rmA = fmaxf(rmA, fmaxf(sacc[nb][0], sacc[nb][1]));
                rmB = fmaxf(rmB, fmaxf(sacc[nb][2], sacc[nb][3]));
            }
            rmA = fmaxf(rmA, __shfl_xor_sync(0xffffffffu, rmA, 1));
            rmA = fmaxf(rmA, __shfl_xor_sync(0xffffffffu, rmA, 2));
            rmB = fmaxf(rmB, __shfl_xor_sync(0xffffffffu, rmB, 1));
            rmB = fmaxf(rmB, __shfl_xor_sync(0xffffffffu, rmB, 2));

            float mnA = fmaxf(mA, rmA), mnB = fmaxf(mB, rmB);
            float aA = ex2(mA - mnA), aB = ex2(mB - mnB);

            // ---- P = 2^(S-m) in fp16 pairs (ex2.f16x2); directly PV A-frags ----
            uint32_t pall[16];
#pragma unroll
            for (int nb = 0; nb < 8; nb++) {
                pall[2 * nb]     = ex2_h2(pack_h2(sacc[nb][0] - mnA, sacc[nb][1] - mnA));
                pall[2 * nb + 1] = ex2_h2(pack_h2(sacc[nb][2] - mnB, sacc[nb][3] - mnB));
            }

            // ---- row sums via ones-MMA (every lane gets the row sum) ----
            float rsum[4] = {0.f, 0.f, 0.f, 0.f};
#pragma unroll
            for (int kb2 = 0; kb2 < 4; kb2++)
                mma16(rsum, &pall[4 * kb2], ONES_H2, ONES_H2);

            lA = lA * aA + rsum[0];  mA = mnA;
            lB = lB * aB + rsum[2];  mB = mnB;
#pragma unroll
            for (int nb = 0; nb < 8; nb++) {
                oacc[nb][0] *= aA; oacc[nb][1] *= aA;
                oacc[nb][2] *= aB; oacc[nb][3] *= aB;
            }

            // ---- O += P V ----
#pragma unroll
            for (int kb2 = 0; kb2 < 4; kb2++) {
#pragma unroll
                for (int nb2 = 0; nb2 < 4; nb2++) {
                    uint32_t b0, b1, b2, b3;
                    ldsm_x4_t(b0, b1, b2, b3,
                              Vu + (uint32_t)(kb2 * 16 * FPH + v4off + nb2 * 16) * 2);
                    mma16(oacc[2 * nb2],     &pall[4 * kb2], b0, b1);
                    mma16(oacc[2 * nb2 + 1], &pall[4 * kb2], b2, b3);
                }
            }
        }
    }

    const int b = bh >> 4, h = bh & 15;
    float invA = 1.0f / lA, invB = 1.0f / lB;
    int rA = q0 + r0 + g, rB = rA + 8;
#pragma unroll
    for (int nb = 0; nb < 8; nb++) {
        int col = h * HEAD_DIM + nb * 8 + 2 * t;
        *(__half2*)&g_ao[((size_t)(b * SEQ + rA)) * HIDDEN + col] =
            __floats2half2_rn(oacc[nb][0] * invA, oacc[nb][1] * invA);
        *(__half2*)&g_ao[((size_t)(b * SEQ + rB)) * HIDDEN + col] =
            __floats2half2_rn(oacc[nb][2] * invB, oacc[nb][3] * invB);
    }
}

// ---------------------------------------------------------------------------
extern "C" void kernel_launch(void* const* d_in, const int* in_sizes, int n_in,
                              void* d_out, int out_size)
{
    const float* X  = (const float*)d_in[0];
    const float* Wq = (const float*)d_in[1];
    const float* bq = (const float*)d_in[2];
    const float* Wk = (const float*)d_in[3];
    const float* bk = (const float*)d_in[4];
    const float* Wv = (const float*)d_in[5];
    const float* bv = (const float*)d_in[6];
    const float* Wo = (const float*)d_in[7];
    const float* bo = (const float*)d_in[8];
    float* out = (float*)d_out;

    static const int GEMM_SMEM  = 4 * STGH * 2;       // 81920
    static const int FLASH_SMEM = 4 * KVH * 2;        // 73728
    cudaFuncSetAttribute(qkv_mma,  cudaFuncAttributeMaxDynamicSharedMemorySize, GEMM_SMEM);
    cudaFuncSetAttribute(out_mma,  cudaFuncAttributeMaxDynamicSharedMemorySize, GEMM_SMEM);
    cudaFuncSetAttribute(flash_mma, cudaFuncAttributeMaxDynamicSharedMemorySize, FLASH_SMEM);

    conv_kernel<<<(CONVN + SEQ * 32) / 256, 256>>>(X, Wq, Wk, Wv, Wo);

    dim3 gq(HIDDEN / 128, MTOT / 128, 3);
    qkv_mma<<<gq, 256, GEMM_SMEM>>>(bq, bk, bv);

    dim3 gf(SEQ / 128, BHN);
    flash_mma<<<gf, 256, FLASH_SMEM>>>();

    dim3 go(HIDDEN / 128, MTOT / 128, 1);
    out_mma<<<go, 256, GEMM_SMEM>>>(bo, out);
}